// round 1
// baseline (speedup 1.0000x reference)
#include <cuda_runtime.h>
#include <cuda_bf16.h>
#include <math.h>

#define Dm    1024
#define SEQn  512
#define NB    2
#define NH    16
#define DHd   64
#define DFFn  2730
#define NV    32000
#define NL    4
#define MT    1024   // NB*SEQn tokens

// ---------------- device scratch (static; no runtime allocation) ----------------
__device__ float g_x[MT*Dm];
__device__ float g_qraw[MT*Dm];
__device__ float g_kraw[MT*Dm];
__device__ float g_vraw[MT*Dm];
__device__ float g_qh[NB*NH*SEQn*DHd];
__device__ float g_kh[NB*NH*SEQn*DHd];
__device__ float g_vh[NB*NH*SEQn*DHd];
__device__ float g_v0h[NB*NH*SEQn*DHd];
__device__ float g_betab[NB*NH*SEQn];
__device__ float g_otok[MT*Dm];
__device__ float g_ffh[MT*DFFn];
__device__ float g_ffg[MT*DFFn];
__device__ float g_fq[NL*Dm];
__device__ float g_fk[NL*Dm];
__device__ float g_fv[NL*Dm];
__device__ float g_fo[NL*Dm];
__device__ float g_fffh[NL*DFFn];
__device__ float g_fffg[NL*DFFn];
__device__ float g_fffo[NL*DFFn];
__device__ float g_flog[NV];
__device__ float g_wbn[DHd];

// ---------------- helpers ----------------
static __device__ __forceinline__ float l2fac(float n){
    // matches jax l2norm: t / max(n / clip(n,1-eps,1+eps), 1e-10)
    float tgt = fminf(fmaxf(n, 1.0f - 1e-5f), 1.0f + 1e-5f);
    return 1.0f / fmaxf(n / tgt, 1e-10f);
}

static __device__ __forceinline__ float warpsum(float v){
    #pragma unroll
    for(int o=16;o>0;o>>=1) v += __shfl_xor_sync(0xffffffffu, v, o);
    return v;
}

static __device__ __forceinline__ float blocksum256(float v, float* red){
    red[threadIdx.x] = v; __syncthreads();
    for(int o=128;o>0;o>>=1){
        if(threadIdx.x < o) red[threadIdx.x] += red[threadIdx.x+o];
        __syncthreads();
    }
    float r = red[0]; __syncthreads();
    return r;
}

// ---------------- norm-factor kernels ----------------
// f[r] = l2 factor for row r of W [gridDim.x rows, C cols] (row-major)
__global__ void rownorm_k(const float* __restrict__ W, float* __restrict__ f, int C){
    __shared__ float red[256];
    int r = blockIdx.x;
    const float* row = W + (size_t)r*C;
    float s = 0.0f;
    for(int c=threadIdx.x;c<C;c+=256){ float w = row[c]; s += w*w; }
    s = blocksum256(s, red);
    if(threadIdx.x==0) f[r] = l2fac(sqrtf(s));
}

// per-layer column norms: W layered [L][R][C]; f[l*C + c]
__global__ void colnorm_k(const float* __restrict__ W, float* __restrict__ f, int R, int C){
    int l = blockIdx.y;
    int c = blockIdx.x*blockDim.x + threadIdx.x;
    if(c >= C) return;
    const float* Wl = W + (size_t)l*R*C;
    float s = 0.0f;
    for(int r=0;r<R;r++){ float w = Wl[(size_t)r*C + c]; s += w*w; }
    f[(size_t)l*C + c] = l2fac(sqrtf(s));
}

// ---------------- embedding gather + row l2norm ----------------
__global__ void embed_k(const int* __restrict__ ids, const float* __restrict__ W_emb,
                        float* __restrict__ x){
    __shared__ float red[256];
    int m = blockIdx.x;
    int tok = ids[m];
    const float* row = W_emb + (size_t)tok*Dm;
    float v[4]; float s = 0.0f;
    #pragma unroll
    for(int i=0;i<4;i++){ v[i] = row[threadIdx.x + i*256]; s += v[i]*v[i]; }
    s = blocksum256(s, red);
    float f = l2fac(sqrtf(s));
    #pragma unroll
    for(int i=0;i<4;i++) x[(size_t)m*Dm + threadIdx.x + i*256] = v[i]*f;
}

// ---------------- generic SGEMM  C[M,N] = A[M,K] @ B[N,K]^T, col-scaled epilogue ----------------
struct GemmOp { const float* B; float* C; const float* cf; const float* cs; float extra; };
struct GemmBatch { GemmOp op[3]; };

template<int BM, int BN, int TM, int TN>
__global__ void __launch_bounds__(256) gemm_bt_k(const float* __restrict__ A, GemmBatch gbt,
                                                 int M, int N, int K){
    const GemmOp op = gbt.op[blockIdx.z];
    const float* __restrict__ Bp = op.B;
    constexpr int BK = 16;
    __shared__ __align__(16) float As[BK][BM+4];
    __shared__ __align__(16) float Bs[BK][BN+4];

    const int tid = threadIdx.x;
    const int tx = tid % (BN/TN);          // 16
    const int ty = tid / (BN/TN);          // 16
    const int row0 = blockIdx.y*BM, col0 = blockIdx.x*BN;

    constexpr int CA = BM*BK/256;          // elems per thread, A tile
    constexpr int TPRA = BK/CA;
    const int arow = tid / TPRA;
    const int acol = (tid % TPRA)*CA;
    constexpr int CB = BN*BK/256;
    constexpr int TPRB = BK/CB;
    const int brow = tid / TPRB;
    const int bcol = (tid % TPRB)*CB;

    float acc[TM][TN];
    #pragma unroll
    for(int i=0;i<TM;i++)
        #pragma unroll
        for(int j=0;j<TN;j++) acc[i][j] = 0.0f;

    for(int k0=0;k0<K;k0+=BK){
        #pragma unroll
        for(int j=0;j<CA;j++){
            int kk = k0 + acol + j;
            float v = 0.0f;
            if((row0+arow) < M && kk < K) v = A[(size_t)(row0+arow)*K + kk];
            As[acol+j][arow] = v;
        }
        #pragma unroll
        for(int j=0;j<CB;j++){
            int kk = k0 + bcol + j;
            float v = 0.0f;
            if((col0+brow) < N && kk < K) v = Bp[(size_t)(col0+brow)*K + kk];
            Bs[bcol+j][brow] = v;
        }
        __syncthreads();
        #pragma unroll
        for(int k=0;k<BK;k++){
            float af[TM], bf[TN];
            #pragma unroll
            for(int i=0;i<TM;i+=4){
                float4 t = *(const float4*)&As[k][ty*TM + i];
                af[i]=t.x; af[i+1]=t.y; af[i+2]=t.z; af[i+3]=t.w;
            }
            #pragma unroll
            for(int j=0;j<TN;j+=4){
                float4 t = *(const float4*)&Bs[k][tx*TN + j];
                bf[j]=t.x; bf[j+1]=t.y; bf[j+2]=t.z; bf[j+3]=t.w;
            }
            #pragma unroll
            for(int i=0;i<TM;i++)
                #pragma unroll
                for(int j=0;j<TN;j++) acc[i][j] += af[i]*bf[j];
        }
        __syncthreads();
    }
    #pragma unroll
    for(int j=0;j<TN;j++){
        int c = col0 + tx*TN + j;
        if(c >= N) continue;
        float s = op.extra;
        if(op.cf) s *= op.cf[c];
        if(op.cs) s *= op.cs[c];
        #pragma unroll
        for(int i=0;i<TM;i++){
            int r = row0 + ty*TM + i;
            if(r < M) op.C[(size_t)r*N + c] = acc[i][j]*s;
        }
    }
}

// ---------------- wbeta: normalized beta projection vector (incl. 0.1*beta_scale) ----------------
__global__ void wbeta_k(const float* __restrict__ Wb, const float* __restrict__ bscale,
                        int l, float* __restrict__ out){
    __shared__ float red[64]; __shared__ float stot;
    int t = threadIdx.x;
    float w = Wb[l*DHd + t];
    red[t] = w*w; __syncthreads();
    if(t<32) red[t] += red[t+32];
    __syncthreads();
    if(t==0){ float s=0; for(int i=0;i<32;i++) s += red[i]; stot = s; }
    __syncthreads();
    float fac = l2fac(sqrtf(stot));
    out[t] = w * fac * (bscale[l] * 0.1f);
}

// ---------------- per-head l2norm + beta + layout transform + value residual ----------------
__global__ void attn_prep_k(const float* __restrict__ qraw, const float* __restrict__ kraw,
                            const float* __restrict__ vraw, const float* __restrict__ qs_l,
                            const float* __restrict__ wbn,
                            float* __restrict__ qh, float* __restrict__ kh,
                            float* __restrict__ vh, float* __restrict__ v0h,
                            float* __restrict__ betab, int is_l0){
    int m = blockIdx.x;
    int b = m / SEQn, s = m % SEQn;
    int lane = threadIdx.x & 31, warp = threadIdx.x >> 5;   // 128 threads, 4 warps
    #pragma unroll
    for(int hi=0; hi<NH/4; hi++){
        int h = warp*4 + hi;
        size_t src = (size_t)m*Dm + h*DHd;
        int d0 = lane, d1 = lane + 32;
        float q0=qraw[src+d0], q1=qraw[src+d1];
        float k0=kraw[src+d0], k1=kraw[src+d1];
        float w0=vraw[src+d0], w1=vraw[src+d1];
        float fq = l2fac(sqrtf(warpsum(q0*q0 + q1*q1)));
        float fk = l2fac(sqrtf(warpsum(k0*k0 + k1*k1)));
        float kn0 = k0*fk, kn1 = k1*fk;
        float bd = warpsum(kn0*wbn[d0] + kn1*wbn[d1]);
        size_t dst = ((size_t)(b*NH + h)*SEQn + s)*DHd;
        qh[dst+d0] = q0*fq*qs_l[h*DHd+d0]*1024.0f;   // Scale forward = param * D
        qh[dst+d1] = q1*fq*qs_l[h*DHd+d1]*1024.0f;
        kh[dst+d0] = kn0; kh[dst+d1] = kn1;
        float vv0, vv1;
        if(is_l0){ vv0=w0; vv1=w1; v0h[dst+d0]=w0; v0h[dst+d1]=w1; }
        else     { vv0=0.5f*(w0 + v0h[dst+d0]); vv1=0.5f*(w1 + v0h[dst+d1]); }
        vh[dst+d0]=vv0; vh[dst+d1]=vv1;
        if(lane==0) betab[(size_t)(b*NH+h)*SEQn + s] = 1.0f/(1.0f + expf(-bd));
    }
}

// ---------------- delta-rule recurrence; writes token-major o pre-scaled by 1/||Wo col|| ----------------
#define DCH 32
__global__ void delta_k(const float* __restrict__ qh, const float* __restrict__ kh,
                        const float* __restrict__ vh, const float* __restrict__ betab,
                        float* __restrict__ otok, const float* __restrict__ fWo){
    int bh = blockIdx.x;               // b*NH + h
    int b = bh / NH, h = bh % NH;
    int v = threadIdx.x;               // 0..63, owns state column v
    float St[DHd];
    #pragma unroll
    for(int i=0;i<DHd;i++) St[i] = 0.0f;

    __shared__ float ks[DCH*DHd];
    __shared__ float qs[DCH*DHd];
    __shared__ float vs[DCH*DHd];
    __shared__ float bs[DCH];

    size_t base = (size_t)bh*SEQn*DHd;
    float fo = fWo[h*DHd + v];

    for(int c0=0;c0<SEQn;c0+=DCH){
        __syncthreads();
        for(int i=v;i<DCH*DHd;i+=DHd){
            ks[i] = kh[base + (size_t)c0*DHd + i];
            qs[i] = qh[base + (size_t)c0*DHd + i];
            vs[i] = vh[base + (size_t)c0*DHd + i];
        }
        if(v < DCH) bs[v] = betab[(size_t)bh*SEQn + c0 + v];
        __syncthreads();
        for(int t=0;t<DCH;t++){
            const float* kt = &ks[t*DHd];
            const float* qt = &qs[t*DHd];
            float a0=0,a1=0,a2=0,a3=0;
            #pragma unroll
            for(int k=0;k<DHd;k+=4){
                a0 += kt[k  ]*St[k  ];
                a1 += kt[k+1]*St[k+1];
                a2 += kt[k+2]*St[k+2];
                a3 += kt[k+3]*St[k+3];
            }
            float kS = (a0+a1) + (a2+a3);
            float dlt = bs[t]*(vs[t*DHd + v] - kS);
            float o0=0,o1=0,o2=0,o3=0;
            #pragma unroll
            for(int k=0;k<DHd;k+=4){
                St[k  ] += kt[k  ]*dlt; o0 += qt[k  ]*St[k  ];
                St[k+1] += kt[k+1]*dlt; o1 += qt[k+1]*St[k+1];
                St[k+2] += kt[k+2]*dlt; o2 += qt[k+2]*St[k+2];
                St[k+3] += kt[k+3]*dlt; o3 += qt[k+3]*St[k+3];
            }
            float o = (o0+o1) + (o2+o3);
            otok[(size_t)(b*SEQn + c0 + t)*Dm + h*DHd + v] = o * fo;
        }
    }
}

// ---------------- residual: x = l2norm(x + alpha*ALPHA_FS*(l2norm(o) - x)) ----------------
__global__ void resid_k(float* __restrict__ x, const float* __restrict__ o,
                        const float* __restrict__ alpha){
    __shared__ float red[256];
    int m = blockIdx.x; int t = threadIdx.x;
    float ov[4]; float s = 0.0f;
    #pragma unroll
    for(int i=0;i<4;i++){ ov[i] = o[(size_t)m*Dm + t + i*256]; s += ov[i]*ov[i]; }
    s = blocksum256(s, red);
    float fh = l2fac(sqrtf(s));
    float yv[4]; float s2 = 0.0f;
    #pragma unroll
    for(int i=0;i<4;i++){
        int c = t + i*256;
        float xv = x[(size_t)m*Dm + c];
        float y = xv + alpha[c]*8.0f*(ov[i]*fh - xv);   // ALPHA_FS = (1/4)/(1024^-0.5) = 8
        yv[i] = y; s2 += y*y;
    }
    s2 = blocksum256(s2, red);
    float f2 = l2fac(sqrtf(s2));
    #pragma unroll
    for(int i=0;i<4;i++) x[(size_t)m*Dm + t + i*256] = yv[i]*f2;
}

// ---------------- z = silu(gate)*hidden * (1/||Wffo col||), in place into hidden ----------------
__global__ void ffmul_k(float* __restrict__ hb, const float* __restrict__ gbuf,
                        const float* __restrict__ fcol){
    size_t idx = (size_t)blockIdx.x*256 + threadIdx.x;
    if(idx >= (size_t)MT*DFFn) return;
    int c = (int)(idx % DFFn);
    float g = gbuf[idx];
    float sg = 1.0f/(1.0f + expf(-g));
    hb[idx] = g*sg*hb[idx]*fcol[c];
}

// ---------------- host ----------------
template<typename T> static float* symaddr(T& s){
    void* p = nullptr; cudaGetSymbolAddress(&p, s); return (float*)p;
}

extern "C" void kernel_launch(void* const* d_in, const int* in_sizes, int n_in,
                              void* d_out, int out_size){
    (void)in_sizes; (void)n_in; (void)out_size;
    const int*   ids        = (const int*)  d_in[0];
    const float* W_emb      = (const float*)d_in[2];
    const float* Wq         = (const float*)d_in[3];
    const float* Wk         = (const float*)d_in[4];
    const float* Wv         = (const float*)d_in[5];
    const float* Wbeta      = (const float*)d_in[6];
    const float* Wo         = (const float*)d_in[7];
    const float* Wffh       = (const float*)d_in[8];
    const float* Wffg       = (const float*)d_in[9];
    const float* Wffo       = (const float*)d_in[10];
    const float* qk_scale   = (const float*)d_in[11];
    const float* beta_scale = (const float*)d_in[12];
    const float* attn_alpha = (const float*)d_in[13];
    const float* ff_alpha   = (const float*)d_in[14];
    const float* ffh_scale  = (const float*)d_in[15];
    const float* ffg_scale  = (const float*)d_in[16];
    const float* W_logits   = (const float*)d_in[17];
    const float* logit_scale= (const float*)d_in[18];
    float* out = (float*)d_out;

    float* x    = symaddr(g_x);
    float* qraw = symaddr(g_qraw);
    float* kraw = symaddr(g_kraw);
    float* vraw = symaddr(g_vraw);
    float* qh   = symaddr(g_qh);
    float* kh   = symaddr(g_kh);
    float* vh   = symaddr(g_vh);
    float* v0h  = symaddr(g_v0h);
    float* betab= symaddr(g_betab);
    float* otok = symaddr(g_otok);
    float* ffh  = symaddr(g_ffh);
    float* ffg  = symaddr(g_ffg);
    float* fq   = symaddr(g_fq);
    float* fk   = symaddr(g_fk);
    float* fv   = symaddr(g_fv);
    float* fo   = symaddr(g_fo);
    float* fffh = symaddr(g_fffh);
    float* fffg = symaddr(g_fffg);
    float* fffo = symaddr(g_fffo);
    float* flog = symaddr(g_flog);
    float* wbn  = symaddr(g_wbn);

    // weight norm factors (all layers at once where row-major-contiguous)
    rownorm_k<<<NL*Dm, 256>>>(Wq,   fq,   Dm);
    rownorm_k<<<NL*Dm, 256>>>(Wk,   fk,   Dm);
    rownorm_k<<<NL*Dm, 256>>>(Wv,   fv,   Dm);
    rownorm_k<<<NL*DFFn, 256>>>(Wffh, fffh, Dm);
    rownorm_k<<<NL*DFFn, 256>>>(Wffg, fffg, Dm);
    rownorm_k<<<NV, 256>>>(W_logits, flog, Dm);
    colnorm_k<<<dim3((Dm+255)/256,   NL), 256>>>(Wo,   fo,   Dm, Dm);
    colnorm_k<<<dim3((DFFn+255)/256, NL), 256>>>(Wffo, fffo, Dm, DFFn);

    embed_k<<<MT, 256>>>(ids, W_emb, x);

    for(int l=0;l<NL;l++){
        size_t wofs = (size_t)l*Dm*Dm;
        // fused q/k/v projections (batched over gridDim.z)
        {
            GemmBatch gbt{};
            gbt.op[0] = { Wq + wofs, qraw, fq + l*Dm, nullptr, 1.0f };
            gbt.op[1] = { Wk + wofs, kraw, fk + l*Dm, nullptr, 1.0f };
            gbt.op[2] = { Wv + wofs, vraw, fv + l*Dm, nullptr, 1.0f };
            gemm_bt_k<64,64,4,4><<<dim3(16,16,3), 256>>>(x, gbt, MT, Dm, Dm);
        }
        wbeta_k<<<1, 64>>>(Wbeta, beta_scale, l, wbn);
        attn_prep_k<<<MT, 128>>>(qraw, kraw, vraw, qk_scale + l*Dm, wbn,
                                 qh, kh, vh, v0h, betab, (l==0) ? 1 : 0);
        delta_k<<<NB*NH, DHd>>>(qh, kh, vh, betab, otok, fo + l*Dm);
        // o projection (A pre-scaled with 1/||Wo col|| in delta epilogue)
        {
            GemmBatch gbt{};
            gbt.op[0] = { Wo + wofs, qraw, nullptr, nullptr, 1.0f };
            gemm_bt_k<64,64,4,4><<<dim3(16,16,1), 256>>>(otok, gbt, MT, Dm, Dm);
        }
        resid_k<<<MT, 256>>>(x, qraw, attn_alpha + l*Dm);
        // feedforward: hidden & gate batched
        {
            GemmBatch gbt{};
            gbt.op[0] = { Wffh + (size_t)l*DFFn*Dm, ffh, fffh + l*DFFn, ffh_scale + l*DFFn, 1.0f };
            gbt.op[1] = { Wffg + (size_t)l*DFFn*Dm, ffg, fffg + l*DFFn, ffg_scale + l*DFFn, 32.0f };
            gemm_bt_k<128,128,8,8><<<dim3((DFFn+127)/128, MT/128, 2), 256>>>(x, gbt, MT, DFFn, Dm);
        }
        ffmul_k<<<(MT*DFFn + 255)/256, 256>>>(ffh, ffg, fffo + l*DFFn);
        {
            GemmBatch gbt{};
            gbt.op[0] = { Wffo + (size_t)l*Dm*DFFn, qraw, nullptr, nullptr, 1.0f };
            gemm_bt_k<64,64,4,4><<<dim3(16,16,1), 256>>>(ffh, gbt, MT, Dm, DFFn);
        }
        resid_k<<<MT, 256>>>(x, qraw, ff_alpha + l*Dm);
    }
    // logits
    {
        GemmBatch gbt{};
        gbt.op[0] = { W_logits, out, flog, logit_scale, 32.0f };
        gemm_bt_k<128,128,8,8><<<dim3((NV+127)/128, MT/128, 1), 256>>>(x, gbt, MT, NV, Dm);
    }
}

// round 2
// speedup vs baseline: 1.5117x; 1.5117x over previous
#include <cuda_runtime.h>
#include <cuda_bf16.h>
#include <math.h>
#include <stdint.h>

#define Dm    1024
#define SEQn  512
#define NB    2
#define NH    16
#define DHd   64
#define DFFn  2730
#define DFFP  2816   // padded to 22*128
#define NV    32000
#define NL    4
#define MT    1024   // NB*SEQn tokens

// ---------------- device scratch (static; no runtime allocation) ----------------
__device__ float g_x[MT*Dm];
__device__ float g_qraw[MT*Dm];
__device__ float g_kraw[MT*Dm];
__device__ float g_vraw[MT*Dm];
__device__ float g_qh[NB*NH*SEQn*DHd];
__device__ float g_kh[NB*NH*SEQn*DHd];
__device__ float g_vh[NB*NH*SEQn*DHd];
__device__ float g_v0h[NB*NH*SEQn*DHd];
__device__ float g_betab[NB*NH*SEQn];
__device__ float g_otok[MT*Dm];
__device__ float g_ffh[MT*DFFP];
__device__ float g_ffg[MT*DFFP];
__device__ float g_wh[DFFP*Dm];    // padded, scaled Wffh copy
__device__ float g_wg[DFFP*Dm];    // padded, scaled Wffg copy
__device__ float g_wo[Dm*DFFP];    // padded, col-scaled Wffo copy
__device__ float g_fq[NL*Dm];
__device__ float g_fk[NL*Dm];
__device__ float g_fv[NL*Dm];
__device__ float g_fo[NL*Dm];
__device__ float g_fffh[NL*DFFn];
__device__ float g_fffg[NL*DFFn];
__device__ float g_fffo[NL*DFFn];
__device__ float g_flog[NV];
__device__ float g_wbn[DHd];

// ---------------- helpers ----------------
static __device__ __forceinline__ float l2fac(float n){
    float tgt = fminf(fmaxf(n, 1.0f - 1e-5f), 1.0f + 1e-5f);
    return 1.0f / fmaxf(n / tgt, 1e-10f);
}

static __device__ __forceinline__ float warpsum(float v){
    #pragma unroll
    for(int o=16;o>0;o>>=1) v += __shfl_xor_sync(0xffffffffu, v, o);
    return v;
}

static __device__ __forceinline__ float blocksum256(float v, float* red){
    red[threadIdx.x] = v; __syncthreads();
    for(int o=128;o>0;o>>=1){
        if(threadIdx.x < o) red[threadIdx.x] += red[threadIdx.x+o];
        __syncthreads();
    }
    float r = red[0]; __syncthreads();
    return r;
}

static __device__ __forceinline__ uint32_t f2tf32(float x){
    uint32_t u;
    asm("cvt.rna.tf32.f32 %0, %1;" : "=r"(u) : "f"(x));
    return u;
}

static __device__ __forceinline__ void mma_tf32(float& c0, float& c1, float& c2, float& c3,
                                                uint32_t a0, uint32_t a1, uint32_t a2, uint32_t a3,
                                                uint32_t b0, uint32_t b1){
    asm volatile("mma.sync.aligned.m16n8k8.row.col.f32.tf32.tf32.f32 "
                 "{%0,%1,%2,%3},{%4,%5,%6,%7},{%8,%9},{%0,%1,%2,%3};"
                 : "+f"(c0), "+f"(c1), "+f"(c2), "+f"(c3)
                 : "r"(a0), "r"(a1), "r"(a2), "r"(a3), "r"(b0), "r"(b1));
}

// ---------------- norm-factor kernels ----------------
__global__ void rownorm_k(const float* __restrict__ W, float* __restrict__ f, int C){
    __shared__ float red[256];
    int r = blockIdx.x;
    const float* row = W + (size_t)r*C;
    float s = 0.0f;
    for(int c=threadIdx.x;c<C;c+=256){ float w = row[c]; s += w*w; }
    s = blocksum256(s, red);
    if(threadIdx.x==0) f[r] = l2fac(sqrtf(s));
}

__global__ void colnorm_k(const float* __restrict__ W, float* __restrict__ f, int R, int C){
    int l = blockIdx.y;
    int c = blockIdx.x*blockDim.x + threadIdx.x;
    if(c >= C) return;
    const float* Wl = W + (size_t)l*R*C;
    float s = 0.0f;
    for(int r=0;r<R;r++){ float w = Wl[(size_t)r*C + c]; s += w*w; }
    f[(size_t)l*C + c] = l2fac(sqrtf(s));
}

// ---------------- embedding gather + row l2norm ----------------
__global__ void embed_k(const int* __restrict__ ids, const float* __restrict__ W_emb,
                        float* __restrict__ x){
    __shared__ float red[256];
    int m = blockIdx.x;
    int tok = ids[m];
    const float* row = W_emb + (size_t)tok*Dm;
    float v[4]; float s = 0.0f;
    #pragma unroll
    for(int i=0;i<4;i++){ v[i] = row[threadIdx.x + i*256]; s += v[i]*v[i]; }
    s = blocksum256(s, red);
    float f = l2fac(sqrtf(s));
    #pragma unroll
    for(int i=0;i<4;i++) x[(size_t)m*Dm + threadIdx.x + i*256] = v[i]*f;
}

// ---------------- padded scaled weight copies ----------------
// dst[DFFP][Dm] = (r < DFFn) ? src[r]*rs1[r]*rs2[r]*extra : 0
__global__ void padrow_k(const float* __restrict__ src, const float* __restrict__ rs1,
                         const float* __restrict__ rs2, float extra, float* __restrict__ dst){
    int r = blockIdx.x;
    float* dp = dst + (size_t)r*Dm;
    if(r < DFFn){
        float s = rs1[r]*rs2[r]*extra;
        const float* sp = src + (size_t)r*Dm;
        #pragma unroll
        for(int i=0;i<4;i++){ int c = threadIdx.x + i*256; dp[c] = sp[c]*s; }
    }else{
        #pragma unroll
        for(int i=0;i<4;i++) dp[threadIdx.x + i*256] = 0.0f;
    }
}

// dst[Dm][DFFP] = (k < DFFn) ? W[r][k]*cs[k] : 0
__global__ void padcol_k(const float* __restrict__ W, const float* __restrict__ cs,
                         float* __restrict__ dst){
    int r = blockIdx.x;
    const float* sp = W + (size_t)r*DFFn;
    float* dp = dst + (size_t)r*DFFP;
    for(int k=threadIdx.x;k<DFFP;k+=256)
        dp[k] = (k < DFFn) ? sp[k]*cs[k] : 0.0f;
}

// ---------------- 3xTF32 tensor-core GEMM: C[M,N] = A[M,K] @ B[N,K]^T ----------------
struct GemmOp { const float* B; float* C; const float* cf; const float* cs; float extra; };
struct GemmBatch { GemmOp op[3]; };

template<int BM, int BN, int WMW, int WNW>
__global__ void __launch_bounds__(WMW*WNW*32, 1) gemm_tf32_k(const float* __restrict__ A,
                                                             GemmBatch gbt, int M, int N, int K){
    constexpr int THREADS = WMW*WNW*32;
    constexpr int WTM = BM/WMW;        // warp tile M
    constexpr int WTN = BN/WNW;        // warp tile N
    constexpr int MI = WTM/16;
    constexpr int NJ = WTN/8;
    constexpr int BK = 16;
    constexpr int CA = BM*BK/(4*THREADS);   // float4 per thread for A tile
    constexpr int CB = BN*BK/(4*THREADS);

    const GemmOp op = gbt.op[blockIdx.z];
    const float* __restrict__ Bp = op.B;

    __shared__ uint32_t Ash[BK][BM+4], Asl[BK][BM+4];
    __shared__ uint32_t Bsh[BK][BN+4], Bsl[BK][BN+4];

    const int tid  = threadIdx.x;
    const int warp = tid >> 5, lane = tid & 31;
    const int wm = warp / WNW, wn = warp % WNW;
    const int g = lane >> 2, t = lane & 3;
    const int rowBase = blockIdx.y*BM, colBase = blockIdx.x*BN;

    float acc[MI][NJ][4];
    #pragma unroll
    for(int i=0;i<MI;i++)
        #pragma unroll
        for(int j=0;j<NJ;j++)
            #pragma unroll
            for(int e=0;e<4;e++) acc[i][j][e] = 0.0f;

    float4 pa[CA], pb[CB];
    // initial prefetch (k0 = 0)
    #pragma unroll
    for(int u=0;u<CA;u++){
        int idx = tid + u*THREADS; int r = idx>>2; int kc = (idx&3)<<2;
        pa[u] = *(const float4*)(A + (size_t)(rowBase+r)*K + kc);
    }
    #pragma unroll
    for(int u=0;u<CB;u++){
        int idx = tid + u*THREADS; int r = idx>>2; int kc = (idx&3)<<2;
        pb[u] = *(const float4*)(Bp + (size_t)(colBase+r)*K + kc);
    }

    for(int k0=0;k0<K;k0+=BK){
        // stage regs -> smem (hi/lo split)
        #pragma unroll
        for(int u=0;u<CA;u++){
            int idx = tid + u*THREADS; int r = idx>>2; int kc = (idx&3)<<2;
            float v[4] = {pa[u].x, pa[u].y, pa[u].z, pa[u].w};
            #pragma unroll
            for(int e=0;e<4;e++){
                uint32_t h = f2tf32(v[e]);
                float hf = __uint_as_float(h);
                Ash[kc+e][r] = h;
                Asl[kc+e][r] = f2tf32(v[e] - hf);
            }
        }
        #pragma unroll
        for(int u=0;u<CB;u++){
            int idx = tid + u*THREADS; int r = idx>>2; int kc = (idx&3)<<2;
            float v[4] = {pb[u].x, pb[u].y, pb[u].z, pb[u].w};
            #pragma unroll
            for(int e=0;e<4;e++){
                uint32_t h = f2tf32(v[e]);
                float hf = __uint_as_float(h);
                Bsh[kc+e][r] = h;
                Bsl[kc+e][r] = f2tf32(v[e] - hf);
            }
        }
        __syncthreads();

        // prefetch next tile
        if(k0 + BK < K){
            #pragma unroll
            for(int u=0;u<CA;u++){
                int idx = tid + u*THREADS; int r = idx>>2; int kc = (idx&3)<<2;
                pa[u] = *(const float4*)(A + (size_t)(rowBase+r)*K + k0 + BK + kc);
            }
            #pragma unroll
            for(int u=0;u<CB;u++){
                int idx = tid + u*THREADS; int r = idx>>2; int kc = (idx&3)<<2;
                pb[u] = *(const float4*)(Bp + (size_t)(colBase+r)*K + k0 + BK + kc);
            }
        }

        // compute 2 k8-steps
        #pragma unroll
        for(int kk=0;kk<BK;kk+=8){
            uint32_t ah[MI][4], al[MI][4], bh[NJ][2], bl[NJ][2];
            #pragma unroll
            for(int i=0;i<MI;i++){
                int m = wm*WTM + i*16 + g;
                ah[i][0] = Ash[kk+t  ][m];   ah[i][1] = Ash[kk+t  ][m+8];
                ah[i][2] = Ash[kk+t+4][m];   ah[i][3] = Ash[kk+t+4][m+8];
                al[i][0] = Asl[kk+t  ][m];   al[i][1] = Asl[kk+t  ][m+8];
                al[i][2] = Asl[kk+t+4][m];   al[i][3] = Asl[kk+t+4][m+8];
            }
            #pragma unroll
            for(int j=0;j<NJ;j++){
                int n = wn*WTN + j*8 + g;
                bh[j][0] = Bsh[kk+t][n];  bh[j][1] = Bsh[kk+t+4][n];
                bl[j][0] = Bsl[kk+t][n];  bl[j][1] = Bsl[kk+t+4][n];
            }
            #pragma unroll
            for(int i=0;i<MI;i++)
                #pragma unroll
                for(int j=0;j<NJ;j++){
                    mma_tf32(acc[i][j][0], acc[i][j][1], acc[i][j][2], acc[i][j][3],
                             ah[i][0], ah[i][1], ah[i][2], ah[i][3], bh[j][0], bh[j][1]);
                    mma_tf32(acc[i][j][0], acc[i][j][1], acc[i][j][2], acc[i][j][3],
                             ah[i][0], ah[i][1], ah[i][2], ah[i][3], bl[j][0], bl[j][1]);
                    mma_tf32(acc[i][j][0], acc[i][j][1], acc[i][j][2], acc[i][j][3],
                             al[i][0], al[i][1], al[i][2], al[i][3], bh[j][0], bh[j][1]);
                }
        }
        __syncthreads();
    }

    // epilogue
    #pragma unroll
    for(int j=0;j<NJ;j++){
        int c = colBase + wn*WTN + j*8 + t*2;
        float s0 = op.extra, s1 = op.extra;
        if(op.cf){ s0 *= op.cf[c]; s1 *= op.cf[c+1]; }
        if(op.cs){ s0 *= op.cs[c]; s1 *= op.cs[c+1]; }
        #pragma unroll
        for(int i=0;i<MI;i++){
            int r = rowBase + wm*WTM + i*16 + g;
            float2 v0 = make_float2(acc[i][j][0]*s0, acc[i][j][1]*s1);
            float2 v1 = make_float2(acc[i][j][2]*s0, acc[i][j][3]*s1);
            *(float2*)(op.C + (size_t)r*N + c)     = v0;
            *(float2*)(op.C + (size_t)(r+8)*N + c) = v1;
        }
    }
}

// ---------------- wbeta ----------------
__global__ void wbeta_k(const float* __restrict__ Wb, const float* __restrict__ bscale,
                        int l, float* __restrict__ out){
    __shared__ float red[64]; __shared__ float stot;
    int t = threadIdx.x;
    float w = Wb[l*DHd + t];
    red[t] = w*w; __syncthreads();
    if(t<32) red[t] += red[t+32];
    __syncthreads();
    if(t==0){ float s=0; for(int i=0;i<32;i++) s += red[i]; stot = s; }
    __syncthreads();
    float fac = l2fac(sqrtf(stot));
    out[t] = w * fac * (bscale[l] * 0.1f);
}

// ---------------- per-head l2norm + beta + layout transform + value residual ----------------
__global__ void attn_prep_k(const float* __restrict__ qraw, const float* __restrict__ kraw,
                            const float* __restrict__ vraw, const float* __restrict__ qs_l,
                            const float* __restrict__ wbn,
                            float* __restrict__ qh, float* __restrict__ kh,
                            float* __restrict__ vh, float* __restrict__ v0h,
                            float* __restrict__ betab, int is_l0){
    int m = blockIdx.x;
    int b = m / SEQn, s = m % SEQn;
    int lane = threadIdx.x & 31, warp = threadIdx.x >> 5;
    #pragma unroll
    for(int hi=0; hi<NH/4; hi++){
        int h = warp*4 + hi;
        size_t src = (size_t)m*Dm + h*DHd;
        int d0 = lane, d1 = lane + 32;
        float q0=qraw[src+d0], q1=qraw[src+d1];
        float k0=kraw[src+d0], k1=kraw[src+d1];
        float w0=vraw[src+d0], w1=vraw[src+d1];
        float fq = l2fac(sqrtf(warpsum(q0*q0 + q1*q1)));
        float fk = l2fac(sqrtf(warpsum(k0*k0 + k1*k1)));
        float kn0 = k0*fk, kn1 = k1*fk;
        float bd = warpsum(kn0*wbn[d0] + kn1*wbn[d1]);
        size_t dst = ((size_t)(b*NH + h)*SEQn + s)*DHd;
        qh[dst+d0] = q0*fq*qs_l[h*DHd+d0]*1024.0f;
        qh[dst+d1] = q1*fq*qs_l[h*DHd+d1]*1024.0f;
        kh[dst+d0] = kn0; kh[dst+d1] = kn1;
        float vv0, vv1;
        if(is_l0){ vv0=w0; vv1=w1; v0h[dst+d0]=w0; v0h[dst+d1]=w1; }
        else     { vv0=0.5f*(w0 + v0h[dst+d0]); vv1=0.5f*(w1 + v0h[dst+d1]); }
        vh[dst+d0]=vv0; vh[dst+d1]=vv1;
        if(lane==0) betab[(size_t)(b*NH+h)*SEQn + s] = 1.0f/(1.0f + expf(-bd));
    }
}

// ---------------- delta-rule recurrence ----------------
#define DCH 32
__global__ void delta_k(const float* __restrict__ qh, const float* __restrict__ kh,
                        const float* __restrict__ vh, const float* __restrict__ betab,
                        float* __restrict__ otok, const float* __restrict__ fWo){
    int bh = blockIdx.x;
    int b = bh / NH, h = bh % NH;
    int v = threadIdx.x;
    float St[DHd];
    #pragma unroll
    for(int i=0;i<DHd;i++) St[i] = 0.0f;

    __shared__ float ks[DCH*DHd];
    __shared__ float qs[DCH*DHd];
    __shared__ float vs[DCH*DHd];
    __shared__ float bs[DCH];

    size_t base = (size_t)bh*SEQn*DHd;
    float fo = fWo[h*DHd + v];

    for(int c0=0;c0<SEQn;c0+=DCH){
        __syncthreads();
        for(int i=v;i<DCH*DHd;i+=DHd){
            ks[i] = kh[base + (size_t)c0*DHd + i];
            qs[i] = qh[base + (size_t)c0*DHd + i];
            vs[i] = vh[base + (size_t)c0*DHd + i];
        }
        if(v < DCH) bs[v] = betab[(size_t)bh*SEQn + c0 + v];
        __syncthreads();
        for(int t=0;t<DCH;t++){
            const float* kt = &ks[t*DHd];
            const float* qt = &qs[t*DHd];
            float a0=0,a1=0,a2=0,a3=0;
            #pragma unroll
            for(int k=0;k<DHd;k+=4){
                a0 += kt[k  ]*St[k  ];
                a1 += kt[k+1]*St[k+1];
                a2 += kt[k+2]*St[k+2];
                a3 += kt[k+3]*St[k+3];
            }
            float kS = (a0+a1) + (a2+a3);
            float dlt = bs[t]*(vs[t*DHd + v] - kS);
            float o0=0,o1=0,o2=0,o3=0;
            #pragma unroll
            for(int k=0;k<DHd;k+=4){
                St[k  ] += kt[k  ]*dlt; o0 += qt[k  ]*St[k  ];
                St[k+1] += kt[k+1]*dlt; o1 += qt[k+1]*St[k+1];
                St[k+2] += kt[k+2]*dlt; o2 += qt[k+2]*St[k+2];
                St[k+3] += kt[k+3]*dlt; o3 += qt[k+3]*St[k+3];
            }
            float o = (o0+o1) + (o2+o3);
            otok[(size_t)(b*SEQn + c0 + t)*Dm + h*DHd + v] = o * fo;
        }
    }
}

// ---------------- residual ----------------
__global__ void resid_k(float* __restrict__ x, const float* __restrict__ o,
                        const float* __restrict__ alpha){
    __shared__ float red[256];
    int m = blockIdx.x; int t = threadIdx.x;
    float ov[4]; float s = 0.0f;
    #pragma unroll
    for(int i=0;i<4;i++){ ov[i] = o[(size_t)m*Dm + t + i*256]; s += ov[i]*ov[i]; }
    s = blocksum256(s, red);
    float fh = l2fac(sqrtf(s));
    float yv[4]; float s2 = 0.0f;
    #pragma unroll
    for(int i=0;i<4;i++){
        int c = t + i*256;
        float xv = x[(size_t)m*Dm + c];
        float y = xv + alpha[c]*8.0f*(ov[i]*fh - xv);
        yv[i] = y; s2 += y*y;
    }
    s2 = blocksum256(s2, red);
    float f2 = l2fac(sqrtf(s2));
    #pragma unroll
    for(int i=0;i<4;i++) x[(size_t)m*Dm + t + i*256] = yv[i]*f2;
}

// ---------------- z = silu(gate)*hidden (padded region stays zero) ----------------
__global__ void ffmul_k(float* __restrict__ hb, const float* __restrict__ gbuf){
    size_t idx = (size_t)blockIdx.x*256 + threadIdx.x;
    if(idx >= (size_t)MT*DFFP) return;
    float g = gbuf[idx];
    float sg = 1.0f/(1.0f + expf(-g));
    hb[idx] = g*sg*hb[idx];
}

// ---------------- host ----------------
template<typename T> static float* symaddr(T& s){
    void* p = nullptr; cudaGetSymbolAddress(&p, s); return (float*)p;
}

extern "C" void kernel_launch(void* const* d_in, const int* in_sizes, int n_in,
                              void* d_out, int out_size){
    (void)in_sizes; (void)n_in; (void)out_size;
    const int*   ids        = (const int*)  d_in[0];
    const float* W_emb      = (const float*)d_in[2];
    const float* Wq         = (const float*)d_in[3];
    const float* Wk         = (const float*)d_in[4];
    const float* Wv         = (const float*)d_in[5];
    const float* Wbeta      = (const float*)d_in[6];
    const float* Wo         = (const float*)d_in[7];
    const float* Wffh       = (const float*)d_in[8];
    const float* Wffg       = (const float*)d_in[9];
    const float* Wffo       = (const float*)d_in[10];
    const float* qk_scale   = (const float*)d_in[11];
    const float* beta_scale = (const float*)d_in[12];
    const float* attn_alpha = (const float*)d_in[13];
    const float* ff_alpha   = (const float*)d_in[14];
    const float* ffh_scale  = (const float*)d_in[15];
    const float* ffg_scale  = (const float*)d_in[16];
    const float* W_logits   = (const float*)d_in[17];
    const float* logit_scale= (const float*)d_in[18];
    float* out = (float*)d_out;

    float* x    = symaddr(g_x);
    float* qraw = symaddr(g_qraw);
    float* kraw = symaddr(g_kraw);
    float* vraw = symaddr(g_vraw);
    float* qh   = symaddr(g_qh);
    float* kh   = symaddr(g_kh);
    float* vh   = symaddr(g_vh);
    float* v0h  = symaddr(g_v0h);
    float* betab= symaddr(g_betab);
    float* otok = symaddr(g_otok);
    float* ffh  = symaddr(g_ffh);
    float* ffg  = symaddr(g_ffg);
    float* wh   = symaddr(g_wh);
    float* wg   = symaddr(g_wg);
    float* wo   = symaddr(g_wo);
    float* fq   = symaddr(g_fq);
    float* fk   = symaddr(g_fk);
    float* fv   = symaddr(g_fv);
    float* fo   = symaddr(g_fo);
    float* fffh = symaddr(g_fffh);
    float* fffg = symaddr(g_fffg);
    float* fffo = symaddr(g_fffo);
    float* flog = symaddr(g_flog);
    float* wbn  = symaddr(g_wbn);

    rownorm_k<<<NL*Dm, 256>>>(Wq,   fq,   Dm);
    rownorm_k<<<NL*Dm, 256>>>(Wk,   fk,   Dm);
    rownorm_k<<<NL*Dm, 256>>>(Wv,   fv,   Dm);
    rownorm_k<<<NL*DFFn, 256>>>(Wffh, fffh, Dm);
    rownorm_k<<<NL*DFFn, 256>>>(Wffg, fffg, Dm);
    rownorm_k<<<NV, 256>>>(W_logits, flog, Dm);
    colnorm_k<<<dim3((Dm+255)/256,   NL), 256>>>(Wo,   fo,   Dm, Dm);
    colnorm_k<<<dim3((DFFn+255)/256, NL), 256>>>(Wffo, fffo, Dm, DFFn);

    embed_k<<<MT, 256>>>(ids, W_emb, x);

    for(int l=0;l<NL;l++){
        size_t wofs = (size_t)l*Dm*Dm;
        // fused q/k/v projections (batched over gridDim.z)
        {
            GemmBatch gbt{};
            gbt.op[0] = { Wq + wofs, qraw, fq + l*Dm, nullptr, 1.0f };
            gbt.op[1] = { Wk + wofs, kraw, fk + l*Dm, nullptr, 1.0f };
            gbt.op[2] = { Wv + wofs, vraw, fv + l*Dm, nullptr, 1.0f };
            gemm_tf32_k<64,64,2,2><<<dim3(16,16,3), 128>>>(x, gbt, MT, Dm, Dm);
        }
        wbeta_k<<<1, 64>>>(Wbeta, beta_scale, l, wbn);
        attn_prep_k<<<MT, 128>>>(qraw, kraw, vraw, qk_scale + l*Dm, wbn,
                                 qh, kh, vh, v0h, betab, (l==0) ? 1 : 0);
        delta_k<<<NB*NH, DHd>>>(qh, kh, vh, betab, otok, fo + l*Dm);
        // o projection
        {
            GemmBatch gbt{};
            gbt.op[0] = { Wo + wofs, qraw, nullptr, nullptr, 1.0f };
            gemm_tf32_k<64,64,2,2><<<dim3(16,16,1), 128>>>(otok, gbt, MT, Dm, Dm);
        }
        resid_k<<<MT, 256>>>(x, qraw, attn_alpha + l*Dm);
        // padded scaled weight copies for ff
        padrow_k<<<DFFP, 256>>>(Wffh + (size_t)l*DFFn*Dm, fffh + l*DFFn, ffh_scale + l*DFFn, 1.0f, wh);
        padrow_k<<<DFFP, 256>>>(Wffg + (size_t)l*DFFn*Dm, fffg + l*DFFn, ffg_scale + l*DFFn, 32.0f, wg);
        padcol_k<<<Dm, 256>>>(Wffo + (size_t)l*Dm*DFFn, fffo + l*DFFn, wo);
        // feedforward hidden & gate (epilogue-free; scales folded into weight copies)
        {
            GemmBatch gbt{};
            gbt.op[0] = { wh, ffh, nullptr, nullptr, 1.0f };
            gbt.op[1] = { wg, ffg, nullptr, nullptr, 1.0f };
            gemm_tf32_k<128,128,2,4><<<dim3(DFFP/128, MT/128, 2), 256>>>(x, gbt, MT, DFFP, Dm);
        }
        ffmul_k<<<(MT*DFFP + 255)/256, 256>>>(ffh, ffg);
        {
            GemmBatch gbt{};
            gbt.op[0] = { wo, qraw, nullptr, nullptr, 1.0f };
            gemm_tf32_k<64,64,2,2><<<dim3(16,16,1), 128>>>(ffh, gbt, MT, Dm, DFFP);
        }
        resid_k<<<MT, 256>>>(x, qraw, ff_alpha + l*Dm);
    }
    // logits
    {
        GemmBatch gbt{};
        gbt.op[0] = { W_logits, out, flog, logit_scale, 32.0f };
        gemm_tf32_k<128,128,2,4><<<dim3(NV/128, MT/128, 1), 256>>>(x, gbt, MT, NV, Dm);
    }
}

// round 3
// speedup vs baseline: 1.5781x; 1.0440x over previous
#include <cuda_runtime.h>
#include <cuda_bf16.h>
#include <math.h>
#include <stdint.h>

#define Dm    1024
#define SEQn  512
#define NB    2
#define NH    16
#define DHd   64
#define DFFn  2730
#define DFFP  2816   // padded to 22*128
#define NV    32000
#define NL    4
#define MT    1024   // NB*SEQn tokens

// ---------------- device scratch ----------------
__device__ float g_x[MT*Dm];
__device__ float g_qraw[MT*Dm];
__device__ float g_kraw[MT*Dm];
__device__ float g_vraw[MT*Dm];
__device__ float g_qh[NB*NH*SEQn*DHd];
__device__ float g_kh[NB*NH*SEQn*DHd];
__device__ float g_vh[NB*NH*SEQn*DHd];
__device__ float g_v0h[NB*NH*SEQn*DHd];
__device__ float g_betab[NB*NH*SEQn];
__device__ float g_ffh[MT*DFFP];
__device__ float g_ffg[MT*DFFP];
__device__ float g_fq[NL*Dm];
__device__ float g_fk[NL*Dm];
__device__ float g_fv[NL*Dm];
__device__ float g_fo[NL*Dm];
__device__ float g_fffh[NL*DFFn];
__device__ float g_fffg[NL*DFFn];
__device__ float g_fffo[NL*DFFn];
__device__ float g_flog[NV];
__device__ float g_wbn[DHd];

// packed bf16 hi/lo pair buffers (uint4 for 16B alignment; logical uint2 per k-pair)
__device__ uint4 g_xp [MT*Dm/4];
__device__ uint4 g_op [MT*Dm/4];
__device__ uint4 g_zp [MT*DFFP/4];
__device__ uint4 g_wqp[NL*Dm*Dm/4];
__device__ uint4 g_wkp[NL*Dm*Dm/4];
__device__ uint4 g_wvp[NL*Dm*Dm/4];
__device__ uint4 g_wop[NL*Dm*Dm/4];
__device__ uint4 g_whp[NL*DFFP*Dm/4];
__device__ uint4 g_wgp[NL*DFFP*Dm/4];
__device__ uint4 g_wfp[NL*Dm*DFFP/4];
__device__ uint4 g_wlp[(size_t)NV*Dm/4];

// ---------------- helpers ----------------
static __device__ __forceinline__ float l2fac(float n){
    float tgt = fminf(fmaxf(n, 1.0f - 1e-5f), 1.0f + 1e-5f);
    return 1.0f / fmaxf(n / tgt, 1e-10f);
}

static __device__ __forceinline__ float warpsum(float v){
    #pragma unroll
    for(int o=16;o>0;o>>=1) v += __shfl_xor_sync(0xffffffffu, v, o);
    return v;
}

static __device__ __forceinline__ float blocksum256(float v, float* red){
    red[threadIdx.x] = v; __syncthreads();
    for(int o=128;o>0;o>>=1){
        if(threadIdx.x < o) red[threadIdx.x] += red[threadIdx.x+o];
        __syncthreads();
    }
    float r = red[0]; __syncthreads();
    return r;
}

// split (x0,x1) into bf16 hi pair word + bf16 lo pair word
static __device__ __forceinline__ uint2 packsplit(float x0, float x1){
    __nv_bfloat162 h = __floats2bfloat162_rn(x0, x1);
    float r0 = x0 - __bfloat162float(__low2bfloat16(h));
    float r1 = x1 - __bfloat162float(__high2bfloat16(h));
    __nv_bfloat162 lo = __floats2bfloat162_rn(r0, r1);
    uint2 u;
    u.x = *reinterpret_cast<uint32_t*>(&h);
    u.y = *reinterpret_cast<uint32_t*>(&lo);
    return u;
}

static __device__ __forceinline__ void mma_bf16(float& c0, float& c1, float& c2, float& c3,
                                                uint32_t a0, uint32_t a1, uint32_t a2, uint32_t a3,
                                                uint32_t b0, uint32_t b1){
    asm volatile("mma.sync.aligned.m16n8k16.row.col.f32.bf16.bf16.f32 "
                 "{%0,%1,%2,%3},{%4,%5,%6,%7},{%8,%9},{%0,%1,%2,%3};"
                 : "+f"(c0), "+f"(c1), "+f"(c2), "+f"(c3)
                 : "r"(a0), "r"(a1), "r"(a2), "r"(a3), "r"(b0), "r"(b1));
}

// ---------------- norm-factor kernels ----------------
__global__ void rownorm_k(const float* __restrict__ W, float* __restrict__ f, int C){
    __shared__ float red[256];
    int r = blockIdx.x;
    const float* row = W + (size_t)r*C;
    float s = 0.0f;
    for(int c=threadIdx.x;c<C;c+=256){ float w = row[c]; s += w*w; }
    s = blocksum256(s, red);
    if(threadIdx.x==0) f[r] = l2fac(sqrtf(s));
}

__global__ void colnorm_k(const float* __restrict__ W, float* __restrict__ f, int R, int C){
    int l = blockIdx.y;
    int c = blockIdx.x*blockDim.x + threadIdx.x;
    if(c >= C) return;
    const float* Wl = W + (size_t)l*R*C;
    float s = 0.0f;
    for(int r=0;r<R;r++){ float w = Wl[(size_t)r*C + c]; s += w*w; }
    f[(size_t)l*C + c] = l2fac(sqrtf(s));
}

// ---------------- weight packing ----------------
// layered rows: dst row r -> layer l=r/NdstL, local rr; src row l*NsrcL+rr if rr<NsrcL else zeros
__global__ void wpackL_k(const float* __restrict__ W, const float* __restrict__ rs1,
                         const float* __restrict__ rs2, float extra,
                         int NdstL, int NsrcL, int K, uint4* __restrict__ dst){
    int r = blockIdx.x;
    int l = r / NdstL, rr = r - l*NdstL;
    uint2* dp = (uint2*)(dst + (size_t)r*(K>>2));
    int K2 = K>>1;
    if(rr >= NsrcL){
        for(int k2=threadIdx.x;k2<K2;k2+=blockDim.x) dp[k2] = make_uint2(0u,0u);
        return;
    }
    size_t sr = (size_t)l*NsrcL + rr;
    float s = extra;
    if(rs1) s *= rs1[sr];
    if(rs2) s *= rs2[sr];
    const float2* sp = (const float2*)(W + sr*K);
    for(int k2=threadIdx.x;k2<K2;k2+=blockDim.x){
        float2 v = sp[k2];
        dp[k2] = packsplit(v.x*s, v.y*s);
    }
}

// ffo: W [L][Dm][DFFn], k-scale ks[L][DFFn], pad K to DFFP
__global__ void wpackO_k(const float* __restrict__ W, const float* __restrict__ ks,
                         uint4* __restrict__ dst){
    int r = blockIdx.x;             // 0..NL*Dm-1
    int l = r / Dm;
    const float* sp = W + (size_t)l*Dm*DFFn + (size_t)(r - l*Dm)*DFFn;
    const float* ksl = ks + (size_t)l*DFFn;
    uint2* dp = (uint2*)(dst + (size_t)r*(DFFP>>2));
    for(int k2=threadIdx.x;k2<DFFP/2;k2+=blockDim.x){
        int k = 2*k2;
        float x0 = (k   < DFFn) ? sp[k  ]*ksl[k  ] : 0.0f;
        float x1 = (k+1 < DFFn) ? sp[k+1]*ksl[k+1] : 0.0f;
        dp[k2] = packsplit(x0, x1);
    }
}

// ---------------- embedding gather + row l2norm (fp32 + packed out) ----------------
__global__ void embed_k(const int* __restrict__ ids, const float* __restrict__ W_emb,
                        float* __restrict__ x, uint4* __restrict__ xp){
    __shared__ float red[256];
    int m = blockIdx.x, t = threadIdx.x;
    int tok = ids[m];
    const float2* row2 = (const float2*)(W_emb + (size_t)tok*Dm);
    float2 a = row2[t], b = row2[t+256];
    float s = a.x*a.x + a.y*a.y + b.x*b.x + b.y*b.y;
    s = blocksum256(s, red);
    float f = l2fac(sqrtf(s));
    a.x*=f; a.y*=f; b.x*=f; b.y*=f;
    float2* x2 = (float2*)(x + (size_t)m*Dm);
    x2[t] = a; x2[t+256] = b;
    uint2* xpp = (uint2*)xp + (size_t)m*(Dm/2);
    xpp[t]     = packsplit(a.x, a.y);
    xpp[t+256] = packsplit(b.x, b.y);
}

// ---------------- pure-bf16x3 tensor GEMM: C[M,N] = A[M,K] @ B[N,K]^T ----------------
struct GOp { const uint4* B; float* C; };
struct GBatch { GOp op[3]; };

template<int BM, int BN, int WMW, int WNW>
__global__ void __launch_bounds__(WMW*WNW*32, 1) gemm_bf16x3_k(const uint4* __restrict__ A,
                                                               GBatch gbt, int M, int N, int K){
    constexpr int THREADS = WMW*WNW*32;
    constexpr int WTM = BM/WMW, WTN = BN/WNW;
    constexpr int MI = WTM/16, NJ = WTN/8;
    constexpr int BK = 32, BK2 = 16, PAD = 8;   // (BM+PAD)%32==8 -> conflict-free frag loads
    constexpr int CA = BM*8/THREADS;            // uint4 per thread for A tile (BM rows x 8 uint4)
    constexpr int CB = BN*8/THREADS;

    const GOp op = gbt.op[blockIdx.z];
    const uint4* __restrict__ Bp = op.B;

    __shared__ uint32_t Ah[BK2][BM+PAD], Al[BK2][BM+PAD];
    __shared__ uint32_t Bh[BK2][BN+PAD], Bl[BK2][BN+PAD];

    const int tid = threadIdx.x, warp = tid>>5, lane = tid&31;
    const int wm = warp / WNW, wn = warp % WNW;
    const int g = lane>>2, t = lane&3;
    const int rowBase = blockIdx.y*BM, colBase = blockIdx.x*BN;
    const int Kq = K>>2;

    float acc[MI][NJ][4];
    #pragma unroll
    for(int i=0;i<MI;i++)
        #pragma unroll
        for(int j=0;j<NJ;j++)
            #pragma unroll
            for(int e=0;e<4;e++) acc[i][j][e] = 0.0f;

    uint4 pa[CA], pb[CB];
    #pragma unroll
    for(int u=0;u<CA;u++){
        int idx = tid + u*THREADS; int r = idx>>3, q = idx&7;
        pa[u] = A[(size_t)(rowBase+r)*Kq + q];
    }
    #pragma unroll
    for(int u=0;u<CB;u++){
        int idx = tid + u*THREADS; int r = idx>>3, q = idx&7;
        pb[u] = Bp[(size_t)(colBase+r)*Kq + q];
    }

    for(int k0=0;k0<K;k0+=BK){
        #pragma unroll
        for(int u=0;u<CA;u++){
            int idx = tid + u*THREADS; int r = idx>>3, k2 = (idx&7)*2;
            Ah[k2  ][r] = pa[u].x;  Al[k2  ][r] = pa[u].y;
            Ah[k2+1][r] = pa[u].z;  Al[k2+1][r] = pa[u].w;
        }
        #pragma unroll
        for(int u=0;u<CB;u++){
            int idx = tid + u*THREADS; int r = idx>>3, k2 = (idx&7)*2;
            Bh[k2  ][r] = pb[u].x;  Bl[k2  ][r] = pb[u].y;
            Bh[k2+1][r] = pb[u].z;  Bl[k2+1][r] = pb[u].w;
        }
        __syncthreads();

        if(k0 + BK < K){
            int kq = (k0 + BK)>>2;
            #pragma unroll
            for(int u=0;u<CA;u++){
                int idx = tid + u*THREADS; int r = idx>>3, q = idx&7;
                pa[u] = A[(size_t)(rowBase+r)*Kq + kq + q];
            }
            #pragma unroll
            for(int u=0;u<CB;u++){
                int idx = tid + u*THREADS; int r = idx>>3, q = idx&7;
                pb[u] = Bp[(size_t)(colBase+r)*Kq + kq + q];
            }
        }

        #pragma unroll
        for(int s=0;s<2;s++){
            const int kk = s*8;
            uint32_t ah[MI][4], al[MI][4], bh[NJ][2], bl[NJ][2];
            #pragma unroll
            for(int i=0;i<MI;i++){
                int m = wm*WTM + i*16 + g;
                ah[i][0] = Ah[kk+t  ][m];   ah[i][1] = Ah[kk+t  ][m+8];
                ah[i][2] = Ah[kk+t+4][m];   ah[i][3] = Ah[kk+t+4][m+8];
                al[i][0] = Al[kk+t  ][m];   al[i][1] = Al[kk+t  ][m+8];
                al[i][2] = Al[kk+t+4][m];   al[i][3] = Al[kk+t+4][m+8];
            }
            #pragma unroll
            for(int j=0;j<NJ;j++){
                int n = wn*WTN + j*8 + g;
                bh[j][0] = Bh[kk+t][n];  bh[j][1] = Bh[kk+t+4][n];
                bl[j][0] = Bl[kk+t][n];  bl[j][1] = Bl[kk+t+4][n];
            }
            #pragma unroll
            for(int i=0;i<MI;i++)
                #pragma unroll
                for(int j=0;j<NJ;j++){
                    mma_bf16(acc[i][j][0], acc[i][j][1], acc[i][j][2], acc[i][j][3],
                             ah[i][0], ah[i][1], ah[i][2], ah[i][3], bh[j][0], bh[j][1]);
                    mma_bf16(acc[i][j][0], acc[i][j][1], acc[i][j][2], acc[i][j][3],
                             ah[i][0], ah[i][1], ah[i][2], ah[i][3], bl[j][0], bl[j][1]);
                    mma_bf16(acc[i][j][0], acc[i][j][1], acc[i][j][2], acc[i][j][3],
                             al[i][0], al[i][1], al[i][2], al[i][3], bh[j][0], bh[j][1]);
                }
        }
        __syncthreads();
    }

    #pragma unroll
    for(int j=0;j<NJ;j++){
        int c = colBase + wn*WTN + j*8 + t*2;
        #pragma unroll
        for(int i=0;i<MI;i++){
            int r = rowBase + wm*WTM + i*16 + g;
            *(float2*)(op.C + (size_t)r*N + c)     = make_float2(acc[i][j][0], acc[i][j][1]);
            *(float2*)(op.C + (size_t)(r+8)*N + c) = make_float2(acc[i][j][2], acc[i][j][3]);
        }
    }
}

// ---------------- wbeta ----------------
__global__ void wbeta_k(const float* __restrict__ Wb, const float* __restrict__ bscale,
                        int l, float* __restrict__ out){
    __shared__ float red[64]; __shared__ float stot;
    int t = threadIdx.x;
    float w = Wb[l*DHd + t];
    red[t] = w*w; __syncthreads();
    if(t<32) red[t] += red[t+32];
    __syncthreads();
    if(t==0){ float s=0; for(int i=0;i<32;i++) s += red[i]; stot = s; }
    __syncthreads();
    float fac = l2fac(sqrtf(stot));
    out[t] = w * fac * (bscale[l] * 0.1f);
}

// ---------------- per-head l2norm + beta + layout transform + value residual ----------------
__global__ void attn_prep_k(const float* __restrict__ qraw, const float* __restrict__ kraw,
                            const float* __restrict__ vraw, const float* __restrict__ qs_l,
                            const float* __restrict__ wbn,
                            float* __restrict__ qh, float* __restrict__ kh,
                            float* __restrict__ vh, float* __restrict__ v0h,
                            float* __restrict__ betab, int is_l0){
    int m = blockIdx.x;
    int b = m / SEQn, s = m % SEQn;
    int lane = threadIdx.x & 31, warp = threadIdx.x >> 5;
    #pragma unroll
    for(int hi=0; hi<NH/4; hi++){
        int h = warp*4 + hi;
        size_t src = (size_t)m*Dm + h*DHd;
        int d0 = lane, d1 = lane + 32;
        float q0=qraw[src+d0], q1=qraw[src+d1];
        float k0=kraw[src+d0], k1=kraw[src+d1];
        float w0=vraw[src+d0], w1=vraw[src+d1];
        float fq = l2fac(sqrtf(warpsum(q0*q0 + q1*q1)));
        float fk = l2fac(sqrtf(warpsum(k0*k0 + k1*k1)));
        float kn0 = k0*fk, kn1 = k1*fk;
        float bd = warpsum(kn0*wbn[d0] + kn1*wbn[d1]);
        size_t dst = ((size_t)(b*NH + h)*SEQn + s)*DHd;
        qh[dst+d0] = q0*fq*qs_l[h*DHd+d0]*1024.0f;
        qh[dst+d1] = q1*fq*qs_l[h*DHd+d1]*1024.0f;
        kh[dst+d0] = kn0; kh[dst+d1] = kn1;
        float vv0, vv1;
        if(is_l0){ vv0=w0; vv1=w1; v0h[dst+d0]=w0; v0h[dst+d1]=w1; }
        else     { vv0=0.5f*(w0 + v0h[dst+d0]); vv1=0.5f*(w1 + v0h[dst+d1]); }
        vh[dst+d0]=vv0; vh[dst+d1]=vv1;
        if(lane==0) betab[(size_t)(b*NH+h)*SEQn + s] = 1.0f/(1.0f + expf(-bd));
    }
}

// ---------------- delta-rule recurrence; epilogue writes packed (o * fo) ----------------
#define DCH 32
__global__ void delta_k(const float* __restrict__ qh, const float* __restrict__ kh,
                        const float* __restrict__ vh, const float* __restrict__ betab,
                        uint4* __restrict__ opk, const float* __restrict__ fWo){
    int bh = blockIdx.x;
    int b = bh / NH, h = bh % NH;
    int v = threadIdx.x;
    float St[DHd];
    #pragma unroll
    for(int i=0;i<DHd;i++) St[i] = 0.0f;

    __shared__ float ks[DCH*DHd];
    __shared__ float qs[DCH*DHd];
    __shared__ float vs[DCH*DHd];
    __shared__ float bs[DCH];

    size_t base = (size_t)bh*SEQn*DHd;
    float fo = fWo[h*DHd + v];
    uint2* op2 = (uint2*)opk;

    for(int c0=0;c0<SEQn;c0+=DCH){
        __syncthreads();
        for(int i=v;i<DCH*DHd;i+=DHd){
            ks[i] = kh[base + (size_t)c0*DHd + i];
            qs[i] = qh[base + (size_t)c0*DHd + i];
            vs[i] = vh[base + (size_t)c0*DHd + i];
        }
        if(v < DCH) bs[v] = betab[(size_t)bh*SEQn + c0 + v];
        __syncthreads();
        for(int t=0;t<DCH;t++){
            const float* kt = &ks[t*DHd];
            const float* qt = &qs[t*DHd];
            float a0=0,a1=0,a2=0,a3=0;
            #pragma unroll
            for(int k=0;k<DHd;k+=4){
                a0 += kt[k  ]*St[k  ];
                a1 += kt[k+1]*St[k+1];
                a2 += kt[k+2]*St[k+2];
                a3 += kt[k+3]*St[k+3];
            }
            float kS = (a0+a1) + (a2+a3);
            float dlt = bs[t]*(vs[t*DHd + v] - kS);
            float o0=0,o1=0,o2=0,o3=0;
            #pragma unroll
            for(int k=0;k<DHd;k+=4){
                St[k  ] += kt[k  ]*dlt; o0 += qt[k  ]*St[k  ];
                St[k+1] += kt[k+1]*dlt; o1 += qt[k+1]*St[k+1];
                St[k+2] += kt[k+2]*dlt; o2 += qt[k+2]*St[k+2];
                St[k+3] += kt[k+3]*dlt; o3 += qt[k+3]*St[k+3];
            }
            float o = ((o0+o1) + (o2+o3)) * fo;
            float on = __shfl_down_sync(0xffffffffu, o, 1);
            if((v & 1) == 0){
                size_t pidx = (((size_t)(b*SEQn + c0 + t)*Dm) + h*DHd + v) >> 1;
                op2[pidx] = packsplit(o, on);
            }
        }
    }
}

// ---------------- residual: x = l2norm(x + alpha*8*(l2norm(o) - x)); emits fp32 + packed ----------------
__global__ void resid_k(float* __restrict__ x, const float* __restrict__ o,
                        const float* __restrict__ alpha, uint4* __restrict__ xp){
    __shared__ float red[256];
    int m = blockIdx.x, t = threadIdx.x;
    const float2* o2 = (const float2*)(o + (size_t)m*Dm);
    float2 oa = o2[t], ob = o2[t+256];
    float s = oa.x*oa.x + oa.y*oa.y + ob.x*ob.x + ob.y*ob.y;
    s = blocksum256(s, red);
    float fh = l2fac(sqrtf(s));
    float2* x2 = (float2*)(x + (size_t)m*Dm);
    float2 xa = x2[t], xb = x2[t+256];
    const float2* al2 = (const float2*)alpha;
    float2 aa = al2[t], ab = al2[t+256];
    float ya0 = xa.x + aa.x*8.0f*(oa.x*fh - xa.x);
    float ya1 = xa.y + aa.y*8.0f*(oa.y*fh - xa.y);
    float yb0 = xb.x + ab.x*8.0f*(ob.x*fh - xb.x);
    float yb1 = xb.y + ab.y*8.0f*(ob.y*fh - xb.y);
    float s2 = ya0*ya0 + ya1*ya1 + yb0*yb0 + yb1*yb1;
    s2 = blocksum256(s2, red);
    float f2 = l2fac(sqrtf(s2));
    ya0*=f2; ya1*=f2; yb0*=f2; yb1*=f2;
    x2[t]     = make_float2(ya0, ya1);
    x2[t+256] = make_float2(yb0, yb1);
    uint2* xpp = (uint2*)xp + (size_t)m*(Dm/2);
    xpp[t]     = packsplit(ya0, ya1);
    xpp[t+256] = packsplit(yb0, yb1);
}

// ---------------- z = silu(gate)*hidden, packed ----------------
__global__ void ffmul_k(const float* __restrict__ hb, const float* __restrict__ gbuf,
                        uint4* __restrict__ zp){
    size_t i2 = (size_t)blockIdx.x*256 + threadIdx.x;
    if(i2 >= (size_t)MT*DFFP/2) return;
    float2 h = ((const float2*)hb)[i2];
    float2 g = ((const float2*)gbuf)[i2];
    float z0 = g.x/(1.0f + expf(-g.x))*h.x;
    float z1 = g.y/(1.0f + expf(-g.y))*h.y;
    ((uint2*)zp)[i2] = packsplit(z0, z1);
}

// ---------------- host ----------------
template<typename T> static void* symaddr(T& s){
    void* p = nullptr; cudaGetSymbolAddress(&p, s); return p;
}

extern "C" void kernel_launch(void* const* d_in, const int* in_sizes, int n_in,
                              void* d_out, int out_size){
    (void)in_sizes; (void)n_in; (void)out_size;
    const int*   ids        = (const int*)  d_in[0];
    const float* W_emb      = (const float*)d_in[2];
    const float* Wq         = (const float*)d_in[3];
    const float* Wk         = (const float*)d_in[4];
    const float* Wv         = (const float*)d_in[5];
    const float* Wbeta      = (const float*)d_in[6];
    const float* Wo         = (const float*)d_in[7];
    const float* Wffh       = (const float*)d_in[8];
    const float* Wffg       = (const float*)d_in[9];
    const float* Wffo       = (const float*)d_in[10];
    const float* qk_scale   = (const float*)d_in[11];
    const float* beta_scale = (const float*)d_in[12];
    const float* attn_alpha = (const float*)d_in[13];
    const float* ff_alpha   = (const float*)d_in[14];
    const float* ffh_scale  = (const float*)d_in[15];
    const float* ffg_scale  = (const float*)d_in[16];
    const float* W_logits   = (const float*)d_in[17];
    const float* logit_scale= (const float*)d_in[18];
    float* out = (float*)d_out;

    float* x    = (float*)symaddr(g_x);
    float* qraw = (float*)symaddr(g_qraw);
    float* kraw = (float*)symaddr(g_kraw);
    float* vraw = (float*)symaddr(g_vraw);
    float* qh   = (float*)symaddr(g_qh);
    float* kh   = (float*)symaddr(g_kh);
    float* vh   = (float*)symaddr(g_vh);
    float* v0h  = (float*)symaddr(g_v0h);
    float* betab= (float*)symaddr(g_betab);
    float* ffh  = (float*)symaddr(g_ffh);
    float* ffg  = (float*)symaddr(g_ffg);
    float* fq   = (float*)symaddr(g_fq);
    float* fk   = (float*)symaddr(g_fk);
    float* fv   = (float*)symaddr(g_fv);
    float* fo   = (float*)symaddr(g_fo);
    float* fffh = (float*)symaddr(g_fffh);
    float* fffg = (float*)symaddr(g_fffg);
    float* fffo = (float*)symaddr(g_fffo);
    float* flog = (float*)symaddr(g_flog);
    float* wbn  = (float*)symaddr(g_wbn);
    uint4* xp   = (uint4*)symaddr(g_xp);
    uint4* opk  = (uint4*)symaddr(g_op);
    uint4* zp   = (uint4*)symaddr(g_zp);
    uint4* wqp  = (uint4*)symaddr(g_wqp);
    uint4* wkp  = (uint4*)symaddr(g_wkp);
    uint4* wvp  = (uint4*)symaddr(g_wvp);
    uint4* wop  = (uint4*)symaddr(g_wop);
    uint4* whp  = (uint4*)symaddr(g_whp);
    uint4* wgp  = (uint4*)symaddr(g_wgp);
    uint4* wfp  = (uint4*)symaddr(g_wfp);
    uint4* wlp  = (uint4*)symaddr(g_wlp);

    // norms
    rownorm_k<<<NL*Dm, 256>>>(Wq,   fq,   Dm);
    rownorm_k<<<NL*Dm, 256>>>(Wk,   fk,   Dm);
    rownorm_k<<<NL*Dm, 256>>>(Wv,   fv,   Dm);
    rownorm_k<<<NL*DFFn, 256>>>(Wffh, fffh, Dm);
    rownorm_k<<<NL*DFFn, 256>>>(Wffg, fffg, Dm);
    rownorm_k<<<NV, 256>>>(W_logits, flog, Dm);
    colnorm_k<<<dim3((Dm+255)/256,   NL), 256>>>(Wo,   fo,   Dm, Dm);
    colnorm_k<<<dim3((DFFn+255)/256, NL), 256>>>(Wffo, fffo, Dm, DFFn);

    // weight packs (scales folded)
    wpackL_k<<<NL*Dm, 256>>>(Wq, fq, nullptr, 1.0f, Dm, Dm, Dm, wqp);
    wpackL_k<<<NL*Dm, 256>>>(Wk, fk, nullptr, 1.0f, Dm, Dm, Dm, wkp);
    wpackL_k<<<NL*Dm, 256>>>(Wv, fv, nullptr, 1.0f, Dm, Dm, Dm, wvp);
    wpackL_k<<<NL*Dm, 256>>>(Wo, nullptr, nullptr, 1.0f, Dm, Dm, Dm, wop);
    wpackL_k<<<NL*DFFP, 256>>>(Wffh, fffh, ffh_scale, 1.0f,  DFFP, DFFn, Dm, whp);
    wpackL_k<<<NL*DFFP, 256>>>(Wffg, fffg, ffg_scale, 32.0f, DFFP, DFFn, Dm, wgp);
    wpackO_k<<<NL*Dm, 256>>>(Wffo, fffo, wfp);
    wpackL_k<<<NV, 256>>>(W_logits, flog, logit_scale, 32.0f, NV, NV, Dm, wlp);

    embed_k<<<MT, 256>>>(ids, W_emb, x, xp);

    const size_t wstep  = (size_t)Dm*Dm/4;
    const size_t wstepF = (size_t)DFFP*Dm/4;

    for(int l=0;l<NL;l++){
        // fused q/k/v projections
        {
            GBatch gb{};
            gb.op[0] = { wqp + l*wstep, qraw };
            gb.op[1] = { wkp + l*wstep, kraw };
            gb.op[2] = { wvp + l*wstep, vraw };
            gemm_bf16x3_k<64,64,2,2><<<dim3(16,16,3), 128>>>(xp, gb, MT, Dm, Dm);
        }
        wbeta_k<<<1, 64>>>(Wbeta, beta_scale, l, wbn);
        attn_prep_k<<<MT, 128>>>(qraw, kraw, vraw, qk_scale + l*Dm, wbn,
                                 qh, kh, vh, v0h, betab, (l==0) ? 1 : 0);
        delta_k<<<NB*NH, DHd>>>(qh, kh, vh, betab, opk, fo + l*Dm);
        // o projection
        {
            GBatch gb{};
            gb.op[0] = { wop + l*wstep, qraw };
            gemm_bf16x3_k<64,64,2,2><<<dim3(16,16,1), 128>>>(opk, gb, MT, Dm, Dm);
        }
        resid_k<<<MT, 256>>>(x, qraw, attn_alpha + l*Dm, xp);
        // feedforward hidden & gate
        {
            GBatch gb{};
            gb.op[0] = { whp + l*wstepF, ffh };
            gb.op[1] = { wgp + l*wstepF, ffg };
            gemm_bf16x3_k<128,128,2,4><<<dim3(DFFP/128, MT/128, 2), 256>>>(xp, gb, MT, DFFP, Dm);
        }
        ffmul_k<<<(MT*DFFP/2 + 255)/256, 256>>>(ffh, ffg, zp);
        {
            GBatch gb{};
            gb.op[0] = { wfp + (size_t)l*Dm*DFFP/4, qraw };
            gemm_bf16x3_k<64,64,2,2><<<dim3(16,16,1), 128>>>(zp, gb, MT, Dm, DFFP);
        }
        resid_k<<<MT, 256>>>(x, qraw, ff_alpha + l*Dm, xp);
    }
    // logits
    {
        GBatch gb{};
        gb.op[0] = { wlp, out };
        gemm_bf16x3_k<128,128,2,4><<<dim3(NV/128, MT/128, 1), 256>>>(xp, gb, MT, NV, Dm);
    }
}

// round 5
// speedup vs baseline: 3.0223x; 1.9151x over previous
#include <cuda_runtime.h>
#include <cuda_bf16.h>
#include <math.h>
#include <stdint.h>

#define Dm    1024
#define SEQn  512
#define NB    2
#define NH    16
#define DHd   64
#define DFFn  2730
#define DFFP  2816
#define NV    32000
#define NL    4
#define MT    1024
#define K3D   3072        // 3*Dm
#define K3F   8448        // 3*DFFP
#define NQKV  3072
#define NHG   5632

// ---------------- fp32 scratch ----------------
__device__ float g_x[MT*Dm];
__device__ float g_qkv[MT*NQKV];
__device__ float g_obuf[MT*Dm];
__device__ float g_hg[MT*NHG];
__device__ float g_qh[NB*NH*SEQn*DHd];
__device__ float g_kh[NB*NH*SEQn*DHd];
__device__ float g_vh[NB*NH*SEQn*DHd];
__device__ float g_v0h[NB*NH*SEQn*DHd];
__device__ float g_betab[NB*NH*SEQn];
__device__ float g_fq[NL*Dm];
__device__ float g_fk[NL*Dm];
__device__ float g_fv[NL*Dm];
__device__ float g_fo[NL*Dm];
__device__ float g_fffh[NL*DFFn];
__device__ float g_fffg[NL*DFFn];
__device__ float g_fffo[NL*DFFn];
__device__ float g_flog[NV];
__device__ float g_wbn[DHd];

// ---------------- packed bf16 triple buffers (uint32 = 2 bf16) ----------------
__device__ uint32_t g_xp3 [MT*(K3D/2)];
__device__ uint32_t g_op3 [MT*(K3D/2)];
__device__ uint32_t g_zp3 [MT*(K3F/2)];
__device__ uint32_t g_wqkvp3[(size_t)NL*NQKV*(K3D/2)];
__device__ uint32_t g_wop3  [(size_t)NL*Dm*(K3D/2)];
__device__ uint32_t g_whgp3 [(size_t)NL*NHG*(K3D/2)];
__device__ uint32_t g_wfop3 [(size_t)NL*Dm*(K3F/2)];
__device__ uint32_t g_wlp3  [(size_t)NV*(K3D/2)];

// ---------------- scalar helpers ----------------
static __device__ __forceinline__ float l2fac(float n){
    float tgt = fminf(fmaxf(n, 1.0f - 1e-5f), 1.0f + 1e-5f);
    return 1.0f / fmaxf(n / tgt, 1e-10f);
}
static __device__ __forceinline__ float warpsum(float v){
    #pragma unroll
    for(int o=16;o>0;o>>=1) v += __shfl_xor_sync(0xffffffffu, v, o);
    return v;
}
static __device__ __forceinline__ float blocksum256(float v, float* red){
    red[threadIdx.x] = v; __syncthreads();
    for(int o=128;o>0;o>>=1){
        if(threadIdx.x < o) red[threadIdx.x] += red[threadIdx.x+o];
        __syncthreads();
    }
    float r = red[0]; __syncthreads();
    return r;
}

static __device__ __forceinline__ void split2(float x0, float x1,
        uint32_t& h0, uint32_t& l0, uint32_t& h1, uint32_t& l1){
    __nv_bfloat16 a = __float2bfloat16(x0);
    __nv_bfloat16 b = __float2bfloat16(x1);
    float ra = x0 - __bfloat162float(a);
    float rb = x1 - __bfloat162float(b);
    __nv_bfloat16 la = __float2bfloat16(ra), lb = __float2bfloat16(rb);
    h0 = (uint32_t)__bfloat16_as_ushort(a);  l0 = (uint32_t)__bfloat16_as_ushort(la);
    h1 = (uint32_t)__bfloat16_as_ushort(b);  l1 = (uint32_t)__bfloat16_as_ushort(lb);
}
// activation pattern per element: [hi, lo, hi]
static __device__ __forceinline__ void pack_act(uint32_t* d, float x0, float x1){
    uint32_t h0,l0,h1,l1; split2(x0,x1,h0,l0,h1,l1);
    d[0] = h0 | (l0<<16);
    d[1] = h0 | (h1<<16);
    d[2] = l1 | (h1<<16);
}
// weight pattern per element: [hi, hi, lo]
static __device__ __forceinline__ void pack_w(uint32_t* d, float x0, float x1){
    uint32_t h0,l0,h1,l1; split2(x0,x1,h0,l0,h1,l1);
    d[0] = h0 | (h0<<16);
    d[1] = l0 | (h1<<16);
    d[2] = h1 | (l1<<16);
}

// ---------------- cp.async / ldmatrix / mma primitives ----------------
static __device__ __forceinline__ void cp16(uint32_t saddr, const void* g){
    asm volatile("cp.async.cg.shared.global [%0], [%1], 16;" :: "r"(saddr), "l"(g) : "memory");
}
static __device__ __forceinline__ void cp_commit(){
    asm volatile("cp.async.commit_group;" ::: "memory");
}
template<int N> static __device__ __forceinline__ void cp_wait(){
    asm volatile("cp.async.wait_group %0;" :: "n"(N) : "memory");
}
static __device__ __forceinline__ void ldsm4(uint32_t* r, uint32_t a){
    asm volatile("ldmatrix.sync.aligned.m8n8.x4.shared.b16 {%0,%1,%2,%3}, [%4];"
        : "=r"(r[0]),"=r"(r[1]),"=r"(r[2]),"=r"(r[3]) : "r"(a));
}
static __device__ __forceinline__ void mma_bf16(float* c,
        uint32_t a0, uint32_t a1, uint32_t a2, uint32_t a3, uint32_t b0, uint32_t b1){
    asm volatile("mma.sync.aligned.m16n8k16.row.col.f32.bf16.bf16.f32 "
                 "{%0,%1,%2,%3},{%4,%5,%6,%7},{%8,%9},{%0,%1,%2,%3};"
                 : "+f"(c[0]), "+f"(c[1]), "+f"(c[2]), "+f"(c[3])
                 : "r"(a0), "r"(a1), "r"(a2), "r"(a3), "r"(b0), "r"(b1));
}

// ---------------- multistage bf16 mma GEMM: C[M,N] = A @ B^T ----------------
// A,B: bf16 K-major (passed as uint32 pairs). C fp32, ldc = N total.
// Tiles: BMxBN=BMx128, BK=64 bf16 (128B rows), 3-stage cp.async, ldmatrix.x4.
template<int BM>
__global__ void __launch_bounds__(256, 2) gemm_mma_k(const uint32_t* __restrict__ Au,
        const uint32_t* __restrict__ Bu, float* __restrict__ C, int ldc, int K){
    constexpr int BN = 128;
    constexpr int S = 3;
    constexpr int ABYTES = BM*128, STAGE = (BM+BN)*128;
    constexpr int WMW = BM/32, WNW = 8/WMW;
    constexpr int WTN = BN/WNW;
    constexpr int MI = 2, NJ = WTN/8, NJ2 = NJ/2;
    constexpr int NLD = (BM+BN)*8/256;

    extern __shared__ char sm[];
    uint32_t smBase = (uint32_t)__cvta_generic_to_shared(sm);

    const int tid = threadIdx.x, warp = tid>>5, lane = tid&31;
    const int wm = warp / WNW, wn = warp % WNW;
    const int i8 = lane&7, sub = lane>>3;
    const int g = lane>>2, t4 = lane&3;
    const int rowBase = blockIdx.x*BM, colBase = blockIdx.y*BN;
    const char* Ab = (const char*)Au;
    const char* Bb = (const char*)Bu;
    const size_t Kb = (size_t)K*2;
    const int NC = (int)(Kb/128);

    // ldmatrix per-lane base row addresses (swizzle xor term is (i8<<4) at use time)
    const int cA = sub>>1;        // A: k8-half selector
    const int cB = sub&1;         // B: k8-half selector
    uint32_t aRow[MI], bRow[NJ2];
    #pragma unroll
    for(int it=0;it<MI;it++)
        aRow[it] = smBase + (uint32_t)((wm*32 + it*16 + (sub&1)*8 + i8)*128);
    #pragma unroll
    for(int jp=0;jp<NJ2;jp++)
        bRow[jp] = smBase + (uint32_t)(ABYTES + (wn*WTN + jp*16 + (sub>>1)*8 + i8)*128);

    float acc[MI][NJ][4];
    #pragma unroll
    for(int i=0;i<MI;i++)
        #pragma unroll
        for(int j=0;j<NJ;j++)
            #pragma unroll
            for(int e=0;e<4;e++) acc[i][j][e] = 0.0f;

    // stage loader
    auto load_chunk = [&](int ck, int s){
        #pragma unroll
        for(int u=0;u<NLD;u++){
            int idx = tid + u*256;
            int isA = (idx < BM*8);
            int ii = isA ? idx : idx - BM*8;
            int r = ii>>3, c = ii&7;
            const char* gp = isA
                ? Ab + (size_t)(rowBase + r)*Kb + (size_t)ck*128 + c*16
                : Bb + (size_t)(colBase + r)*Kb + (size_t)ck*128 + c*16;
            uint32_t so = smBase + (uint32_t)(s*STAGE + (isA?0:ABYTES)
                        + r*128 + (((c ^ (r&7)))<<4));
            cp16(so, gp);
        }
        cp_commit();
    };

    load_chunk(0, 0);
    load_chunk(1, 1);

    for(int c=0;c<NC;c++){
        cp_wait<S-2>();
        __syncthreads();
        if(c+2 < NC) load_chunk(c+2, (c+2)%S);
        else cp_commit();

        const uint32_t bufOff = (uint32_t)((c%S)*STAGE);
        #pragma unroll
        for(int kk=0;kk<4;kk++){
            uint32_t ah[MI][4], bb[NJ2][4];
            #pragma unroll
            for(int it=0;it<MI;it++)
                ldsm4(ah[it], aRow[it] + bufOff + (uint32_t)((((2*kk + cA) ^ i8))<<4));
            #pragma unroll
            for(int jp=0;jp<NJ2;jp++)
                ldsm4(bb[jp], bRow[jp] + bufOff + (uint32_t)((((2*kk + cB) ^ i8))<<4));
            #pragma unroll
            for(int it=0;it<MI;it++)
                #pragma unroll
                for(int jt=0;jt<NJ;jt++){
                    const uint32_t* bf = bb[jt>>1];
                    int o = (jt&1)*2;
                    mma_bf16(acc[it][jt], ah[it][0], ah[it][1], ah[it][2], ah[it][3],
                             bf[o], bf[o+1]);
                }
        }
        __syncthreads();
    }

    // epilogue
    #pragma unroll
    for(int jt=0;jt<NJ;jt++){
        int c = colBase + wn*WTN + jt*8 + t4*2;
        #pragma unroll
        for(int it=0;it<MI;it++){
            int r = rowBase + wm*32 + it*16 + g;
            *(float2*)(C + (size_t)r*ldc + c)     = make_float2(acc[it][jt][0], acc[it][jt][1]);
            *(float2*)(C + (size_t)(r+8)*ldc + c) = make_float2(acc[it][jt][2], acc[it][jt][3]);
        }
    }
}

// ---------------- norm factors ----------------
__global__ void rownorm_k(const float* __restrict__ W, float* __restrict__ f, int C){
    __shared__ float red[256];
    int r = blockIdx.x;
    const float* row = W + (size_t)r*C;
    float s = 0.0f;
    for(int c=threadIdx.x;c<C;c+=256){ float w = row[c]; s += w*w; }
    s = blocksum256(s, red);
    if(threadIdx.x==0) f[r] = l2fac(sqrtf(s));
}
__global__ void colnorm_k(const float* __restrict__ W, float* __restrict__ f, int R, int C){
    int l = blockIdx.y;
    int c = blockIdx.x*blockDim.x + threadIdx.x;
    if(c >= C) return;
    const float* Wl = W + (size_t)l*R*C;
    float s = 0.0f;
    for(int r=0;r<R;r++){ float w = Wl[(size_t)r*C + c]; s += w*w; }
    f[(size_t)l*C + c] = l2fac(sqrtf(s));
}

// ---------------- weight packing ----------------
__global__ void wpack_qkv_k(const float* __restrict__ Wq, const float* __restrict__ Wk,
                            const float* __restrict__ Wv, const float* __restrict__ fq,
                            const float* __restrict__ fk, const float* __restrict__ fv,
                            uint32_t* __restrict__ dst){
    int rr = blockIdx.x;
    int l = rr / NQKV, r = rr % NQKV;
    int which = r >> 10, rl = r & 1023;
    const float* W; const float* f;
    if(which==0){ W=Wq; f=fq; } else if(which==1){ W=Wk; f=fk; } else { W=Wv; f=fv; }
    size_t srow = (size_t)l*Dm + rl;
    float s = f[srow];
    const float2* sp = (const float2*)(W + srow*Dm);
    uint32_t* dp = dst + (size_t)rr*(K3D/2);
    for(int j=threadIdx.x;j<Dm/2;j+=256){
        float2 v = sp[j];
        pack_w(dp + 3*j, v.x*s, v.y*s);
    }
}
__global__ void wpack_o_k(const float* __restrict__ Wo, uint32_t* __restrict__ dst){
    int rr = blockIdx.x;
    const float2* sp = (const float2*)(Wo + (size_t)rr*Dm);
    uint32_t* dp = dst + (size_t)rr*(K3D/2);
    for(int j=threadIdx.x;j<Dm/2;j+=256){
        float2 v = sp[j];
        pack_w(dp + 3*j, v.x, v.y);
    }
}
__global__ void wpack_hg_k(const float* __restrict__ Wffh, const float* __restrict__ Wffg,
                           const float* __restrict__ fffh, const float* __restrict__ fffg,
                           const float* __restrict__ hsc, const float* __restrict__ gsc,
                           uint32_t* __restrict__ dst){
    int rr = blockIdx.x;
    int l = rr / NHG, r = rr % NHG;
    uint32_t* dp = dst + (size_t)rr*(K3D/2);
    const float* W; float s; int valid = 1;
    if(r < DFFP){
        if(r < DFFn){ size_t sr=(size_t)l*DFFn+r; W=Wffh+sr*Dm; s=fffh[sr]*hsc[sr]; }
        else valid = 0;
    } else {
        int rg = r - DFFP;
        if(rg < DFFn){ size_t sr=(size_t)l*DFFn+rg; W=Wffg+sr*Dm; s=fffg[sr]*gsc[sr]*32.0f; }
        else valid = 0;
    }
    if(!valid){
        for(int j=threadIdx.x;j<K3D/2;j+=256) dp[j] = 0u;
        return;
    }
    const float2* sp = (const float2*)W;
    for(int j=threadIdx.x;j<Dm/2;j+=256){
        float2 v = sp[j];
        pack_w(dp + 3*j, v.x*s, v.y*s);
    }
}
__global__ void wpack_fo_k(const float* __restrict__ Wffo, const float* __restrict__ fffo,
                           uint32_t* __restrict__ dst){
    int rr = blockIdx.x;
    int l = rr / Dm, rl = rr % Dm;
    const float* sp = Wffo + ((size_t)l*Dm + rl)*DFFn;
    const float* ks = fffo + (size_t)l*DFFn;
    uint32_t* dp = dst + (size_t)rr*(K3F/2);
    for(int j=threadIdx.x;j<DFFP/2;j+=256){
        int k = 2*j;
        float x0 = 0.0f, x1 = 0.0f;
        if(k < DFFn){ x0 = sp[k]*ks[k]; x1 = sp[k+1]*ks[k+1]; }
        pack_w(dp + 3*j, x0, x1);
    }
}
__global__ void wpack_log_k(const float* __restrict__ Wl, const float* __restrict__ flog,
                            const float* __restrict__ lsc, uint32_t* __restrict__ dst){
    int r = blockIdx.x;
    float s = flog[r]*lsc[r]*32.0f;
    const float2* sp = (const float2*)(Wl + (size_t)r*Dm);
    uint32_t* dp = dst + (size_t)r*(K3D/2);
    for(int j=threadIdx.x;j<Dm/2;j+=256){
        float2 v = sp[j];
        pack_w(dp + 3*j, v.x*s, v.y*s);
    }
}

// ---------------- embedding ----------------
__global__ void embed_k(const int* __restrict__ ids, const float* __restrict__ W_emb,
                        float* __restrict__ x, uint32_t* __restrict__ xp3){
    __shared__ float red[256];
    int m = blockIdx.x, t = threadIdx.x;
    int tok = ids[m];
    const float2* row2 = (const float2*)(W_emb + (size_t)tok*Dm);
    float2 a = row2[t], b = row2[t+256];
    float s = a.x*a.x + a.y*a.y + b.x*b.x + b.y*b.y;
    s = blocksum256(s, red);
    float f = l2fac(sqrtf(s));
    a.x*=f; a.y*=f; b.x*=f; b.y*=f;
    float2* x2 = (float2*)(x + (size_t)m*Dm);
    x2[t] = a; x2[t+256] = b;
    uint32_t* dp = xp3 + (size_t)m*(K3D/2);
    pack_act(dp + 3*t,       a.x, a.y);
    pack_act(dp + 3*(t+256), b.x, b.y);
}

// ---------------- wbeta ----------------
__global__ void wbeta_k(const float* __restrict__ Wb, const float* __restrict__ bscale,
                        int l, float* __restrict__ out){
    __shared__ float red[64]; __shared__ float stot;
    int t = threadIdx.x;
    float w = Wb[l*DHd + t];
    red[t] = w*w; __syncthreads();
    if(t<32) red[t] += red[t+32];
    __syncthreads();
    if(t==0){ float s=0; for(int i=0;i<32;i++) s += red[i]; stot = s; }
    __syncthreads();
    float fac = l2fac(sqrtf(stot));
    out[t] = w * fac * (bscale[l] * 0.1f);
}

// ---------------- attn prep ----------------
__global__ void attn_prep_k(const float* __restrict__ qkv, const float* __restrict__ qs_l,
                            const float* __restrict__ wbn,
                            float* __restrict__ qh, float* __restrict__ kh,
                            float* __restrict__ vh, float* __restrict__ v0h,
                            float* __restrict__ betab, int is_l0){
    int m = blockIdx.x;
    int b = m / SEQn, s = m % SEQn;
    int lane = threadIdx.x & 31, warp = threadIdx.x >> 5;
    #pragma unroll
    for(int hi=0; hi<NH/4; hi++){
        int h = warp*4 + hi;
        size_t src = (size_t)m*NQKV + h*DHd;
        int d0 = lane, d1 = lane + 32;
        float q0=qkv[src+d0],        q1=qkv[src+d1];
        float k0=qkv[src+Dm+d0],     k1=qkv[src+Dm+d1];
        float w0=qkv[src+2*Dm+d0],   w1=qkv[src+2*Dm+d1];
        float fqv = l2fac(sqrtf(warpsum(q0*q0 + q1*q1)));
        float fkv = l2fac(sqrtf(warpsum(k0*k0 + k1*k1)));
        float kn0 = k0*fkv, kn1 = k1*fkv;
        float bd = warpsum(kn0*wbn[d0] + kn1*wbn[d1]);
        size_t dst = ((size_t)(b*NH + h)*SEQn + s)*DHd;
        qh[dst+d0] = q0*fqv*qs_l[h*DHd+d0]*1024.0f;
        qh[dst+d1] = q1*fqv*qs_l[h*DHd+d1]*1024.0f;
        kh[dst+d0] = kn0; kh[dst+d1] = kn1;
        float vv0, vv1;
        if(is_l0){ vv0=w0; vv1=w1; v0h[dst+d0]=w0; v0h[dst+d1]=w1; }
        else     { vv0=0.5f*(w0 + v0h[dst+d0]); vv1=0.5f*(w1 + v0h[dst+d1]); }
        vh[dst+d0]=vv0; vh[dst+d1]=vv1;
        if(lane==0) betab[(size_t)(b*NH+h)*SEQn + s] = 1.0f/(1.0f + expf(-bd));
    }
}

// ---------------- delta rule; epilogue packs (o*fo) into triple bf16 ----------------
#define DCH 32
__global__ void delta_k(const float* __restrict__ qh, const float* __restrict__ kh,
                        const float* __restrict__ vh, const float* __restrict__ betab,
                        uint32_t* __restrict__ op3, const float* __restrict__ fWo){
    int bh = blockIdx.x;
    int b = bh / NH, h = bh % NH;
    int v = threadIdx.x;
    float St[DHd];
    #pragma unroll
    for(int i=0;i<DHd;i++) St[i] = 0.0f;

    __shared__ float ks[DCH*DHd];
    __shared__ float qs[DCH*DHd];
    __shared__ float vs[DCH*DHd];
    __shared__ float bs[DCH];

    size_t base = (size_t)bh*SEQn*DHd;
    float fo = fWo[h*DHd + v];

    for(int c0=0;c0<SEQn;c0+=DCH){
        __syncthreads();
        for(int i=v;i<DCH*DHd;i+=DHd){
            ks[i] = kh[base + (size_t)c0*DHd + i];
            qs[i] = qh[base + (size_t)c0*DHd + i];
            vs[i] = vh[base + (size_t)c0*DHd + i];
        }
        if(v < DCH) bs[v] = betab[(size_t)bh*SEQn + c0 + v];
        __syncthreads();
        for(int t=0;t<DCH;t++){
            const float* kt = &ks[t*DHd];
            const float* qt = &qs[t*DHd];
            float a0=0,a1=0,a2=0,a3=0;
            #pragma unroll
            for(int k=0;k<DHd;k+=4){
                a0 += kt[k  ]*St[k  ];
                a1 += kt[k+1]*St[k+1];
                a2 += kt[k+2]*St[k+2];
                a3 += kt[k+3]*St[k+3];
            }
            float kS = (a0+a1) + (a2+a3);
            float dlt = bs[t]*(vs[t*DHd + v] - kS);
            float o0=0,o1=0,o2=0,o3=0;
            #pragma unroll
            for(int k=0;k<DHd;k+=4){
                St[k  ] += kt[k  ]*dlt; o0 += qt[k  ]*St[k  ];
                St[k+1] += kt[k+1]*dlt; o1 += qt[k+1]*St[k+1];
                St[k+2] += kt[k+2]*dlt; o2 += qt[k+2]*St[k+2];
                St[k+3] += kt[k+3]*dlt; o3 += qt[k+3]*St[k+3];
            }
            float o = (((o0+o1) + (o2+o3))) * fo;
            float on = __shfl_down_sync(0xffffffffu, o, 1);
            if((v & 1) == 0){
                uint32_t* dp = op3 + (size_t)(b*SEQn + c0 + t)*(K3D/2)
                             + 3*(h*32 + (v>>1));
                pack_act(dp, o, on);
            }
        }
    }
}

// ---------------- residual ----------------
__global__ void resid_k(float* __restrict__ x, const float* __restrict__ o,
                        const float* __restrict__ alpha, uint32_t* __restrict__ xp3){
    __shared__ float red[256];
    int m = blockIdx.x, t = threadIdx.x;
    const float2* o2 = (const float2*)(o + (size_t)m*Dm);
    float2 oa = o2[t], ob = o2[t+256];
    float s = oa.x*oa.x + oa.y*oa.y + ob.x*ob.x + ob.y*ob.y;
    s = blocksum256(s, red);
    float fh = l2fac(sqrtf(s));
    float2* x2 = (float2*)(x + (size_t)m*Dm);
    float2 xa = x2[t], xb = x2[t+256];
    const float2* al2 = (const float2*)alpha;
    float2 aa = al2[t], ab = al2[t+256];
    float ya0 = xa.x + aa.x*8.0f*(oa.x*fh - xa.x);
    float ya1 = xa.y + aa.y*8.0f*(oa.y*fh - xa.y);
    float yb0 = xb.x + ab.x*8.0f*(ob.x*fh - xb.x);
    float yb1 = xb.y + ab.y*8.0f*(ob.y*fh - xb.y);
    float s2 = ya0*ya0 + ya1*ya1 + yb0*yb0 + yb1*yb1;
    s2 = blocksum256(s2, red);
    float f2 = l2fac(sqrtf(s2));
    ya0*=f2; ya1*=f2; yb0*=f2; yb1*=f2;
    x2[t]     = make_float2(ya0, ya1);
    x2[t+256] = make_float2(yb0, yb1);
    uint32_t* dp = xp3 + (size_t)m*(K3D/2);
    pack_act(dp + 3*t,       ya0, ya1);
    pack_act(dp + 3*(t+256), yb0, yb1);
}

// ---------------- silu(gate)*hidden -> packed z ----------------
__global__ void ffmul_k(const float* __restrict__ hg, uint32_t* __restrict__ zp3){
    size_t idx = (size_t)blockIdx.x*256 + threadIdx.x;
    if(idx >= (size_t)MT*(DFFP/2)) return;
    int m = (int)(idx / (DFFP/2));
    int j = (int)(idx % (DFFP/2));
    const float2* row = (const float2*)(hg + (size_t)m*NHG);
    float2 h = row[j];
    float2 g = row[DFFP/2 + j];
    float z0 = g.x/(1.0f + expf(-g.x))*h.x;
    float z1 = g.y/(1.0f + expf(-g.y))*h.y;
    pack_act(zp3 + (size_t)m*(K3F/2) + 3*j, z0, z1);
}

// ---------------- host ----------------
template<typename T> static void* symaddr(T& s){
    void* p = nullptr; cudaGetSymbolAddress(&p, s); return p;
}

extern "C" void kernel_launch(void* const* d_in, const int* in_sizes, int n_in,
                              void* d_out, int out_size){
    (void)in_sizes; (void)n_in; (void)out_size;
    const int*   ids        = (const int*)  d_in[0];
    const float* W_emb      = (const float*)d_in[2];
    const float* Wq         = (const float*)d_in[3];
    const float* Wk         = (const float*)d_in[4];
    const float* Wv         = (const float*)d_in[5];
    const float* Wbeta      = (const float*)d_in[6];
    const float* Wo         = (const float*)d_in[7];
    const float* Wffh       = (const float*)d_in[8];
    const float* Wffg       = (const float*)d_in[9];
    const float* Wffo       = (const float*)d_in[10];
    const float* qk_scale   = (const float*)d_in[11];
    const float* beta_scale = (const float*)d_in[12];
    const float* attn_alpha = (const float*)d_in[13];
    const float* ff_alpha   = (const float*)d_in[14];
    const float* ffh_scale  = (const float*)d_in[15];
    const float* ffg_scale  = (const float*)d_in[16];
    const float* W_logits   = (const float*)d_in[17];
    const float* logit_scale= (const float*)d_in[18];
    float* out = (float*)d_out;

    float* x     = (float*)symaddr(g_x);
    float* qkv   = (float*)symaddr(g_qkv);
    float* obuf  = (float*)symaddr(g_obuf);
    float* hg    = (float*)symaddr(g_hg);
    float* qh    = (float*)symaddr(g_qh);
    float* kh    = (float*)symaddr(g_kh);
    float* vh    = (float*)symaddr(g_vh);
    float* v0h   = (float*)symaddr(g_v0h);
    float* betab = (float*)symaddr(g_betab);
    float* fq    = (float*)symaddr(g_fq);
    float* fk    = (float*)symaddr(g_fk);
    float* fv    = (float*)symaddr(g_fv);
    float* fo    = (float*)symaddr(g_fo);
    float* fffh  = (float*)symaddr(g_fffh);
    float* fffg  = (float*)symaddr(g_fffg);
    float* fffo  = (float*)symaddr(g_fffo);
    float* flog  = (float*)symaddr(g_flog);
    float* wbn   = (float*)symaddr(g_wbn);
    uint32_t* xp3   = (uint32_t*)symaddr(g_xp3);
    uint32_t* op3   = (uint32_t*)symaddr(g_op3);
    uint32_t* zp3   = (uint32_t*)symaddr(g_zp3);
    uint32_t* wqkvp = (uint32_t*)symaddr(g_wqkvp3);
    uint32_t* wop   = (uint32_t*)symaddr(g_wop3);
    uint32_t* whgp  = (uint32_t*)symaddr(g_whgp3);
    uint32_t* wfop  = (uint32_t*)symaddr(g_wfop3);
    uint32_t* wlp   = (uint32_t*)symaddr(g_wlp3);

    cudaFuncSetAttribute(gemm_mma_k<128>, cudaFuncAttributeMaxDynamicSharedMemorySize, 98304);
    cudaFuncSetAttribute(gemm_mma_k<64>,  cudaFuncAttributeMaxDynamicSharedMemorySize, 73728);

    // norms
    rownorm_k<<<NL*Dm, 256>>>(Wq,   fq,   Dm);
    rownorm_k<<<NL*Dm, 256>>>(Wk,   fk,   Dm);
    rownorm_k<<<NL*Dm, 256>>>(Wv,   fv,   Dm);
    rownorm_k<<<NL*DFFn, 256>>>(Wffh, fffh, Dm);
    rownorm_k<<<NL*DFFn, 256>>>(Wffg, fffg, Dm);
    rownorm_k<<<NV, 256>>>(W_logits, flog, Dm);
    colnorm_k<<<dim3((Dm+255)/256,   NL), 256>>>(Wo,   fo,   Dm, Dm);
    colnorm_k<<<dim3((DFFn+255)/256, NL), 256>>>(Wffo, fffo, Dm, DFFn);

    // packs
    wpack_qkv_k<<<NL*NQKV, 256>>>(Wq, Wk, Wv, fq, fk, fv, wqkvp);
    wpack_o_k<<<NL*Dm, 256>>>(Wo, wop);
    wpack_hg_k<<<NL*NHG, 256>>>(Wffh, Wffg, fffh, fffg, ffh_scale, ffg_scale, whgp);
    wpack_fo_k<<<NL*Dm, 256>>>(Wffo, fffo, wfop);
    wpack_log_k<<<NV, 256>>>(W_logits, flog, logit_scale, wlp);

    embed_k<<<MT, 256>>>(ids, W_emb, x, xp3);

    for(int l=0;l<NL;l++){
        // fused qkv: [1024,3072]
        gemm_mma_k<128><<<dim3(8, NQKV/128), 256, 98304>>>(
            xp3, wqkvp + (size_t)l*NQKV*(K3D/2), qkv, NQKV, K3D);
        wbeta_k<<<1, 64>>>(Wbeta, beta_scale, l, wbn);
        attn_prep_k<<<MT, 128>>>(qkv, qk_scale + l*Dm, wbn, qh, kh, vh, v0h, betab, (l==0)?1:0);
        delta_k<<<NB*NH, DHd>>>(qh, kh, vh, betab, op3, fo + l*Dm);
        // o projection: [1024,1024]
        gemm_mma_k<64><<<dim3(16, Dm/128), 256, 73728>>>(
            op3, wop + (size_t)l*Dm*(K3D/2), obuf, Dm, K3D);
        resid_k<<<MT, 256>>>(x, obuf, attn_alpha + l*Dm, xp3);
        // fused ff hidden|gate: [1024,5632]
        gemm_mma_k<128><<<dim3(8, NHG/128), 256, 98304>>>(
            xp3, whgp + (size_t)l*NHG*(K3D/2), hg, NHG, K3D);
        ffmul_k<<<(MT*(DFFP/2) + 255)/256, 256>>>(hg, zp3);
        // ff out: [1024,1024], K=8448
        gemm_mma_k<64><<<dim3(16, Dm/128), 256, 73728>>>(
            zp3, wfop + (size_t)l*Dm*(K3F/2), obuf, Dm, K3F);
        resid_k<<<MT, 256>>>(x, obuf, ff_alpha + l*Dm, xp3);
    }
    // logits: [1024,32000]
    gemm_mma_k<128><<<dim3(8, NV/128), 256, 98304>>>(
        xp3, wlp, out, NV, K3D);
}

// round 6
// speedup vs baseline: 3.7793x; 1.2505x over previous
#include <cuda_runtime.h>
#include <cuda_bf16.h>
#include <cuda_fp16.h>
#include <math.h>
#include <stdint.h>

#define Dm    1024
#define SEQn  512
#define NB    2
#define NH    16
#define DHd   64
#define DFFn  2730
#define DFFP  2816
#define NV    32000
#define NL    4
#define MT    1024
#define NQKV  3072
#define NHG   5632
#define UD    1024    // uint32 per row, K-slots=2048 (2*Dm)
#define UF    2816    // uint32 per row, K-slots=5632 (2*DFFP)

// ---------------- fp32 scratch ----------------
__device__ float g_x[MT*Dm];
__device__ float g_qkv[MT*NQKV];
__device__ float g_obuf[MT*Dm];
__device__ float g_hg[MT*NHG];
__device__ float g_qh[NB*NH*SEQn*DHd];
__device__ float g_kh[NB*NH*SEQn*DHd];
__device__ float g_vh[NB*NH*SEQn*DHd];
__device__ float g_v0h[NB*NH*SEQn*DHd];
__device__ float g_betab[NB*NH*SEQn];
__device__ float g_fo[NL*Dm];
__device__ float g_fffo[NL*DFFn];
__device__ float g_wbn[DHd];

// ---------------- packed fp16 2-plane buffers (uint32 = 2 fp16 k-slots) ----------------
__device__ uint32_t g_xp2 [MT*UD];
__device__ uint32_t g_op2 [MT*UD];
__device__ uint32_t g_zp2 [MT*UF];
__device__ uint32_t g_wqkv2[(size_t)NL*NQKV*UD];
__device__ uint32_t g_wo2  [(size_t)NL*Dm*UD];
__device__ uint32_t g_whg2 [(size_t)NL*NHG*UD];
__device__ uint32_t g_wfo2 [(size_t)NL*Dm*UF];
__device__ uint32_t g_wl2  [(size_t)NV*UD];

// ---------------- scalar helpers ----------------
static __device__ __forceinline__ float l2fac(float n){
    float tgt = fminf(fmaxf(n, 1.0f - 1e-5f), 1.0f + 1e-5f);
    return 1.0f / fmaxf(n / tgt, 1e-10f);
}
static __device__ __forceinline__ float warpsum(float v){
    #pragma unroll
    for(int o=16;o>0;o>>=1) v += __shfl_xor_sync(0xffffffffu, v, o);
    return v;
}
static __device__ __forceinline__ float blocksum256(float v, float* red){
    red[threadIdx.x] = v; __syncthreads();
    for(int o=128;o>0;o>>=1){
        if(threadIdx.x < o) red[threadIdx.x] += red[threadIdx.x+o];
        __syncthreads();
    }
    float r = red[0]; __syncthreads();
    return r;
}

// activations: slots [hi, lo] per element — exact fp32 reconstruction
static __device__ __forceinline__ void pack_a2(uint32_t* d, float x0, float x1){
    __half h0=__float2half_rn(x0), h1=__float2half_rn(x1);
    __half l0=__float2half_rn(x0-__half2float(h0));
    __half l1=__float2half_rn(x1-__half2float(h1));
    d[0] = (uint32_t)__half_as_ushort(h0) | ((uint32_t)__half_as_ushort(l0)<<16);
    d[1] = (uint32_t)__half_as_ushort(h1) | ((uint32_t)__half_as_ushort(l1)<<16);
}
// weights: slots [hi, hi] per element
static __device__ __forceinline__ void pack_w2f(uint32_t* d, float x0, float x1){
    uint32_t h0=__half_as_ushort(__float2half_rn(x0));
    uint32_t h1=__half_as_ushort(__float2half_rn(x1));
    d[0] = h0|(h0<<16); d[1] = h1|(h1<<16);
}

// ---------------- cp.async / ldmatrix / mma primitives ----------------
static __device__ __forceinline__ void cp16(uint32_t saddr, const void* g){
    asm volatile("cp.async.cg.shared.global [%0], [%1], 16;" :: "r"(saddr), "l"(g) : "memory");
}
static __device__ __forceinline__ void cp_commit(){
    asm volatile("cp.async.commit_group;" ::: "memory");
}
template<int N> static __device__ __forceinline__ void cp_wait(){
    asm volatile("cp.async.wait_group %0;" :: "n"(N) : "memory");
}
static __device__ __forceinline__ void ldsm4(uint32_t* r, uint32_t a){
    asm volatile("ldmatrix.sync.aligned.m8n8.x4.shared.b16 {%0,%1,%2,%3}, [%4];"
        : "=r"(r[0]),"=r"(r[1]),"=r"(r[2]),"=r"(r[3]) : "r"(a));
}
static __device__ __forceinline__ void mma_f16(float* c,
        uint32_t a0, uint32_t a1, uint32_t a2, uint32_t a3, uint32_t b0, uint32_t b1){
    asm volatile("mma.sync.aligned.m16n8k16.row.col.f32.f16.f16.f32 "
                 "{%0,%1,%2,%3},{%4,%5,%6,%7},{%8,%9},{%0,%1,%2,%3};"
                 : "+f"(c[0]), "+f"(c[1]), "+f"(c[2]), "+f"(c[3])
                 : "r"(a0), "r"(a1), "r"(a2), "r"(a3), "r"(b0), "r"(b1));
}

// ---------------- multistage fp16 mma GEMM: C[M,N] = A @ B^T ----------------
// A,B: fp16 K-slot-major as uint32 pairs. Ks = slot count (mult of 64). Chunk = 64 slots = 128B.
template<int BM,int BN,int WM,int WN>
__global__ void __launch_bounds__(256, ((BM+BN)*768 <= 228*1024) ? 2 : 1)
gemm_mma_k(const uint32_t* __restrict__ Au, const uint32_t* __restrict__ Bu,
           float* __restrict__ C, int ldc, int Ks){
    constexpr int S = 3;
    constexpr int ABYTES = BM*128, STAGE = (BM+BN)*128;
    constexpr int WNW = BN/WN;
    constexpr int MI = WM/16, NJ = WN/8, NJ2 = NJ/2;
    constexpr int NLD = (BM+BN)/32;

    extern __shared__ char sm[];
    uint32_t smBase = (uint32_t)__cvta_generic_to_shared(sm);

    const int tid = threadIdx.x, warp = tid>>5, lane = tid&31;
    const int wm = warp / WNW, wn = warp % WNW;
    const int i8 = lane&7, sub = lane>>3;
    const int g = lane>>2, t4 = lane&3;
    const int rowBase = blockIdx.x*BM, colBase = blockIdx.y*BN;
    const char* Ab = (const char*)Au;
    const char* Bb = (const char*)Bu;
    const size_t Kb = (size_t)Ks*2;
    const int NC = Ks>>6;

    const int cA = sub>>1, cB = sub&1;
    uint32_t aRow[MI], bRow[NJ2];
    #pragma unroll
    for(int it=0;it<MI;it++)
        aRow[it] = smBase + (uint32_t)((wm*WM + it*16 + (sub&1)*8 + i8)*128);
    #pragma unroll
    for(int jp=0;jp<NJ2;jp++)
        bRow[jp] = smBase + (uint32_t)(ABYTES + (wn*WN + jp*16 + (sub>>1)*8 + i8)*128);

    float acc[MI][NJ][4];
    #pragma unroll
    for(int i=0;i<MI;i++)
        #pragma unroll
        for(int j=0;j<NJ;j++)
            #pragma unroll
            for(int e=0;e<4;e++) acc[i][j][e] = 0.0f;

    auto load_chunk = [&](int ck, int s){
        #pragma unroll
        for(int u=0;u<NLD;u++){
            int idx = tid + u*256;
            int isA = (idx < BM*8);
            int ii = isA ? idx : idx - BM*8;
            int r = ii>>3, c = ii&7;
            const char* gp = isA
                ? Ab + (size_t)(rowBase + r)*Kb + (size_t)ck*128 + c*16
                : Bb + (size_t)(colBase + r)*Kb + (size_t)ck*128 + c*16;
            uint32_t so = smBase + (uint32_t)(s*STAGE + (isA?0:ABYTES)
                        + r*128 + ((c ^ (r&7))<<4));
            cp16(so, gp);
        }
        cp_commit();
    };

    load_chunk(0, 0);
    load_chunk(1, 1);

    for(int c=0;c<NC;c++){
        cp_wait<1>();
        __syncthreads();
        if(c+2 < NC) load_chunk(c+2, (c+2)%S);
        else cp_commit();

        const uint32_t bufOff = (uint32_t)((c%S)*STAGE);
        #pragma unroll
        for(int kk=0;kk<4;kk++){
            uint32_t ah[MI][4], bb[NJ2][4];
            #pragma unroll
            for(int it=0;it<MI;it++)
                ldsm4(ah[it], aRow[it] + bufOff + (uint32_t)((((2*kk + cA) ^ i8))<<4));
            #pragma unroll
            for(int jp=0;jp<NJ2;jp++)
                ldsm4(bb[jp], bRow[jp] + bufOff + (uint32_t)((((2*kk + cB) ^ i8))<<4));
            #pragma unroll
            for(int it=0;it<MI;it++)
                #pragma unroll
                for(int jt=0;jt<NJ;jt++){
                    const uint32_t* bf = bb[jt>>1];
                    int o = (jt&1)*2;
                    mma_f16(acc[it][jt], ah[it][0], ah[it][1], ah[it][2], ah[it][3],
                            bf[o], bf[o+1]);
                }
        }
    }

    #pragma unroll
    for(int jt=0;jt<NJ;jt++){
        int c = colBase + wn*WN + jt*8 + t4*2;
        #pragma unroll
        for(int it=0;it<MI;it++){
            int r = rowBase + wm*WM + it*16 + g;
            *(float2*)(C + (size_t)r*ldc + c)     = make_float2(acc[it][jt][0], acc[it][jt][1]);
            *(float2*)(C + (size_t)(r+8)*ldc + c) = make_float2(acc[it][jt][2], acc[it][jt][3]);
        }
    }
}

// ---------------- column norms (for fo / fffo, consumed by delta / wpack_fo) ----------------
__global__ void colnorm_k(const float* __restrict__ W, float* __restrict__ f, int R, int C){
    int l = blockIdx.y;
    int c = blockIdx.x*blockDim.x + threadIdx.x;
    if(c >= C) return;
    const float* Wl = W + (size_t)l*R*C;
    float s = 0.0f;
    for(int r=0;r<R;r++){ float w = Wl[(size_t)r*C + c]; s += w*w; }
    f[(size_t)l*C + c] = l2fac(sqrtf(s));
}

// ---------------- fused norm + pack kernels (weights read once) ----------------
__global__ void wpack_qkv_k(const float* __restrict__ Wq, const float* __restrict__ Wk,
                            const float* __restrict__ Wv, uint32_t* __restrict__ dst){
    __shared__ float red[256];
    int rr = blockIdx.x;
    int l = rr / NQKV, r = rr % NQKV;
    int which = r >> 10, rl = r & 1023;
    const float* W = (which==0) ? Wq : (which==1) ? Wk : Wv;
    const float4* sp = (const float4*)(W + ((size_t)l*Dm + rl)*Dm);
    float4 v = sp[threadIdx.x];
    float s = v.x*v.x + v.y*v.y + v.z*v.z + v.w*v.w;
    s = blocksum256(s, red);
    float f = l2fac(sqrtf(s));
    uint32_t* dp = dst + (size_t)rr*UD + 4*threadIdx.x;
    pack_w2f(dp,   v.x*f, v.y*f);
    pack_w2f(dp+2, v.z*f, v.w*f);
}
__global__ void wpack_o_k(const float* __restrict__ Wo, uint32_t* __restrict__ dst){
    int rr = blockIdx.x;
    const float4* sp = (const float4*)(Wo + (size_t)rr*Dm);
    float4 v = sp[threadIdx.x];
    uint32_t* dp = dst + (size_t)rr*UD + 4*threadIdx.x;
    pack_w2f(dp,   v.x, v.y);
    pack_w2f(dp+2, v.z, v.w);
}
__global__ void wpack_hg_k(const float* __restrict__ Wffh, const float* __restrict__ Wffg,
                           const float* __restrict__ hsc, const float* __restrict__ gsc,
                           uint32_t* __restrict__ dst){
    __shared__ float red[256];
    int rr = blockIdx.x;
    int l = rr / NHG, r = rr % NHG;
    uint32_t* dp0 = dst + (size_t)rr*UD;
    const float* W; float sc; int valid = 1;
    if(r < DFFP){
        if(r < DFFn){ size_t sr=(size_t)l*DFFn+r; W=Wffh+sr*Dm; sc=hsc[sr]; }
        else valid = 0;
    } else {
        int rg = r - DFFP;
        if(rg < DFFn){ size_t sr=(size_t)l*DFFn+rg; W=Wffg+sr*Dm; sc=gsc[sr]*32.0f; }
        else valid = 0;
    }
    if(!valid){
        #pragma unroll
        for(int u=0;u<4;u++) dp0[threadIdx.x + u*256] = 0u;
        return;
    }
    float4 v = ((const float4*)W)[threadIdx.x];
    float s = v.x*v.x + v.y*v.y + v.z*v.z + v.w*v.w;
    s = blocksum256(s, red);
    float f = l2fac(sqrtf(s))*sc;
    uint32_t* dp = dp0 + 4*threadIdx.x;
    pack_w2f(dp,   v.x*f, v.y*f);
    pack_w2f(dp+2, v.z*f, v.w*f);
}
__global__ void wpack_fo_k(const float* __restrict__ Wffo, const float* __restrict__ fffo,
                           uint32_t* __restrict__ dst){
    int rr = blockIdx.x;
    int l = rr / Dm, rl = rr % Dm;
    const float2* sp = (const float2*)(Wffo + ((size_t)l*Dm + rl)*DFFn);
    const float* ks = fffo + (size_t)l*DFFn;
    uint32_t* dp = dst + (size_t)rr*UF;
    for(int j=threadIdx.x;j<DFFP/2;j+=256){
        float x0=0.0f, x1=0.0f;
        if(2*j < DFFn){ float2 vv = sp[j]; x0 = vv.x*ks[2*j]; x1 = vv.y*ks[2*j+1]; }
        pack_w2f(dp + 2*j, x0, x1);
    }
}
__global__ void wpack_log_k(const float* __restrict__ Wl, const float* __restrict__ lsc,
                            uint32_t* __restrict__ dst){
    __shared__ float red[256];
    int r = blockIdx.x;
    const float4* sp = (const float4*)(Wl + (size_t)r*Dm);
    float4 v = sp[threadIdx.x];
    float s = v.x*v.x + v.y*v.y + v.z*v.z + v.w*v.w;
    s = blocksum256(s, red);
    float f = l2fac(sqrtf(s))*lsc[r]*32.0f;
    uint32_t* dp = dst + (size_t)r*UD + 4*threadIdx.x;
    pack_w2f(dp,   v.x*f, v.y*f);
    pack_w2f(dp+2, v.z*f, v.w*f);
}

// ---------------- embedding ----------------
__global__ void embed_k(const int* __restrict__ ids, const float* __restrict__ W_emb,
                        float* __restrict__ x, uint32_t* __restrict__ xp2){
    __shared__ float red[256];
    int m = blockIdx.x, t = threadIdx.x;
    int tok = ids[m];
    const float2* row2 = (const float2*)(W_emb + (size_t)tok*Dm);
    float2 a = row2[t], b = row2[t+256];
    float s = a.x*a.x + a.y*a.y + b.x*b.x + b.y*b.y;
    s = blocksum256(s, red);
    float f = l2fac(sqrtf(s));
    a.x*=f; a.y*=f; b.x*=f; b.y*=f;
    float2* x2 = (float2*)(x + (size_t)m*Dm);
    x2[t] = a; x2[t+256] = b;
    uint32_t* dp = xp2 + (size_t)m*UD;
    pack_a2(dp + 2*t,       a.x, a.y);
    pack_a2(dp + 2*(t+256), b.x, b.y);
}

// ---------------- wbeta ----------------
__global__ void wbeta_k(const float* __restrict__ Wb, const float* __restrict__ bscale,
                        int l, float* __restrict__ out){
    __shared__ float red[64]; __shared__ float stot;
    int t = threadIdx.x;
    float w = Wb[l*DHd + t];
    red[t] = w*w; __syncthreads();
    if(t<32) red[t] += red[t+32];
    __syncthreads();
    if(t==0){ float s=0; for(int i=0;i<32;i++) s += red[i]; stot = s; }
    __syncthreads();
    float fac = l2fac(sqrtf(stot));
    out[t] = w * fac * (bscale[l] * 0.1f);
}

// ---------------- attn prep ----------------
__global__ void attn_prep_k(const float* __restrict__ qkv, const float* __restrict__ qs_l,
                            const float* __restrict__ wbn,
                            float* __restrict__ qh, float* __restrict__ kh,
                            float* __restrict__ vh, float* __restrict__ v0h,
                            float* __restrict__ betab, int is_l0){
    int m = blockIdx.x;
    int b = m / SEQn, s = m % SEQn;
    int lane = threadIdx.x & 31, warp = threadIdx.x >> 5;
    #pragma unroll
    for(int hi=0; hi<NH/4; hi++){
        int h = warp*4 + hi;
        size_t src = (size_t)m*NQKV + h*DHd;
        int d0 = lane, d1 = lane + 32;
        float q0=qkv[src+d0],        q1=qkv[src+d1];
        float k0=qkv[src+Dm+d0],     k1=qkv[src+Dm+d1];
        float w0=qkv[src+2*Dm+d0],   w1=qkv[src+2*Dm+d1];
        float fqv = l2fac(sqrtf(warpsum(q0*q0 + q1*q1)));
        float fkv = l2fac(sqrtf(warpsum(k0*k0 + k1*k1)));
        float kn0 = k0*fkv, kn1 = k1*fkv;
        float bd = warpsum(kn0*wbn[d0] + kn1*wbn[d1]);
        size_t dst = ((size_t)(b*NH + h)*SEQn + s)*DHd;
        qh[dst+d0] = q0*fqv*qs_l[h*DHd+d0]*1024.0f;
        qh[dst+d1] = q1*fqv*qs_l[h*DHd+d1]*1024.0f;
        kh[dst+d0] = kn0; kh[dst+d1] = kn1;
        float vv0, vv1;
        if(is_l0){ vv0=w0; vv1=w1; v0h[dst+d0]=w0; v0h[dst+d1]=w1; }
        else     { vv0=0.5f*(w0 + v0h[dst+d0]); vv1=0.5f*(w1 + v0h[dst+d1]); }
        vh[dst+d0]=vv0; vh[dst+d1]=vv1;
        if(lane==0) betab[(size_t)(b*NH+h)*SEQn + s] = 1.0f/(1.0f + expf(-bd));
    }
}

// ---------------- delta rule (128 threads: k-dim split by parity) ----------------
#define DCH 32
__global__ void delta_k(const float* __restrict__ qh, const float* __restrict__ kh,
                        const float* __restrict__ vh, const float* __restrict__ betab,
                        uint32_t* __restrict__ op2, const float* __restrict__ fWo){
    int bh = blockIdx.x;
    int b = bh / NH, h = bh % NH;
    int t = threadIdx.x;            // 0..127
    int col = t>>1, par = t&1;      // col: output column; par: k-parity half
    float St[32];                   // state rows 2j+par, column col
    #pragma unroll
    for(int i=0;i<32;i++) St[i] = 0.0f;

    __shared__ float ks[DCH*DHd];
    __shared__ float qs[DCH*DHd];
    __shared__ float vs[DCH*DHd];
    __shared__ float bs[DCH];

    size_t base = (size_t)bh*SEQn*DHd;
    float fo = fWo[h*DHd + col];

    for(int c0=0;c0<SEQn;c0+=DCH){
        __syncthreads();
        for(int i=t;i<DCH*DHd;i+=128){
            ks[i] = kh[base + (size_t)c0*DHd + i];
            qs[i] = qh[base + (size_t)c0*DHd + i];
            vs[i] = vh[base + (size_t)c0*DHd + i];
        }
        if(t < DCH) bs[t] = betab[(size_t)bh*SEQn + c0 + t];
        __syncthreads();
        for(int tt=0;tt<DCH;tt++){
            const float* kt = &ks[tt*DHd];
            const float* qt = &qs[tt*DHd];
            float p0=0,p1=0,p2=0,p3=0;
            #pragma unroll
            for(int j=0;j<32;j+=4){
                p0 += kt[2*j+par]*St[j];
                p1 += kt[2*(j+1)+par]*St[j+1];
                p2 += kt[2*(j+2)+par]*St[j+2];
                p3 += kt[2*(j+3)+par]*St[j+3];
            }
            float kS = (p0+p1)+(p2+p3);
            kS += __shfl_xor_sync(0xffffffffu, kS, 1);
            float dlt = bs[tt]*(vs[tt*DHd + col] - kS);
            float o0=0,o1=0,o2=0,o3=0;
            #pragma unroll
            for(int j=0;j<32;j+=4){
                St[j]   += kt[2*j+par]*dlt;     o0 += qt[2*j+par]*St[j];
                St[j+1] += kt[2*(j+1)+par]*dlt; o1 += qt[2*(j+1)+par]*St[j+1];
                St[j+2] += kt[2*(j+2)+par]*dlt; o2 += qt[2*(j+2)+par]*St[j+2];
                St[j+3] += kt[2*(j+3)+par]*dlt; o3 += qt[2*(j+3)+par]*St[j+3];
            }
            float o = (o0+o1)+(o2+o3);
            o += __shfl_xor_sync(0xffffffffu, o, 1);
            o *= fo;
            float oN = __shfl_down_sync(0xffffffffu, o, 2);
            if((t & 3) == 0){
                uint32_t* dp = op2 + (size_t)(b*SEQn + c0 + tt)*UD + 2*(h*32 + (col>>1));
                pack_a2(dp, o, oN);
            }
        }
    }
}

// ---------------- residual ----------------
__global__ void resid_k(float* __restrict__ x, const float* __restrict__ o,
                        const float* __restrict__ alpha, uint32_t* __restrict__ xp2){
    __shared__ float red[256];
    int m = blockIdx.x, t = threadIdx.x;
    const float2* o2 = (const float2*)(o + (size_t)m*Dm);
    float2 oa = o2[t], ob = o2[t+256];
    float s = oa.x*oa.x + oa.y*oa.y + ob.x*ob.x + ob.y*ob.y;
    s = blocksum256(s, red);
    float fh = l2fac(sqrtf(s));
    float2* x2 = (float2*)(x + (size_t)m*Dm);
    float2 xa = x2[t], xb = x2[t+256];
    const float2* al2 = (const float2*)alpha;
    float2 aa = al2[t], ab = al2[t+256];
    float ya0 = xa.x + aa.x*8.0f*(oa.x*fh - xa.x);
    float ya1 = xa.y + aa.y*8.0f*(oa.y*fh - xa.y);
    float yb0 = xb.x + ab.x*8.0f*(ob.x*fh - xb.x);
    float yb1 = xb.y + ab.y*8.0f*(ob.y*fh - xb.y);
    float s2 = ya0*ya0 + ya1*ya1 + yb0*yb0 + yb1*yb1;
    s2 = blocksum256(s2, red);
    float f2 = l2fac(sqrtf(s2));
    ya0*=f2; ya1*=f2; yb0*=f2; yb1*=f2;
    x2[t]     = make_float2(ya0, ya1);
    x2[t+256] = make_float2(yb0, yb1);
    uint32_t* dp = xp2 + (size_t)m*UD;
    pack_a2(dp + 2*t,       ya0, ya1);
    pack_a2(dp + 2*(t+256), yb0, yb1);
}

// ---------------- silu(gate)*hidden -> packed z ----------------
__global__ void ffmul_k(const float* __restrict__ hg, uint32_t* __restrict__ zp2){
    size_t idx = (size_t)blockIdx.x*256 + threadIdx.x;
    if(idx >= (size_t)MT*(DFFP/2)) return;
    int m = (int)(idx / (DFFP/2));
    int j = (int)(idx % (DFFP/2));
    const float2* row = (const float2*)(hg + (size_t)m*NHG);
    float2 h = row[j];
    float2 gt = row[DFFP/2 + j];
    float z0 = gt.x/(1.0f + expf(-gt.x))*h.x;
    float z1 = gt.y/(1.0f + expf(-gt.y))*h.y;
    pack_a2(zp2 + (size_t)m*UF + 2*j, z0, z1);
}

// ---------------- host ----------------
template<typename T> static void* symaddr(T& s){
    void* p = nullptr; cudaGetSymbolAddress(&p, s); return p;
}

extern "C" void kernel_launch(void* const* d_in, const int* in_sizes, int n_in,
                              void* d_out, int out_size){
    (void)in_sizes; (void)n_in; (void)out_size;
    const int*   ids        = (const int*)  d_in[0];
    const float* W_emb      = (const float*)d_in[2];
    const float* Wq         = (const float*)d_in[3];
    const float* Wk         = (const float*)d_in[4];
    const float* Wv         = (const float*)d_in[5];
    const float* Wbeta      = (const float*)d_in[6];
    const float* Wo         = (const float*)d_in[7];
    const float* Wffh       = (const float*)d_in[8];
    const float* Wffg       = (const float*)d_in[9];
    const float* Wffo       = (const float*)d_in[10];
    const float* qk_scale   = (const float*)d_in[11];
    const float* beta_scale = (const float*)d_in[12];
    const float* attn_alpha = (const float*)d_in[13];
    const float* ff_alpha   = (const float*)d_in[14];
    const float* ffh_scale  = (const float*)d_in[15];
    const float* ffg_scale  = (const float*)d_in[16];
    const float* W_logits   = (const float*)d_in[17];
    const float* logit_scale= (const float*)d_in[18];
    float* out = (float*)d_out;

    float* x     = (float*)symaddr(g_x);
    float* qkv   = (float*)symaddr(g_qkv);
    float* obuf  = (float*)symaddr(g_obuf);
    float* hg    = (float*)symaddr(g_hg);
    float* qh    = (float*)symaddr(g_qh);
    float* kh    = (float*)symaddr(g_kh);
    float* vh    = (float*)symaddr(g_vh);
    float* v0h   = (float*)symaddr(g_v0h);
    float* betab = (float*)symaddr(g_betab);
    float* fo    = (float*)symaddr(g_fo);
    float* fffo  = (float*)symaddr(g_fffo);
    float* wbn   = (float*)symaddr(g_wbn);
    uint32_t* xp2   = (uint32_t*)symaddr(g_xp2);
    uint32_t* op2   = (uint32_t*)symaddr(g_op2);
    uint32_t* zp2   = (uint32_t*)symaddr(g_zp2);
    uint32_t* wqkv2 = (uint32_t*)symaddr(g_wqkv2);
    uint32_t* wo2   = (uint32_t*)symaddr(g_wo2);
    uint32_t* whg2  = (uint32_t*)symaddr(g_whg2);
    uint32_t* wfo2  = (uint32_t*)symaddr(g_wfo2);
    uint32_t* wl2   = (uint32_t*)symaddr(g_wl2);

    cudaFuncSetAttribute(gemm_mma_k<128,128,64,32>, cudaFuncAttributeMaxDynamicSharedMemorySize, 98304);
    cudaFuncSetAttribute(gemm_mma_k<64,128,32,32>,  cudaFuncAttributeMaxDynamicSharedMemorySize, 73728);
    cudaFuncSetAttribute(gemm_mma_k<128,256,64,64>, cudaFuncAttributeMaxDynamicSharedMemorySize, 147456);

    // column norms (consumed by delta epilogue / wpack_fo)
    colnorm_k<<<dim3((Dm+255)/256,   NL), 256>>>(Wo,   fo,   Dm, Dm);
    colnorm_k<<<dim3((DFFn+255)/256, NL), 256>>>(Wffo, fffo, Dm, DFFn);

    // fused norm+pack (weights read once)
    wpack_qkv_k<<<NL*NQKV, 256>>>(Wq, Wk, Wv, wqkv2);
    wpack_o_k<<<NL*Dm, 256>>>(Wo, wo2);
    wpack_hg_k<<<NL*NHG, 256>>>(Wffh, Wffg, ffh_scale, ffg_scale, whg2);
    wpack_fo_k<<<NL*Dm, 256>>>(Wffo, fffo, wfo2);
    wpack_log_k<<<NV, 256>>>(W_logits, logit_scale, wl2);

    embed_k<<<MT, 256>>>(ids, W_emb, x, xp2);

    for(int l=0;l<NL;l++){
        // fused qkv: [1024,3072], Ks=2048
        gemm_mma_k<128,128,64,32><<<dim3(8, NQKV/128), 256, 98304>>>(
            xp2, wqkv2 + (size_t)l*NQKV*UD, qkv, NQKV, 2*Dm);
        wbeta_k<<<1, 64>>>(Wbeta, beta_scale, l, wbn);
        attn_prep_k<<<MT, 128>>>(qkv, qk_scale + l*Dm, wbn, qh, kh, vh, v0h, betab, (l==0)?1:0);
        delta_k<<<NB*NH, 128>>>(qh, kh, vh, betab, op2, fo + l*Dm);
        // o projection: [1024,1024]
        gemm_mma_k<64,128,32,32><<<dim3(16, Dm/128), 256, 73728>>>(
            op2, wo2 + (size_t)l*Dm*UD, obuf, Dm, 2*Dm);
        resid_k<<<MT, 256>>>(x, obuf, attn_alpha + l*Dm, xp2);
        // fused ff hidden|gate: [1024,5632]
        gemm_mma_k<128,256,64,64><<<dim3(8, NHG/256), 256, 147456>>>(
            xp2, whg2 + (size_t)l*NHG*UD, hg, NHG, 2*Dm);
        ffmul_k<<<(MT*(DFFP/2) + 255)/256, 256>>>(hg, zp2);
        // ff out: [1024,1024], Ks=5632
        gemm_mma_k<64,128,32,32><<<dim3(16, Dm/128), 256, 73728>>>(
            zp2, wfo2 + (size_t)l*Dm*UF, obuf, Dm, 2*DFFP);
        resid_k<<<MT, 256>>>(x, obuf, ff_alpha + l*Dm, xp2);
    }
    // logits: [1024,32000]
    gemm_mma_k<128,256,64,64><<<dim3(8, NV/256), 256, 147456>>>(
        xp2, wl2, out, NV, 2*Dm);
}

// round 7
// speedup vs baseline: 3.8850x; 1.0280x over previous
#include <cuda_runtime.h>
#include <cuda_bf16.h>
#include <cuda_fp16.h>
#include <math.h>
#include <stdint.h>

#define Dm    1024
#define SEQn  512
#define NB    2
#define NH    16
#define DHd   64
#define DFFn  2730
#define DFFP  2816
#define NV    32000
#define NL    4
#define MT    1024
#define NQKV  3072
#define NHG   5632
#define UD    1024    // uint32 per row, K-slots=2048 (2*Dm)
#define UF    2816    // uint32 per row, K-slots=5632 (2*DFFP)

// ---------------- fp32 scratch ----------------
__device__ float g_x[MT*Dm];
__device__ float g_qkv[MT*NQKV];
__device__ float g_obuf[MT*Dm];
__device__ float g_qh[NB*NH*SEQn*DHd];
__device__ float g_kh[NB*NH*SEQn*DHd];
__device__ float g_vh[NB*NH*SEQn*DHd];
__device__ float g_v0h[NB*NH*SEQn*DHd];
__device__ float g_betab[NB*NH*SEQn];
__device__ float g_fo[NL*Dm];
__device__ float g_fffo[NL*DFFn];

// ---------------- packed fp16 2-plane buffers (uint32 = 2 fp16 k-slots) ----------------
__device__ uint32_t g_xp2 [MT*UD];
__device__ uint32_t g_op2 [MT*UD];
__device__ uint32_t g_zp2 [MT*UF];
__device__ uint32_t g_wqkv2[(size_t)NL*NQKV*UD];
__device__ uint32_t g_wo2  [(size_t)NL*Dm*UD];
__device__ uint32_t g_whg2 [(size_t)NL*NHG*UD];
__device__ uint32_t g_wfo2 [(size_t)NL*Dm*UF];
__device__ uint32_t g_wl2  [(size_t)NV*UD];

// ---------------- scalar helpers ----------------
static __device__ __forceinline__ float l2fac(float n){
    float tgt = fminf(fmaxf(n, 1.0f - 1e-5f), 1.0f + 1e-5f);
    return 1.0f / fmaxf(n / tgt, 1e-10f);
}
static __device__ __forceinline__ float warpsum(float v){
    #pragma unroll
    for(int o=16;o>0;o>>=1) v += __shfl_xor_sync(0xffffffffu, v, o);
    return v;
}
static __device__ __forceinline__ float blocksum256(float v, float* red){
    red[threadIdx.x] = v; __syncthreads();
    for(int o=128;o>0;o>>=1){
        if(threadIdx.x < o) red[threadIdx.x] += red[threadIdx.x+o];
        __syncthreads();
    }
    float r = red[0]; __syncthreads();
    return r;
}

// activations: slots [hi, lo] per element — exact fp32 reconstruction
static __device__ __forceinline__ uint32_t pack_a1(float x){
    __half h=__float2half_rn(x);
    __half l=__float2half_rn(x-__half2float(h));
    return (uint32_t)__half_as_ushort(h) | ((uint32_t)__half_as_ushort(l)<<16);
}
static __device__ __forceinline__ void pack_a2(uint32_t* d, float x0, float x1){
    d[0] = pack_a1(x0);
    d[1] = pack_a1(x1);
}
// weights: slots [hi, hi] per element
static __device__ __forceinline__ void pack_w2f(uint32_t* d, float x0, float x1){
    uint32_t h0=__half_as_ushort(__float2half_rn(x0));
    uint32_t h1=__half_as_ushort(__float2half_rn(x1));
    d[0] = h0|(h0<<16); d[1] = h1|(h1<<16);
}

// ---------------- cp.async / ldmatrix / mma primitives ----------------
static __device__ __forceinline__ void cp16(uint32_t saddr, const void* g){
    asm volatile("cp.async.cg.shared.global [%0], [%1], 16;" :: "r"(saddr), "l"(g) : "memory");
}
static __device__ __forceinline__ void cp_commit(){
    asm volatile("cp.async.commit_group;" ::: "memory");
}
template<int N> static __device__ __forceinline__ void cp_wait(){
    asm volatile("cp.async.wait_group %0;" :: "n"(N) : "memory");
}
static __device__ __forceinline__ void ldsm4(uint32_t* r, uint32_t a){
    asm volatile("ldmatrix.sync.aligned.m8n8.x4.shared.b16 {%0,%1,%2,%3}, [%4];"
        : "=r"(r[0]),"=r"(r[1]),"=r"(r[2]),"=r"(r[3]) : "r"(a));
}
static __device__ __forceinline__ void mma_f16(float* c,
        uint32_t a0, uint32_t a1, uint32_t a2, uint32_t a3, uint32_t b0, uint32_t b1){
    asm volatile("mma.sync.aligned.m16n8k16.row.col.f32.f16.f16.f32 "
                 "{%0,%1,%2,%3},{%4,%5,%6,%7},{%8,%9},{%0,%1,%2,%3};"
                 : "+f"(c[0]), "+f"(c[1]), "+f"(c[2]), "+f"(c[3])
                 : "r"(a0), "r"(a1), "r"(a2), "r"(a3), "r"(b0), "r"(b1));
}

// ---------------- multistage fp16 mma GEMM: C[M,N] = A @ B^T ----------------
// EPI 0: C fp32 (ldc = fp32 stride). EPI 1: adjacent col pairs are (h,g);
// writes pack_a1(silu(g)*h) into uint32 C at column pair index (ldc = uint32 stride).
template<int BM,int BN,int WM,int WN,int S,int EPI>
__global__ void __launch_bounds__(256, ((BM+BN)*128*S <= 114688) ? 2 : 1)
gemm_mma_k(const uint32_t* __restrict__ Au, const uint32_t* __restrict__ Bu,
           void* __restrict__ Cv, int ldc, int Ks){
    constexpr int ABYTES = BM*128, STAGE = (BM+BN)*128;
    constexpr int WNW = BN/WN;
    constexpr int MI = WM/16, NJ = WN/8, NJ2 = NJ/2;
    constexpr int NLD = (BM+BN)/32;

    extern __shared__ char sm[];
    uint32_t smBase = (uint32_t)__cvta_generic_to_shared(sm);

    const int tid = threadIdx.x, warp = tid>>5, lane = tid&31;
    const int wm = warp / WNW, wn = warp % WNW;
    const int i8 = lane&7, sub = lane>>3;
    const int g = lane>>2, t4 = lane&3;
    const int rowBase = blockIdx.x*BM, colBase = blockIdx.y*BN;
    const char* Ab = (const char*)Au;
    const char* Bb = (const char*)Bu;
    const size_t Kb = (size_t)Ks*2;
    const int NC = Ks>>6;

    const int cA = sub>>1, cB = sub&1;
    uint32_t aRow[MI], bRow[NJ2];
    #pragma unroll
    for(int it=0;it<MI;it++)
        aRow[it] = smBase + (uint32_t)((wm*WM + it*16 + (sub&1)*8 + i8)*128);
    #pragma unroll
    for(int jp=0;jp<NJ2;jp++)
        bRow[jp] = smBase + (uint32_t)(ABYTES + (wn*WN + jp*16 + (sub>>1)*8 + i8)*128);

    float acc[MI][NJ][4];
    #pragma unroll
    for(int i=0;i<MI;i++)
        #pragma unroll
        for(int j=0;j<NJ;j++)
            #pragma unroll
            for(int e=0;e<4;e++) acc[i][j][e] = 0.0f;

    auto load_chunk = [&](int ck, int s){
        #pragma unroll
        for(int u=0;u<NLD;u++){
            int idx = tid + u*256;
            int isA = (idx < BM*8);
            int ii = isA ? idx : idx - BM*8;
            int r = ii>>3, c = ii&7;
            const char* gp = isA
                ? Ab + (size_t)(rowBase + r)*Kb + (size_t)ck*128 + c*16
                : Bb + (size_t)(colBase + r)*Kb + (size_t)ck*128 + c*16;
            uint32_t so = smBase + (uint32_t)(s*STAGE + (isA?0:ABYTES)
                        + r*128 + ((c ^ (r&7))<<4));
            cp16(so, gp);
        }
        cp_commit();
    };

    #pragma unroll
    for(int s=0;s<S-1;s++) load_chunk(s, s);

    for(int c=0;c<NC;c++){
        cp_wait<S-2>();
        __syncthreads();
        if(c+S-1 < NC) load_chunk(c+S-1, (c+S-1)%S);
        else cp_commit();

        const uint32_t bufOff = (uint32_t)((c%S)*STAGE);
        #pragma unroll
        for(int kk=0;kk<4;kk++){
            uint32_t ah[MI][4], bb[NJ2][4];
            #pragma unroll
            for(int it=0;it<MI;it++)
                ldsm4(ah[it], aRow[it] + bufOff + (uint32_t)((((2*kk + cA) ^ i8))<<4));
            #pragma unroll
            for(int jp=0;jp<NJ2;jp++)
                ldsm4(bb[jp], bRow[jp] + bufOff + (uint32_t)((((2*kk + cB) ^ i8))<<4));
            #pragma unroll
            for(int it=0;it<MI;it++)
                #pragma unroll
                for(int jt=0;jt<NJ;jt++){
                    const uint32_t* bf = bb[jt>>1];
                    int o = (jt&1)*2;
                    mma_f16(acc[it][jt], ah[it][0], ah[it][1], ah[it][2], ah[it][3],
                            bf[o], bf[o+1]);
                }
        }
    }

    if(EPI == 0){
        float* C = (float*)Cv;
        #pragma unroll
        for(int jt=0;jt<NJ;jt++){
            int c = colBase + wn*WN + jt*8 + t4*2;
            #pragma unroll
            for(int it=0;it<MI;it++){
                int r = rowBase + wm*WM + it*16 + g;
                *(float2*)(C + (size_t)r*ldc + c)     = make_float2(acc[it][jt][0], acc[it][jt][1]);
                *(float2*)(C + (size_t)(r+8)*ldc + c) = make_float2(acc[it][jt][2], acc[it][jt][3]);
            }
        }
    } else {
        uint32_t* C = (uint32_t*)Cv;
        #pragma unroll
        for(int jt=0;jt<NJ;jt++){
            int cpair = (colBase + wn*WN + jt*8 + t4*2) >> 1;
            #pragma unroll
            for(int it=0;it<MI;it++){
                int r = rowBase + wm*WM + it*16 + g;
                float h0 = acc[it][jt][0], g0 = acc[it][jt][1];
                float h1 = acc[it][jt][2], g1 = acc[it][jt][3];
                float z0 = g0/(1.0f + expf(-g0))*h0;
                float z1 = g1/(1.0f + expf(-g1))*h1;
                C[(size_t)r*ldc + cpair]     = pack_a1(z0);
                C[(size_t)(r+8)*ldc + cpair] = pack_a1(z1);
            }
        }
    }
}

// ---------------- column norms ----------------
__global__ void colnorm_k(const float* __restrict__ W, float* __restrict__ f, int R, int C){
    int l = blockIdx.y;
    int c = blockIdx.x*blockDim.x + threadIdx.x;
    if(c >= C) return;
    const float* Wl = W + (size_t)l*R*C;
    float s = 0.0f;
    for(int r=0;r<R;r++){ float w = Wl[(size_t)r*C + c]; s += w*w; }
    f[(size_t)l*C + c] = l2fac(sqrtf(s));
}

// ---------------- fused norm + pack kernels ----------------
__global__ void wpack_qkv_k(const float* __restrict__ Wq, const float* __restrict__ Wk,
                            const float* __restrict__ Wv, uint32_t* __restrict__ dst){
    __shared__ float red[256];
    int rr = blockIdx.x;
    int l = rr / NQKV, r = rr % NQKV;
    int which = r >> 10, rl = r & 1023;
    const float* W = (which==0) ? Wq : (which==1) ? Wk : Wv;
    const float4* sp = (const float4*)(W + ((size_t)l*Dm + rl)*Dm);
    float4 v = sp[threadIdx.x];
    float s = v.x*v.x + v.y*v.y + v.z*v.z + v.w*v.w;
    s = blocksum256(s, red);
    float f = l2fac(sqrtf(s));
    uint32_t* dp = dst + (size_t)rr*UD + 4*threadIdx.x;
    pack_w2f(dp,   v.x*f, v.y*f);
    pack_w2f(dp+2, v.z*f, v.w*f);
}
__global__ void wpack_o_k(const float* __restrict__ Wo, uint32_t* __restrict__ dst){
    int rr = blockIdx.x;
    const float4* sp = (const float4*)(Wo + (size_t)rr*Dm);
    float4 v = sp[threadIdx.x];
    uint32_t* dp = dst + (size_t)rr*UD + 4*threadIdx.x;
    pack_w2f(dp,   v.x, v.y);
    pack_w2f(dp+2, v.z, v.w);
}
// interleaved h/g rows: dst row 2p = Wffh row p, dst row 2p+1 = Wffg row p
__global__ void wpack_hg_k(const float* __restrict__ Wffh, const float* __restrict__ Wffg,
                           const float* __restrict__ hsc, const float* __restrict__ gsc,
                           uint32_t* __restrict__ dst){
    __shared__ float red[256];
    int rr = blockIdx.x;
    int l = rr / NHG, r = rr % NHG;
    int p = r >> 1, isG = r & 1;
    uint32_t* dp0 = dst + (size_t)rr*UD;
    if(p >= DFFn){
        #pragma unroll
        for(int u=0;u<4;u++) dp0[threadIdx.x + u*256] = 0u;
        return;
    }
    size_t sr = (size_t)l*DFFn + p;
    const float* W = isG ? (Wffg + sr*Dm) : (Wffh + sr*Dm);
    float sc = isG ? gsc[sr]*32.0f : hsc[sr];
    float4 v = ((const float4*)W)[threadIdx.x];
    float s = v.x*v.x + v.y*v.y + v.z*v.z + v.w*v.w;
    s = blocksum256(s, red);
    float f = l2fac(sqrtf(s))*sc;
    uint32_t* dp = dp0 + 4*threadIdx.x;
    pack_w2f(dp,   v.x*f, v.y*f);
    pack_w2f(dp+2, v.z*f, v.w*f);
}
__global__ void wpack_fo_k(const float* __restrict__ Wffo, const float* __restrict__ fffo,
                           uint32_t* __restrict__ dst){
    int rr = blockIdx.x;
    int l = rr / Dm, rl = rr % Dm;
    const float2* sp = (const float2*)(Wffo + ((size_t)l*Dm + rl)*DFFn);
    const float* ks = fffo + (size_t)l*DFFn;
    uint32_t* dp = dst + (size_t)rr*UF;
    for(int j=threadIdx.x;j<DFFP/2;j+=256){
        float x0=0.0f, x1=0.0f;
        if(2*j < DFFn){ float2 vv = sp[j]; x0 = vv.x*ks[2*j]; x1 = vv.y*ks[2*j+1]; }
        pack_w2f(dp + 2*j, x0, x1);
    }
}
__global__ void wpack_log_k(const float* __restrict__ Wl, const float* __restrict__ lsc,
                            uint32_t* __restrict__ dst){
    __shared__ float red[256];
    int r = blockIdx.x;
    const float4* sp = (const float4*)(Wl + (size_t)r*Dm);
    float4 v = sp[threadIdx.x];
    float s = v.x*v.x + v.y*v.y + v.z*v.z + v.w*v.w;
    s = blocksum256(s, red);
    float f = l2fac(sqrtf(s))*lsc[r]*32.0f;
    uint32_t* dp = dst + (size_t)r*UD + 4*threadIdx.x;
    pack_w2f(dp,   v.x*f, v.y*f);
    pack_w2f(dp+2, v.z*f, v.w*f);
}

// ---------------- embedding ----------------
__global__ void embed_k(const int* __restrict__ ids, const float* __restrict__ W_emb,
                        float* __restrict__ x, uint32_t* __restrict__ xp2){
    __shared__ float red[256];
    int m = blockIdx.x, t = threadIdx.x;
    int tok = ids[m];
    const float2* row2 = (const float2*)(W_emb + (size_t)tok*Dm);
    float2 a = row2[t], b = row2[t+256];
    float s = a.x*a.x + a.y*a.y + b.x*b.x + b.y*b.y;
    s = blocksum256(s, red);
    float f = l2fac(sqrtf(s));
    a.x*=f; a.y*=f; b.x*=f; b.y*=f;
    float2* x2 = (float2*)(x + (size_t)m*Dm);
    x2[t] = a; x2[t+256] = b;
    uint32_t* dp = xp2 + (size_t)m*UD;
    pack_a2(dp + 2*t,       a.x, a.y);
    pack_a2(dp + 2*(t+256), b.x, b.y);
}

// ---------------- attn prep (wbeta folded in) ----------------
__global__ void attn_prep_k(const float* __restrict__ qkv, const float* __restrict__ qs_l,
                            const float* __restrict__ Wbeta, const float* __restrict__ bscale,
                            int l,
                            float* __restrict__ qh, float* __restrict__ kh,
                            float* __restrict__ vh, float* __restrict__ v0h,
                            float* __restrict__ betab, int is_l0){
    int m = blockIdx.x;
    int b = m / SEQn, s = m % SEQn;
    int lane = threadIdx.x & 31, warp = threadIdx.x >> 5;
    // inline wbeta: each warp computes the normalized beta vector (64 elems, lanes hold d, d+32)
    float wb0 = Wbeta[l*DHd + lane], wb1 = Wbeta[l*DHd + lane + 32];
    float wfac = l2fac(sqrtf(warpsum(wb0*wb0 + wb1*wb1))) * (bscale[l]*0.1f);
    float wbn0 = wb0*wfac, wbn1 = wb1*wfac;
    #pragma unroll
    for(int hi=0; hi<NH/4; hi++){
        int h = warp*4 + hi;
        size_t src = (size_t)m*NQKV + h*DHd;
        int d0 = lane, d1 = lane + 32;
        float q0=qkv[src+d0],        q1=qkv[src+d1];
        float k0=qkv[src+Dm+d0],     k1=qkv[src+Dm+d1];
        float w0=qkv[src+2*Dm+d0],   w1=qkv[src+2*Dm+d1];
        float fqv = l2fac(sqrtf(warpsum(q0*q0 + q1*q1)));
        float fkv = l2fac(sqrtf(warpsum(k0*k0 + k1*k1)));
        float kn0 = k0*fkv, kn1 = k1*fkv;
        float bd = warpsum(kn0*wbn0 + kn1*wbn1);
        size_t dst = ((size_t)(b*NH + h)*SEQn + s)*DHd;
        qh[dst+d0] = q0*fqv*qs_l[h*DHd+d0]*1024.0f;
        qh[dst+d1] = q1*fqv*qs_l[h*DHd+d1]*1024.0f;
        kh[dst+d0] = kn0; kh[dst+d1] = kn1;
        float vv0, vv1;
        if(is_l0){ vv0=w0; vv1=w1; v0h[dst+d0]=w0; v0h[dst+d1]=w1; }
        else     { vv0=0.5f*(w0 + v0h[dst+d0]); vv1=0.5f*(w1 + v0h[dst+d1]); }
        vh[dst+d0]=vv0; vh[dst+d1]=vv1;
        if(lane==0) betab[(size_t)(b*NH+h)*SEQn + s] = 1.0f/(1.0f + expf(-bd));
    }
}

// ---------------- delta rule (128 threads: k-dim split by parity) ----------------
#define DCH 32
__global__ void delta_k(const float* __restrict__ qh, const float* __restrict__ kh,
                        const float* __restrict__ vh, const float* __restrict__ betab,
                        uint32_t* __restrict__ op2, const float* __restrict__ fWo){
    int bh = blockIdx.x;
    int b = bh / NH, h = bh % NH;
    int t = threadIdx.x;
    int col = t>>1, par = t&1;
    float St[32];
    #pragma unroll
    for(int i=0;i<32;i++) St[i] = 0.0f;

    __shared__ float ks[DCH*DHd];
    __shared__ float qs[DCH*DHd];
    __shared__ float vs[DCH*DHd];
    __shared__ float bs[DCH];

    size_t base = (size_t)bh*SEQn*DHd;
    float fo = fWo[h*DHd + col];

    for(int c0=0;c0<SEQn;c0+=DCH){
        __syncthreads();
        for(int i=t;i<DCH*DHd;i+=128){
            ks[i] = kh[base + (size_t)c0*DHd + i];
            qs[i] = qh[base + (size_t)c0*DHd + i];
            vs[i] = vh[base + (size_t)c0*DHd + i];
        }
        if(t < DCH) bs[t] = betab[(size_t)bh*SEQn + c0 + t];
        __syncthreads();
        for(int tt=0;tt<DCH;tt++){
            const float* kt = &ks[tt*DHd];
            const float* qt = &qs[tt*DHd];
            float p0=0,p1=0,p2=0,p3=0;
            #pragma unroll
            for(int j=0;j<32;j+=4){
                p0 += kt[2*j+par]*St[j];
                p1 += kt[2*(j+1)+par]*St[j+1];
                p2 += kt[2*(j+2)+par]*St[j+2];
                p3 += kt[2*(j+3)+par]*St[j+3];
            }
            float kS = (p0+p1)+(p2+p3);
            kS += __shfl_xor_sync(0xffffffffu, kS, 1);
            float dlt = bs[tt]*(vs[tt*DHd + col] - kS);
            float o0=0,o1=0,o2=0,o3=0;
            #pragma unroll
            for(int j=0;j<32;j+=4){
                St[j]   += kt[2*j+par]*dlt;     o0 += qt[2*j+par]*St[j];
                St[j+1] += kt[2*(j+1)+par]*dlt; o1 += qt[2*(j+1)+par]*St[j+1];
                St[j+2] += kt[2*(j+2)+par]*dlt; o2 += qt[2*(j+2)+par]*St[j+2];
                St[j+3] += kt[2*(j+3)+par]*dlt; o3 += qt[2*(j+3)+par]*St[j+3];
            }
            float o = (o0+o1)+(o2+o3);
            o += __shfl_xor_sync(0xffffffffu, o, 1);
            o *= fo;
            float oN = __shfl_down_sync(0xffffffffu, o, 2);
            if((t & 3) == 0){
                uint32_t* dp = op2 + (size_t)(b*SEQn + c0 + tt)*UD + 2*(h*32 + (col>>1));
                pack_a2(dp, o, oN);
            }
        }
    }
}

// ---------------- residual ----------------
__global__ void resid_k(float* __restrict__ x, const float* __restrict__ o,
                        const float* __restrict__ alpha, uint32_t* __restrict__ xp2){
    __shared__ float red[256];
    int m = blockIdx.x, t = threadIdx.x;
    const float2* o2 = (const float2*)(o + (size_t)m*Dm);
    float2 oa = o2[t], ob = o2[t+256];
    float s = oa.x*oa.x + oa.y*oa.y + ob.x*ob.x + ob.y*ob.y;
    s = blocksum256(s, red);
    float fh = l2fac(sqrtf(s));
    float2* x2 = (float2*)(x + (size_t)m*Dm);
    float2 xa = x2[t], xb = x2[t+256];
    const float2* al2 = (const float2*)alpha;
    float2 aa = al2[t], ab = al2[t+256];
    float ya0 = xa.x + aa.x*8.0f*(oa.x*fh - xa.x);
    float ya1 = xa.y + aa.y*8.0f*(oa.y*fh - xa.y);
    float yb0 = xb.x + ab.x*8.0f*(ob.x*fh - xb.x);
    float yb1 = xb.y + ab.y*8.0f*(ob.y*fh - xb.y);
    float s2 = ya0*ya0 + ya1*ya1 + yb0*yb0 + yb1*yb1;
    s2 = blocksum256(s2, red);
    float f2 = l2fac(sqrtf(s2));
    ya0*=f2; ya1*=f2; yb0*=f2; yb1*=f2;
    x2[t]     = make_float2(ya0, ya1);
    x2[t+256] = make_float2(yb0, yb1);
    uint32_t* dp = xp2 + (size_t)m*UD;
    pack_a2(dp + 2*t,       ya0, ya1);
    pack_a2(dp + 2*(t+256), yb0, yb1);
}

// ---------------- host ----------------
template<typename T> static void* symaddr(T& s){
    void* p = nullptr; cudaGetSymbolAddress(&p, s); return p;
}

extern "C" void kernel_launch(void* const* d_in, const int* in_sizes, int n_in,
                              void* d_out, int out_size){
    (void)in_sizes; (void)n_in; (void)out_size;
    const int*   ids        = (const int*)  d_in[0];
    const float* W_emb      = (const float*)d_in[2];
    const float* Wq         = (const float*)d_in[3];
    const float* Wk         = (const float*)d_in[4];
    const float* Wv         = (const float*)d_in[5];
    const float* Wbeta      = (const float*)d_in[6];
    const float* Wo         = (const float*)d_in[7];
    const float* Wffh       = (const float*)d_in[8];
    const float* Wffg       = (const float*)d_in[9];
    const float* Wffo       = (const float*)d_in[10];
    const float* qk_scale   = (const float*)d_in[11];
    const float* beta_scale = (const float*)d_in[12];
    const float* attn_alpha = (const float*)d_in[13];
    const float* ff_alpha   = (const float*)d_in[14];
    const float* ffh_scale  = (const float*)d_in[15];
    const float* ffg_scale  = (const float*)d_in[16];
    const float* W_logits   = (const float*)d_in[17];
    const float* logit_scale= (const float*)d_in[18];
    float* out = (float*)d_out;

    float* x     = (float*)symaddr(g_x);
    float* qkv   = (float*)symaddr(g_qkv);
    float* obuf  = (float*)symaddr(g_obuf);
    float* qh    = (float*)symaddr(g_qh);
    float* kh    = (float*)symaddr(g_kh);
    float* vh    = (float*)symaddr(g_vh);
    float* v0h   = (float*)symaddr(g_v0h);
    float* betab = (float*)symaddr(g_betab);
    float* fo    = (float*)symaddr(g_fo);
    float* fffo  = (float*)symaddr(g_fffo);
    uint32_t* xp2   = (uint32_t*)symaddr(g_xp2);
    uint32_t* op2   = (uint32_t*)symaddr(g_op2);
    uint32_t* zp2   = (uint32_t*)symaddr(g_zp2);
    uint32_t* wqkv2 = (uint32_t*)symaddr(g_wqkv2);
    uint32_t* wo2   = (uint32_t*)symaddr(g_wo2);
    uint32_t* whg2  = (uint32_t*)symaddr(g_whg2);
    uint32_t* wfo2  = (uint32_t*)symaddr(g_wfo2);
    uint32_t* wl2   = (uint32_t*)symaddr(g_wl2);

    cudaFuncSetAttribute(gemm_mma_k<128,128,64,32,3,0>, cudaFuncAttributeMaxDynamicSharedMemorySize, 98304);
    cudaFuncSetAttribute(gemm_mma_k<128,128,64,32,3,1>, cudaFuncAttributeMaxDynamicSharedMemorySize, 98304);
    cudaFuncSetAttribute(gemm_mma_k<64,64,32,16,4,0>,   cudaFuncAttributeMaxDynamicSharedMemorySize, 65536);

    // column norms (consumed by delta epilogue / wpack_fo)
    colnorm_k<<<dim3((Dm+255)/256,   NL), 256>>>(Wo,   fo,   Dm, Dm);
    colnorm_k<<<dim3((DFFn+255)/256, NL), 256>>>(Wffo, fffo, Dm, DFFn);

    // fused norm+pack (weights read once)
    wpack_qkv_k<<<NL*NQKV, 256>>>(Wq, Wk, Wv, wqkv2);
    wpack_o_k<<<NL*Dm, 256>>>(Wo, wo2);
    wpack_hg_k<<<NL*NHG, 256>>>(Wffh, Wffg, ffh_scale, ffg_scale, whg2);
    wpack_fo_k<<<NL*Dm, 256>>>(Wffo, fffo, wfo2);
    wpack_log_k<<<NV, 256>>>(W_logits, logit_scale, wl2);

    embed_k<<<MT, 256>>>(ids, W_emb, x, xp2);

    for(int l=0;l<NL;l++){
        // fused qkv: [1024,3072], Ks=2048
        gemm_mma_k<128,128,64,32,3,0><<<dim3(8, NQKV/128), 256, 98304>>>(
            xp2, wqkv2 + (size_t)l*NQKV*UD, qkv, NQKV, 2*Dm);
        attn_prep_k<<<MT, 128>>>(qkv, qk_scale + l*Dm, Wbeta, beta_scale, l,
                                 qh, kh, vh, v0h, betab, (l==0)?1:0);
        delta_k<<<NB*NH, 128>>>(qh, kh, vh, betab, op2, fo + l*Dm);
        // o projection: [1024,1024] — 256 CTAs
        gemm_mma_k<64,64,32,16,4,0><<<dim3(16, 16), 256, 65536>>>(
            op2, wo2 + (size_t)l*Dm*UD, obuf, Dm, 2*Dm);
        resid_k<<<MT, 256>>>(x, obuf, attn_alpha + l*Dm, xp2);
        // fused ff hidden|gate with silu-mul epilogue -> zp2 directly
        gemm_mma_k<128,128,64,32,3,1><<<dim3(8, NHG/128), 256, 98304>>>(
            xp2, whg2 + (size_t)l*NHG*UD, zp2, UF, 2*Dm);
        // ff out: [1024,1024], Ks=5632 — 256 CTAs
        gemm_mma_k<64,64,32,16,4,0><<<dim3(16, 16), 256, 65536>>>(
            zp2, wfo2 + (size_t)l*Dm*UF, obuf, Dm, 2*DFFP);
        resid_k<<<MT, 256>>>(x, obuf, ff_alpha + l*Dm, xp2);
    }
    // logits: [1024,32000]
    gemm_mma_k<128,128,64,32,3,0><<<dim3(8, NV/128), 256, 98304>>>(
        xp2, wl2, out, NV, 2*Dm);
}

// round 8
// speedup vs baseline: 4.5357x; 1.1675x over previous
#include <cuda_runtime.h>
#include <cuda_bf16.h>
#include <cuda_fp16.h>
#include <math.h>
#include <stdint.h>

#define Dm    1024
#define SEQn  512
#define NB    2
#define NH    16
#define DHd   64
#define DFFn  2730
#define DFFP  2816
#define NV    32000
#define NL    4
#define MT    1024
#define NQKV  3072
#define NHG   5632
#define UD    512     // uint32 per row for K=Dm fp16
#define UF    1408    // uint32 per row for K=DFFP fp16

// ---------------- fp32 scratch ----------------
__device__ float g_x[MT*Dm];
__device__ float g_qkv[MT*NQKV];
__device__ float g_obuf[MT*Dm];
__device__ float g_v0h[NB*NH*SEQn*DHd];
__device__ float g_fo[NL*Dm];
__device__ float g_fffo[NL*DFFn];

// ---------------- packed fp16 buffers (uint32 = 2 fp16 k-slots) ----------------
__device__ uint32_t g_xp2 [MT*UD];
__device__ uint32_t g_op2 [MT*UD];
__device__ uint32_t g_zp2 [MT*UF];
__device__ uint32_t g_wqkv2[(size_t)NL*NQKV*UD];
__device__ uint32_t g_wo2  [(size_t)NL*Dm*UD];
__device__ uint32_t g_whg2 [(size_t)NL*NHG*UD];
__device__ uint32_t g_wfo2 [(size_t)NL*Dm*UF];
__device__ uint32_t g_wl2  [(size_t)NV*UD];

// ---------------- scalar helpers ----------------
static __device__ __forceinline__ float l2fac(float n){
    float tgt = fminf(fmaxf(n, 1.0f - 1e-5f), 1.0f + 1e-5f);
    return 1.0f / fmaxf(n / tgt, 1e-10f);
}
static __device__ __forceinline__ float warpsum(float v){
    #pragma unroll
    for(int o=16;o>0;o>>=1) v += __shfl_xor_sync(0xffffffffu, v, o);
    return v;
}
static __device__ __forceinline__ float blocksum256(float v, float* red){
    red[threadIdx.x] = v; __syncthreads();
    for(int o=128;o>0;o>>=1){
        if(threadIdx.x < o) red[threadIdx.x] += red[threadIdx.x+o];
        __syncthreads();
    }
    float r = red[0]; __syncthreads();
    return r;
}
// pack two fp32 into one uint32 of fp16 pair
static __device__ __forceinline__ uint32_t packh2(float x0, float x1){
    return (uint32_t)__half_as_ushort(__float2half_rn(x0))
         | ((uint32_t)__half_as_ushort(__float2half_rn(x1))<<16);
}

// ---------------- cp.async / ldmatrix / mma primitives ----------------
static __device__ __forceinline__ void cp16(uint32_t saddr, const void* g){
    asm volatile("cp.async.cg.shared.global [%0], [%1], 16;" :: "r"(saddr), "l"(g) : "memory");
}
static __device__ __forceinline__ void cp_commit(){
    asm volatile("cp.async.commit_group;" ::: "memory");
}
template<int N> static __device__ __forceinline__ void cp_wait(){
    asm volatile("cp.async.wait_group %0;" :: "n"(N) : "memory");
}
static __device__ __forceinline__ void ldsm4(uint32_t* r, uint32_t a){
    asm volatile("ldmatrix.sync.aligned.m8n8.x4.shared.b16 {%0,%1,%2,%3}, [%4];"
        : "=r"(r[0]),"=r"(r[1]),"=r"(r[2]),"=r"(r[3]) : "r"(a));
}
static __device__ __forceinline__ void mma_f16(float* c,
        uint32_t a0, uint32_t a1, uint32_t a2, uint32_t a3, uint32_t b0, uint32_t b1){
    asm volatile("mma.sync.aligned.m16n8k16.row.col.f32.f16.f16.f32 "
                 "{%0,%1,%2,%3},{%4,%5,%6,%7},{%8,%9},{%0,%1,%2,%3};"
                 : "+f"(c[0]), "+f"(c[1]), "+f"(c[2]), "+f"(c[3])
                 : "r"(a0), "r"(a1), "r"(a2), "r"(a3), "r"(b0), "r"(b1));
}

// ---------------- multistage fp16 mma GEMM: C[M,N] = A @ B^T ----------------
// EPI 0: C fp32 (ldc = fp32 stride). EPI 1: adjacent col pairs (h,g);
// writes half(silu(g)*h) into __half C at pair index (ldc = half stride).
template<int BM,int BN,int WM,int WN,int S,int EPI>
__global__ void __launch_bounds__(256, ((BM+BN)*128*S <= 114688) ? 2 : 1)
gemm_mma_k(const uint32_t* __restrict__ Au, const uint32_t* __restrict__ Bu,
           void* __restrict__ Cv, int ldc, int Ks){
    constexpr int ABYTES = BM*128, STAGE = (BM+BN)*128;
    constexpr int WNW = BN/WN;
    constexpr int MI = WM/16, NJ = WN/8, NJ2 = NJ/2;
    constexpr int NLD = (BM+BN)/32;

    extern __shared__ char sm[];
    uint32_t smBase = (uint32_t)__cvta_generic_to_shared(sm);

    const int tid = threadIdx.x, warp = tid>>5, lane = tid&31;
    const int wm = warp / WNW, wn = warp % WNW;
    const int i8 = lane&7, sub = lane>>3;
    const int g = lane>>2, t4 = lane&3;
    const int rowBase = blockIdx.x*BM, colBase = blockIdx.y*BN;
    const char* Ab = (const char*)Au;
    const char* Bb = (const char*)Bu;
    const size_t Kb = (size_t)Ks*2;
    const int NC = Ks>>6;

    const int cA = sub>>1, cB = sub&1;
    uint32_t aRow[MI], bRow[NJ2];
    #pragma unroll
    for(int it=0;it<MI;it++)
        aRow[it] = smBase + (uint32_t)((wm*WM + it*16 + (sub&1)*8 + i8)*128);
    #pragma unroll
    for(int jp=0;jp<NJ2;jp++)
        bRow[jp] = smBase + (uint32_t)(ABYTES + (wn*WN + jp*16 + (sub>>1)*8 + i8)*128);

    float acc[MI][NJ][4];
    #pragma unroll
    for(int i=0;i<MI;i++)
        #pragma unroll
        for(int j=0;j<NJ;j++)
            #pragma unroll
            for(int e=0;e<4;e++) acc[i][j][e] = 0.0f;

    auto load_chunk = [&](int ck, int s){
        #pragma unroll
        for(int u=0;u<NLD;u++){
            int idx = tid + u*256;
            int isA = (idx < BM*8);
            int ii = isA ? idx : idx - BM*8;
            int r = ii>>3, c = ii&7;
            const char* gp = isA
                ? Ab + (size_t)(rowBase + r)*Kb + (size_t)ck*128 + c*16
                : Bb + (size_t)(colBase + r)*Kb + (size_t)ck*128 + c*16;
            uint32_t so = smBase + (uint32_t)(s*STAGE + (isA?0:ABYTES)
                        + r*128 + ((c ^ (r&7))<<4));
            cp16(so, gp);
        }
        cp_commit();
    };

    #pragma unroll
    for(int s=0;s<S-1;s++) load_chunk(s, s);

    for(int c=0;c<NC;c++){
        cp_wait<S-2>();
        __syncthreads();
        if(c+S-1 < NC) load_chunk(c+S-1, (c+S-1)%S);
        else cp_commit();

        const uint32_t bufOff = (uint32_t)((c%S)*STAGE);
        #pragma unroll
        for(int kk=0;kk<4;kk++){
            uint32_t ah[MI][4], bb[NJ2][4];
            #pragma unroll
            for(int it=0;it<MI;it++)
                ldsm4(ah[it], aRow[it] + bufOff + (uint32_t)((((2*kk + cA) ^ i8))<<4));
            #pragma unroll
            for(int jp=0;jp<NJ2;jp++)
                ldsm4(bb[jp], bRow[jp] + bufOff + (uint32_t)((((2*kk + cB) ^ i8))<<4));
            #pragma unroll
            for(int it=0;it<MI;it++)
                #pragma unroll
                for(int jt=0;jt<NJ;jt++){
                    const uint32_t* bf = bb[jt>>1];
                    int o = (jt&1)*2;
                    mma_f16(acc[it][jt], ah[it][0], ah[it][1], ah[it][2], ah[it][3],
                            bf[o], bf[o+1]);
                }
        }
    }

    if(EPI == 0){
        float* C = (float*)Cv;
        #pragma unroll
        for(int jt=0;jt<NJ;jt++){
            int c = colBase + wn*WN + jt*8 + t4*2;
            #pragma unroll
            for(int it=0;it<MI;it++){
                int r = rowBase + wm*WM + it*16 + g;
                *(float2*)(C + (size_t)r*ldc + c)     = make_float2(acc[it][jt][0], acc[it][jt][1]);
                *(float2*)(C + (size_t)(r+8)*ldc + c) = make_float2(acc[it][jt][2], acc[it][jt][3]);
            }
        }
    } else {
        __half* C = (__half*)Cv;
        #pragma unroll
        for(int jt=0;jt<NJ;jt++){
            int cpair = (colBase + wn*WN + jt*8 + t4*2) >> 1;
            #pragma unroll
            for(int it=0;it<MI;it++){
                int r = rowBase + wm*WM + it*16 + g;
                float h0 = acc[it][jt][0], g0 = acc[it][jt][1];
                float h1 = acc[it][jt][2], g1 = acc[it][jt][3];
                float z0 = g0/(1.0f + expf(-g0))*h0;
                float z1 = g1/(1.0f + expf(-g1))*h1;
                C[(size_t)r*ldc + cpair]     = __float2half_rn(z0);
                C[(size_t)(r+8)*ldc + cpair] = __float2half_rn(z1);
            }
        }
    }
}

// ---------------- column norms ----------------
__global__ void colnorm_k(const float* __restrict__ W, float* __restrict__ f, int R, int C){
    int l = blockIdx.y;
    int c = blockIdx.x*blockDim.x + threadIdx.x;
    if(c >= C) return;
    const float* Wl = W + (size_t)l*R*C;
    float s = 0.0f;
    for(int r=0;r<R;r++){ float w = Wl[(size_t)r*C + c]; s += w*w; }
    f[(size_t)l*C + c] = l2fac(sqrtf(s));
}

// ---------------- fused norm + pack kernels (single fp16 plane) ----------------
__global__ void wpack_qkv_k(const float* __restrict__ Wq, const float* __restrict__ Wk,
                            const float* __restrict__ Wv, uint32_t* __restrict__ dst){
    __shared__ float red[256];
    int rr = blockIdx.x;
    int l = rr / NQKV, r = rr % NQKV;
    int which = r >> 10, rl = r & 1023;
    const float* W = (which==0) ? Wq : (which==1) ? Wk : Wv;
    const float4* sp = (const float4*)(W + ((size_t)l*Dm + rl)*Dm);
    float4 v = sp[threadIdx.x];
    float s = v.x*v.x + v.y*v.y + v.z*v.z + v.w*v.w;
    s = blocksum256(s, red);
    float f = l2fac(sqrtf(s));
    uint32_t* dp = dst + (size_t)rr*UD + 2*threadIdx.x;
    dp[0] = packh2(v.x*f, v.y*f);
    dp[1] = packh2(v.z*f, v.w*f);
}
__global__ void wpack_o_k(const float* __restrict__ Wo, uint32_t* __restrict__ dst){
    int rr = blockIdx.x;
    const float4* sp = (const float4*)(Wo + (size_t)rr*Dm);
    float4 v = sp[threadIdx.x];
    uint32_t* dp = dst + (size_t)rr*UD + 2*threadIdx.x;
    dp[0] = packh2(v.x, v.y);
    dp[1] = packh2(v.z, v.w);
}
// interleaved h/g rows: dst row 2p = Wffh row p, dst row 2p+1 = Wffg row p
__global__ void wpack_hg_k(const float* __restrict__ Wffh, const float* __restrict__ Wffg,
                           const float* __restrict__ hsc, const float* __restrict__ gsc,
                           uint32_t* __restrict__ dst){
    __shared__ float red[256];
    int rr = blockIdx.x;
    int l = rr / NHG, r = rr % NHG;
    int p = r >> 1, isG = r & 1;
    uint32_t* dp0 = dst + (size_t)rr*UD;
    if(p >= DFFn){
        dp0[threadIdx.x] = 0u; dp0[threadIdx.x + 256] = 0u;
        return;
    }
    size_t sr = (size_t)l*DFFn + p;
    const float* W = isG ? (Wffg + sr*Dm) : (Wffh + sr*Dm);
    float sc = isG ? gsc[sr]*32.0f : hsc[sr];
    float4 v = ((const float4*)W)[threadIdx.x];
    float s = v.x*v.x + v.y*v.y + v.z*v.z + v.w*v.w;
    s = blocksum256(s, red);
    float f = l2fac(sqrtf(s))*sc;
    uint32_t* dp = dp0 + 2*threadIdx.x;
    dp[0] = packh2(v.x*f, v.y*f);
    dp[1] = packh2(v.z*f, v.w*f);
}
__global__ void wpack_fo_k(const float* __restrict__ Wffo, const float* __restrict__ fffo,
                           uint32_t* __restrict__ dst){
    int rr = blockIdx.x;
    int l = rr / Dm, rl = rr % Dm;
    const float2* sp = (const float2*)(Wffo + ((size_t)l*Dm + rl)*DFFn);
    const float* ks = fffo + (size_t)l*DFFn;
    uint32_t* dp = dst + (size_t)rr*UF;
    for(int j=threadIdx.x;j<UF;j+=256){
        float x0=0.0f, x1=0.0f;
        if(2*j < DFFn){ float2 vv = sp[j]; x0 = vv.x*ks[2*j]; x1 = vv.y*ks[2*j+1]; }
        dp[j] = packh2(x0, x1);
    }
}
__global__ void wpack_log_k(const float* __restrict__ Wl, const float* __restrict__ lsc,
                            uint32_t* __restrict__ dst){
    __shared__ float red[256];
    int r = blockIdx.x;
    const float4* sp = (const float4*)(Wl + (size_t)r*Dm);
    float4 v = sp[threadIdx.x];
    float s = v.x*v.x + v.y*v.y + v.z*v.z + v.w*v.w;
    s = blocksum256(s, red);
    float f = l2fac(sqrtf(s))*lsc[r]*32.0f;
    uint32_t* dp = dst + (size_t)r*UD + 2*threadIdx.x;
    dp[0] = packh2(v.x*f, v.y*f);
    dp[1] = packh2(v.z*f, v.w*f);
}

// ---------------- embedding ----------------
__global__ void embed_k(const int* __restrict__ ids, const float* __restrict__ W_emb,
                        float* __restrict__ x, uint32_t* __restrict__ xp2){
    __shared__ float red[256];
    int m = blockIdx.x, t = threadIdx.x;
    int tok = ids[m];
    const float2* row2 = (const float2*)(W_emb + (size_t)tok*Dm);
    float2 a = row2[t], b = row2[t+256];
    float s = a.x*a.x + a.y*a.y + b.x*b.x + b.y*b.y;
    s = blocksum256(s, red);
    float f = l2fac(sqrtf(s));
    a.x*=f; a.y*=f; b.x*=f; b.y*=f;
    float2* x2 = (float2*)(x + (size_t)m*Dm);
    x2[t] = a; x2[t+256] = b;
    uint32_t* dp = xp2 + (size_t)m*UD;
    dp[t]     = packh2(a.x, a.y);
    dp[t+256] = packh2(b.x, b.y);
}

// ---------------- fused attn-prep + delta rule ----------------
// block = (b,h); 128 threads. Normalizes q/k, computes beta, applies value
// residual while staging each 32-token chunk, then runs the recurrence.
#define DCH 32
__global__ void delta_k(const float* __restrict__ qkv, const float* __restrict__ qs_l,
                        const float* __restrict__ Wbeta, const float* __restrict__ bscale,
                        int l, int is_l0, float* __restrict__ v0h,
                        uint32_t* __restrict__ op2, const float* __restrict__ fWo){
    int bh = blockIdx.x;
    int b = bh / NH, h = bh % NH;
    int t = threadIdx.x;
    int warp = t>>5, lane = t&31;
    int col = t>>1, par = t&1;

    // normalized beta projection vector (per warp, lanes hold dims lane, lane+32)
    float wb0 = Wbeta[l*DHd + lane], wb1 = Wbeta[l*DHd + lane + 32];
    float wfac = l2fac(sqrtf(warpsum(wb0*wb0 + wb1*wb1))) * (bscale[l]*0.1f);
    float wbn0 = wb0*wfac, wbn1 = wb1*wfac;
    float qsc0 = qs_l[h*DHd + lane]*1024.0f, qsc1 = qs_l[h*DHd + lane + 32]*1024.0f;

    float St[32];
    #pragma unroll
    for(int i=0;i<32;i++) St[i] = 0.0f;

    __shared__ float ks[DCH*DHd];
    __shared__ float qs[DCH*DHd];
    __shared__ float vs[DCH*DHd];
    __shared__ float bs[DCH];

    float fo = fWo[h*DHd + col];

    for(int c0=0;c0<SEQn;c0+=DCH){
        __syncthreads();
        // stage + normalize: warp w handles tokens w, w+4, ..., w+28
        #pragma unroll
        for(int j=0;j<8;j++){
            int i = warp + 4*j;
            int m = b*SEQn + c0 + i;
            size_t src = (size_t)m*NQKV + h*DHd;
            float q0=qkv[src+lane],       q1=qkv[src+lane+32];
            float k0=qkv[src+Dm+lane],    k1=qkv[src+Dm+lane+32];
            float v0=qkv[src+2*Dm+lane],  v1=qkv[src+2*Dm+lane+32];
            float fq = l2fac(sqrtf(warpsum(q0*q0 + q1*q1)));
            float fk = l2fac(sqrtf(warpsum(k0*k0 + k1*k1)));
            float kn0 = k0*fk, kn1 = k1*fk;
            float bd = warpsum(kn0*wbn0 + kn1*wbn1);
            size_t vdst = ((size_t)bh*SEQn + c0 + i)*DHd;
            float vv0, vv1;
            if(is_l0){ vv0=v0; vv1=v1; v0h[vdst+lane]=v0; v0h[vdst+lane+32]=v1; }
            else     { vv0=0.5f*(v0 + v0h[vdst+lane]); vv1=0.5f*(v1 + v0h[vdst+lane+32]); }
            qs[i*DHd+lane] = q0*fq*qsc0;  qs[i*DHd+lane+32] = q1*fq*qsc1;
            ks[i*DHd+lane] = kn0;         ks[i*DHd+lane+32] = kn1;
            vs[i*DHd+lane] = vv0;         vs[i*DHd+lane+32] = vv1;
            if(lane==0) bs[i] = 1.0f/(1.0f + expf(-bd));
        }
        __syncthreads();
        for(int tt=0;tt<DCH;tt++){
            const float* kt = &ks[tt*DHd];
            const float* qt = &qs[tt*DHd];
            float p0=0,p1=0,p2=0,p3=0;
            #pragma unroll
            for(int j=0;j<32;j+=4){
                p0 += kt[2*j+par]*St[j];
                p1 += kt[2*(j+1)+par]*St[j+1];
                p2 += kt[2*(j+2)+par]*St[j+2];
                p3 += kt[2*(j+3)+par]*St[j+3];
            }
            float kS = (p0+p1)+(p2+p3);
            kS += __shfl_xor_sync(0xffffffffu, kS, 1);
            float dlt = bs[tt]*(vs[tt*DHd + col] - kS);
            float o0=0,o1=0,o2=0,o3=0;
            #pragma unroll
            for(int j=0;j<32;j+=4){
                St[j]   += kt[2*j+par]*dlt;     o0 += qt[2*j+par]*St[j];
                St[j+1] += kt[2*(j+1)+par]*dlt; o1 += qt[2*(j+1)+par]*St[j+1];
                St[j+2] += kt[2*(j+2)+par]*dlt; o2 += qt[2*(j+2)+par]*St[j+2];
                St[j+3] += kt[2*(j+3)+par]*dlt; o3 += qt[2*(j+3)+par]*St[j+3];
            }
            float o = (o0+o1)+(o2+o3);
            o += __shfl_xor_sync(0xffffffffu, o, 1);
            o *= fo;
            float oN = __shfl_down_sync(0xffffffffu, o, 2);
            if((t & 3) == 0){
                op2[(size_t)(b*SEQn + c0 + tt)*UD + h*32 + (col>>1)] = packh2(o, oN);
            }
        }
    }
}

// ---------------- residual ----------------
__global__ void resid_k(float* __restrict__ x, const float* __restrict__ o,
                        const float* __restrict__ alpha, uint32_t* __restrict__ xp2){
    __shared__ float red[256];
    int m = blockIdx.x, t = threadIdx.x;
    const float2* o2 = (const float2*)(o + (size_t)m*Dm);
    float2 oa = o2[t], ob = o2[t+256];
    float s = oa.x*oa.x + oa.y*oa.y + ob.x*ob.x + ob.y*ob.y;
    s = blocksum256(s, red);
    float fh = l2fac(sqrtf(s));
    float2* x2 = (float2*)(x + (size_t)m*Dm);
    float2 xa = x2[t], xb = x2[t+256];
    const float2* al2 = (const float2*)alpha;
    float2 aa = al2[t], ab = al2[t+256];
    float ya0 = xa.x + aa.x*8.0f*(oa.x*fh - xa.x);
    float ya1 = xa.y + aa.y*8.0f*(oa.y*fh - xa.y);
    float yb0 = xb.x + ab.x*8.0f*(ob.x*fh - xb.x);
    float yb1 = xb.y + ab.y*8.0f*(ob.y*fh - xb.y);
    float s2 = ya0*ya0 + ya1*ya1 + yb0*yb0 + yb1*yb1;
    s2 = blocksum256(s2, red);
    float f2 = l2fac(sqrtf(s2));
    ya0*=f2; ya1*=f2; yb0*=f2; yb1*=f2;
    x2[t]     = make_float2(ya0, ya1);
    x2[t+256] = make_float2(yb0, yb1);
    uint32_t* dp = xp2 + (size_t)m*UD;
    dp[t]     = packh2(ya0, ya1);
    dp[t+256] = packh2(yb0, yb1);
}

// ---------------- host ----------------
template<typename T> static void* symaddr(T& s){
    void* p = nullptr; cudaGetSymbolAddress(&p, s); return p;
}

extern "C" void kernel_launch(void* const* d_in, const int* in_sizes, int n_in,
                              void* d_out, int out_size){
    (void)in_sizes; (void)n_in; (void)out_size;
    const int*   ids        = (const int*)  d_in[0];
    const float* W_emb      = (const float*)d_in[2];
    const float* Wq         = (const float*)d_in[3];
    const float* Wk         = (const float*)d_in[4];
    const float* Wv         = (const float*)d_in[5];
    const float* Wbeta      = (const float*)d_in[6];
    const float* Wo         = (const float*)d_in[7];
    const float* Wffh       = (const float*)d_in[8];
    const float* Wffg       = (const float*)d_in[9];
    const float* Wffo       = (const float*)d_in[10];
    const float* qk_scale   = (const float*)d_in[11];
    const float* beta_scale = (const float*)d_in[12];
    const float* attn_alpha = (const float*)d_in[13];
    const float* ff_alpha   = (const float*)d_in[14];
    const float* ffh_scale  = (const float*)d_in[15];
    const float* ffg_scale  = (const float*)d_in[16];
    const float* W_logits   = (const float*)d_in[17];
    const float* logit_scale= (const float*)d_in[18];
    float* out = (float*)d_out;

    float* x     = (float*)symaddr(g_x);
    float* qkv   = (float*)symaddr(g_qkv);
    float* obuf  = (float*)symaddr(g_obuf);
    float* v0h   = (float*)symaddr(g_v0h);
    float* fo    = (float*)symaddr(g_fo);
    float* fffo  = (float*)symaddr(g_fffo);
    uint32_t* xp2   = (uint32_t*)symaddr(g_xp2);
    uint32_t* op2   = (uint32_t*)symaddr(g_op2);
    uint32_t* zp2   = (uint32_t*)symaddr(g_zp2);
    uint32_t* wqkv2 = (uint32_t*)symaddr(g_wqkv2);
    uint32_t* wo2   = (uint32_t*)symaddr(g_wo2);
    uint32_t* whg2  = (uint32_t*)symaddr(g_whg2);
    uint32_t* wfo2  = (uint32_t*)symaddr(g_wfo2);
    uint32_t* wl2   = (uint32_t*)symaddr(g_wl2);

    cudaFuncSetAttribute(gemm_mma_k<128,128,64,32,3,0>, cudaFuncAttributeMaxDynamicSharedMemorySize, 98304);
    cudaFuncSetAttribute(gemm_mma_k<128,64,32,32,3,1>,  cudaFuncAttributeMaxDynamicSharedMemorySize, 73728);
    cudaFuncSetAttribute(gemm_mma_k<64,64,32,16,4,0>,   cudaFuncAttributeMaxDynamicSharedMemorySize, 65536);

    // column norms (consumed by delta epilogue / wpack_fo)
    colnorm_k<<<dim3((Dm+255)/256,   NL), 256>>>(Wo,   fo,   Dm, Dm);
    colnorm_k<<<dim3((DFFn+255)/256, NL), 256>>>(Wffo, fffo, Dm, DFFn);

    // fused norm+pack (weights read once)
    wpack_qkv_k<<<NL*NQKV, 256>>>(Wq, Wk, Wv, wqkv2);
    wpack_o_k<<<NL*Dm, 256>>>(Wo, wo2);
    wpack_hg_k<<<NL*NHG, 256>>>(Wffh, Wffg, ffh_scale, ffg_scale, whg2);
    wpack_fo_k<<<NL*Dm, 256>>>(Wffo, fffo, wfo2);
    wpack_log_k<<<NV, 256>>>(W_logits, logit_scale, wl2);

    embed_k<<<MT, 256>>>(ids, W_emb, x, xp2);

    for(int l=0;l<NL;l++){
        // fused qkv: [1024,3072], Ks=1024
        gemm_mma_k<128,128,64,32,3,0><<<dim3(8, NQKV/128), 256, 98304>>>(
            xp2, wqkv2 + (size_t)l*NQKV*UD, qkv, NQKV, Dm);
        // fused prep + delta recurrence
        delta_k<<<NB*NH, 128>>>(qkv, qk_scale + l*Dm, Wbeta, beta_scale, l,
                                (l==0)?1:0, v0h, op2, fo + l*Dm);
        // o projection: [1024,1024]
        gemm_mma_k<64,64,32,16,4,0><<<dim3(16, 16), 256, 65536>>>(
            op2, wo2 + (size_t)l*Dm*UD, obuf, Dm, Dm);
        resid_k<<<MT, 256>>>(x, obuf, attn_alpha + l*Dm, xp2);
        // fused ff hidden|gate with silu-mul epilogue -> zp2 (fp16)
        gemm_mma_k<128,64,32,32,3,1><<<dim3(8, NHG/64), 256, 73728>>>(
            xp2, whg2 + (size_t)l*NHG*UD, zp2, DFFP, Dm);
        // ff out: [1024,1024], Ks=2816
        gemm_mma_k<64,64,32,16,4,0><<<dim3(16, 16), 256, 65536>>>(
            zp2, wfo2 + (size_t)l*Dm*UF, obuf, Dm, DFFP);
        resid_k<<<MT, 256>>>(x, obuf, ff_alpha + l*Dm, xp2);
    }
    // logits: [1024,32000], Ks=1024
    gemm_mma_k<128,128,64,32,3,0><<<dim3(8, NV/128), 256, 98304>>>(
        xp2, wl2, out, NV, Dm);
}

// round 9
// speedup vs baseline: 4.5666x; 1.0068x over previous
#include <cuda_runtime.h>
#include <cuda_bf16.h>
#include <cuda_fp16.h>
#include <math.h>
#include <stdint.h>

#define Dm    1024
#define SEQn  512
#define NB    2
#define NH    16
#define DHd   64
#define DFFn  2730
#define DFFP  2816
#define NV    32000
#define NL    4
#define MT    1024
#define NQKV  3072
#define NHG   5632
#define UD    512     // uint32 per row for K=Dm fp16
#define UF    1408    // uint32 per row for K=DFFP fp16

// ---------------- fp32 scratch ----------------
__device__ float g_x[MT*Dm];
__device__ float g_qkv[MT*NQKV];
__device__ float g_obuf[MT*Dm];
__device__ float g_v0h[NB*NH*SEQn*DHd];
__device__ float g_fo[NL*Dm];
__device__ float g_fffo[NL*DFFn];

// ---------------- packed fp16 buffers (uint32 = 2 fp16 k-slots) ----------------
__device__ uint32_t g_xp2 [MT*UD];
__device__ uint32_t g_op2 [MT*UD];
__device__ uint32_t g_zp2 [MT*UF];
__device__ uint32_t g_wqkv2[(size_t)NL*NQKV*UD];
__device__ uint32_t g_wo2  [(size_t)NL*Dm*UD];
__device__ uint32_t g_whg2 [(size_t)NL*NHG*UD];
__device__ uint32_t g_wfo2 [(size_t)NL*Dm*UF];
__device__ uint32_t g_wl2  [(size_t)NV*UD];

// ---------------- scalar helpers ----------------
static __device__ __forceinline__ float l2fac(float n){
    float tgt = fminf(fmaxf(n, 1.0f - 1e-5f), 1.0f + 1e-5f);
    return 1.0f / fmaxf(n / tgt, 1e-10f);
}
static __device__ __forceinline__ float warpsum(float v){
    #pragma unroll
    for(int o=16;o>0;o>>=1) v += __shfl_xor_sync(0xffffffffu, v, o);
    return v;
}
static __device__ __forceinline__ float blocksum256(float v, float* red){
    red[threadIdx.x] = v; __syncthreads();
    for(int o=128;o>0;o>>=1){
        if(threadIdx.x < o) red[threadIdx.x] += red[threadIdx.x+o];
        __syncthreads();
    }
    float r = red[0]; __syncthreads();
    return r;
}
static __device__ __forceinline__ uint32_t packh2(float x0, float x1){
    return (uint32_t)__half_as_ushort(__float2half_rn(x0))
         | ((uint32_t)__half_as_ushort(__float2half_rn(x1))<<16);
}

// ---------------- cp.async / ldmatrix / mma primitives ----------------
static __device__ __forceinline__ void cp16(uint32_t saddr, const void* g){
    asm volatile("cp.async.cg.shared.global [%0], [%1], 16;" :: "r"(saddr), "l"(g) : "memory");
}
static __device__ __forceinline__ void cp_commit(){
    asm volatile("cp.async.commit_group;" ::: "memory");
}
template<int N> static __device__ __forceinline__ void cp_wait(){
    asm volatile("cp.async.wait_group %0;" :: "n"(N) : "memory");
}
static __device__ __forceinline__ void ldsm4(uint32_t* r, uint32_t a){
    asm volatile("ldmatrix.sync.aligned.m8n8.x4.shared.b16 {%0,%1,%2,%3}, [%4];"
        : "=r"(r[0]),"=r"(r[1]),"=r"(r[2]),"=r"(r[3]) : "r"(a));
}
static __device__ __forceinline__ void mma_f16(float* c,
        uint32_t a0, uint32_t a1, uint32_t a2, uint32_t a3, uint32_t b0, uint32_t b1){
    asm volatile("mma.sync.aligned.m16n8k16.row.col.f32.f16.f16.f32 "
                 "{%0,%1,%2,%3},{%4,%5,%6,%7},{%8,%9},{%0,%1,%2,%3};"
                 : "+f"(c[0]), "+f"(c[1]), "+f"(c[2]), "+f"(c[3])
                 : "r"(a0), "r"(a1), "r"(a2), "r"(a3), "r"(b0), "r"(b1));
}

// ---------------- multistage fp16 mma GEMM: C[M,N] = A @ B^T ----------------
// Fragment ping-pong: kk+1's ldmatrix issues before kk's mmas so HMMA covers LDS latency.
// EPI 0: C fp32. EPI 1: adjacent col pairs (h,g) -> half(silu(g)*h), ldc = half stride.
template<int BM,int BN,int WM,int WN,int S,int EPI>
__global__ void __launch_bounds__(256, ((BM+BN)*128*S <= 114688) ? 2 : 1)
gemm_mma_k(const uint32_t* __restrict__ Au, const uint32_t* __restrict__ Bu,
           void* __restrict__ Cv, int ldc, int Ks){
    constexpr int ABYTES = BM*128, STAGE = (BM+BN)*128;
    constexpr int WNW = BN/WN;
    constexpr int MI = WM/16, NJ = WN/8, NJ2 = NJ/2;
    constexpr int NLD = (BM+BN)/32;

    extern __shared__ char sm[];
    uint32_t smBase = (uint32_t)__cvta_generic_to_shared(sm);

    const int tid = threadIdx.x, warp = tid>>5, lane = tid&31;
    const int wm = warp / WNW, wn = warp % WNW;
    const int i8 = lane&7, sub = lane>>3;
    const int g = lane>>2, t4 = lane&3;
    const int rowBase = blockIdx.x*BM, colBase = blockIdx.y*BN;
    const char* Ab = (const char*)Au;
    const char* Bb = (const char*)Bu;
    const size_t Kb = (size_t)Ks*2;
    const int NC = Ks>>6;

    const int cA = sub>>1, cB = sub&1;
    uint32_t aRow[MI], bRow[NJ2];
    #pragma unroll
    for(int it=0;it<MI;it++)
        aRow[it] = smBase + (uint32_t)((wm*WM + it*16 + (sub&1)*8 + i8)*128);
    #pragma unroll
    for(int jp=0;jp<NJ2;jp++)
        bRow[jp] = smBase + (uint32_t)(ABYTES + (wn*WN + jp*16 + (sub>>1)*8 + i8)*128);

    float acc[MI][NJ][4];
    #pragma unroll
    for(int i=0;i<MI;i++)
        #pragma unroll
        for(int j=0;j<NJ;j++)
            #pragma unroll
            for(int e=0;e<4;e++) acc[i][j][e] = 0.0f;

    auto load_chunk = [&](int ck, int s){
        #pragma unroll
        for(int u=0;u<NLD;u++){
            int idx = tid + u*256;
            int isA = (idx < BM*8);
            int ii = isA ? idx : idx - BM*8;
            int r = ii>>3, c = ii&7;
            const char* gp = isA
                ? Ab + (size_t)(rowBase + r)*Kb + (size_t)ck*128 + c*16
                : Bb + (size_t)(colBase + r)*Kb + (size_t)ck*128 + c*16;
            uint32_t so = smBase + (uint32_t)(s*STAGE + (isA?0:ABYTES)
                        + r*128 + ((c ^ (r&7))<<4));
            cp16(so, gp);
        }
        cp_commit();
    };

    #pragma unroll
    for(int s=0;s<S-1;s++) load_chunk(s, s);

    uint32_t ahB[2][MI][4], bbB[2][NJ2][4];

    for(int c=0;c<NC;c++){
        cp_wait<S-2>();
        __syncthreads();
        if(c+S-1 < NC) load_chunk(c+S-1, (c+S-1)%S);
        else cp_commit();

        const uint32_t bufOff = (uint32_t)((c%S)*STAGE);

        // fragment loader for k-step kk into buffer slot p
        #define LD_FRAG(kk, p) do{                                                   \
            _Pragma("unroll")                                                        \
            for(int it_=0;it_<MI;it_++)                                              \
                ldsm4(ahB[p][it_], aRow[it_] + bufOff + (uint32_t)((((2*(kk) + cA) ^ i8))<<4)); \
            _Pragma("unroll")                                                        \
            for(int jp_=0;jp_<NJ2;jp_++)                                             \
                ldsm4(bbB[p][jp_], bRow[jp_] + bufOff + (uint32_t)((((2*(kk) + cB) ^ i8))<<4)); \
        }while(0)

        LD_FRAG(0, 0);
        #pragma unroll
        for(int kk=0;kk<4;kk++){
            const int cur = kk&1;
            if(kk<3) LD_FRAG(kk+1, cur^1);
            #pragma unroll
            for(int it=0;it<MI;it++)
                #pragma unroll
                for(int jt=0;jt<NJ;jt++){
                    const uint32_t* bf = bbB[cur][jt>>1];
                    int o = (jt&1)*2;
                    mma_f16(acc[it][jt], ahB[cur][it][0], ahB[cur][it][1],
                            ahB[cur][it][2], ahB[cur][it][3], bf[o], bf[o+1]);
                }
        }
        #undef LD_FRAG
    }

    if(EPI == 0){
        float* C = (float*)Cv;
        #pragma unroll
        for(int jt=0;jt<NJ;jt++){
            int c = colBase + wn*WN + jt*8 + t4*2;
            #pragma unroll
            for(int it=0;it<MI;it++){
                int r = rowBase + wm*WM + it*16 + g;
                *(float2*)(C + (size_t)r*ldc + c)     = make_float2(acc[it][jt][0], acc[it][jt][1]);
                *(float2*)(C + (size_t)(r+8)*ldc + c) = make_float2(acc[it][jt][2], acc[it][jt][3]);
            }
        }
    } else {
        __half* C = (__half*)Cv;
        #pragma unroll
        for(int jt=0;jt<NJ;jt++){
            int cpair = (colBase + wn*WN + jt*8 + t4*2) >> 1;
            #pragma unroll
            for(int it=0;it<MI;it++){
                int r = rowBase + wm*WM + it*16 + g;
                float h0 = acc[it][jt][0], g0 = acc[it][jt][1];
                float h1 = acc[it][jt][2], g1 = acc[it][jt][3];
                float z0 = g0/(1.0f + __expf(-g0))*h0;
                float z1 = g1/(1.0f + __expf(-g1))*h1;
                C[(size_t)r*ldc + cpair]     = __float2half_rn(z0);
                C[(size_t)(r+8)*ldc + cpair] = __float2half_rn(z1);
            }
        }
    }
}

// ---------------- column norms ----------------
__global__ void colnorm_k(const float* __restrict__ W, float* __restrict__ f, int R, int C){
    int l = blockIdx.y;
    int c = blockIdx.x*blockDim.x + threadIdx.x;
    if(c >= C) return;
    const float* Wl = W + (size_t)l*R*C;
    float s = 0.0f;
    for(int r=0;r<R;r++){ float w = Wl[(size_t)r*C + c]; s += w*w; }
    f[(size_t)l*C + c] = l2fac(sqrtf(s));
}

// ---------------- fused norm + pack kernels (single fp16 plane) ----------------
__global__ void wpack_qkv_k(const float* __restrict__ Wq, const float* __restrict__ Wk,
                            const float* __restrict__ Wv, uint32_t* __restrict__ dst){
    __shared__ float red[256];
    int rr = blockIdx.x;
    int l = rr / NQKV, r = rr % NQKV;
    int which = r >> 10, rl = r & 1023;
    const float* W = (which==0) ? Wq : (which==1) ? Wk : Wv;
    const float4* sp = (const float4*)(W + ((size_t)l*Dm + rl)*Dm);
    float4 v = sp[threadIdx.x];
    float s = v.x*v.x + v.y*v.y + v.z*v.z + v.w*v.w;
    s = blocksum256(s, red);
    float f = l2fac(sqrtf(s));
    uint32_t* dp = dst + (size_t)rr*UD + 2*threadIdx.x;
    dp[0] = packh2(v.x*f, v.y*f);
    dp[1] = packh2(v.z*f, v.w*f);
}
__global__ void wpack_o_k(const float* __restrict__ Wo, uint32_t* __restrict__ dst){
    int rr = blockIdx.x;
    const float4* sp = (const float4*)(Wo + (size_t)rr*Dm);
    float4 v = sp[threadIdx.x];
    uint32_t* dp = dst + (size_t)rr*UD + 2*threadIdx.x;
    dp[0] = packh2(v.x, v.y);
    dp[1] = packh2(v.z, v.w);
}
// interleaved h/g rows: dst row 2p = Wffh row p, dst row 2p+1 = Wffg row p
__global__ void wpack_hg_k(const float* __restrict__ Wffh, const float* __restrict__ Wffg,
                           const float* __restrict__ hsc, const float* __restrict__ gsc,
                           uint32_t* __restrict__ dst){
    __shared__ float red[256];
    int rr = blockIdx.x;
    int l = rr / NHG, r = rr % NHG;
    int p = r >> 1, isG = r & 1;
    uint32_t* dp0 = dst + (size_t)rr*UD;
    if(p >= DFFn){
        dp0[threadIdx.x] = 0u; dp0[threadIdx.x + 256] = 0u;
        return;
    }
    size_t sr = (size_t)l*DFFn + p;
    const float* W = isG ? (Wffg + sr*Dm) : (Wffh + sr*Dm);
    float sc = isG ? gsc[sr]*32.0f : hsc[sr];
    float4 v = ((const float4*)W)[threadIdx.x];
    float s = v.x*v.x + v.y*v.y + v.z*v.z + v.w*v.w;
    s = blocksum256(s, red);
    float f = l2fac(sqrtf(s))*sc;
    uint32_t* dp = dp0 + 2*threadIdx.x;
    dp[0] = packh2(v.x*f, v.y*f);
    dp[1] = packh2(v.z*f, v.w*f);
}
__global__ void wpack_fo_k(const float* __restrict__ Wffo, const float* __restrict__ fffo,
                           uint32_t* __restrict__ dst){
    int rr = blockIdx.x;
    int l = rr / Dm, rl = rr % Dm;
    const float2* sp = (const float2*)(Wffo + ((size_t)l*Dm + rl)*DFFn);
    const float* ks = fffo + (size_t)l*DFFn;
    uint32_t* dp = dst + (size_t)rr*UF;
    for(int j=threadIdx.x;j<UF;j+=256){
        float x0=0.0f, x1=0.0f;
        if(2*j < DFFn){ float2 vv = sp[j]; x0 = vv.x*ks[2*j]; x1 = vv.y*ks[2*j+1]; }
        dp[j] = packh2(x0, x1);
    }
}
__global__ void wpack_log_k(const float* __restrict__ Wl, const float* __restrict__ lsc,
                            uint32_t* __restrict__ dst){
    __shared__ float red[256];
    int r = blockIdx.x;
    const float4* sp = (const float4*)(Wl + (size_t)r*Dm);
    float4 v = sp[threadIdx.x];
    float s = v.x*v.x + v.y*v.y + v.z*v.z + v.w*v.w;
    s = blocksum256(s, red);
    float f = l2fac(sqrtf(s))*lsc[r]*32.0f;
    uint32_t* dp = dst + (size_t)r*UD + 2*threadIdx.x;
    dp[0] = packh2(v.x*f, v.y*f);
    dp[1] = packh2(v.z*f, v.w*f);
}

// ---------------- embedding ----------------
__global__ void embed_k(const int* __restrict__ ids, const float* __restrict__ W_emb,
                        float* __restrict__ x, uint32_t* __restrict__ xp2){
    __shared__ float red[256];
    int m = blockIdx.x, t = threadIdx.x;
    int tok = ids[m];
    const float2* row2 = (const float2*)(W_emb + (size_t)tok*Dm);
    float2 a = row2[t], b = row2[t+256];
    float s = a.x*a.x + a.y*a.y + b.x*b.x + b.y*b.y;
    s = blocksum256(s, red);
    float f = l2fac(sqrtf(s));
    a.x*=f; a.y*=f; b.x*=f; b.y*=f;
    float2* x2 = (float2*)(x + (size_t)m*Dm);
    x2[t] = a; x2[t+256] = b;
    uint32_t* dp = xp2 + (size_t)m*UD;
    dp[t]     = packh2(a.x, a.y);
    dp[t+256] = packh2(b.x, b.y);
}

// ---------------- fused attn-prep + delta rule ----------------
#define DCH 32
__global__ void delta_k(const float* __restrict__ qkv, const float* __restrict__ qs_l,
                        const float* __restrict__ Wbeta, const float* __restrict__ bscale,
                        int l, int is_l0, float* __restrict__ v0h,
                        uint32_t* __restrict__ op2, const float* __restrict__ fWo){
    int bh = blockIdx.x;
    int b = bh / NH, h = bh % NH;
    int t = threadIdx.x;
    int warp = t>>5, lane = t&31;
    int col = t>>1, par = t&1;

    float wb0 = Wbeta[l*DHd + lane], wb1 = Wbeta[l*DHd + lane + 32];
    float wfac = l2fac(sqrtf(warpsum(wb0*wb0 + wb1*wb1))) * (bscale[l]*0.1f);
    float wbn0 = wb0*wfac, wbn1 = wb1*wfac;
    float qsc0 = qs_l[h*DHd + lane]*1024.0f, qsc1 = qs_l[h*DHd + lane + 32]*1024.0f;

    float St[32];
    #pragma unroll
    for(int i=0;i<32;i++) St[i] = 0.0f;

    __shared__ float ks[DCH*DHd];
    __shared__ float qs[DCH*DHd];
    __shared__ float vs[DCH*DHd];
    __shared__ float bs[DCH];

    float fo = fWo[h*DHd + col];

    for(int c0=0;c0<SEQn;c0+=DCH){
        __syncthreads();
        #pragma unroll
        for(int j=0;j<8;j++){
            int i = warp + 4*j;
            int m = b*SEQn + c0 + i;
            size_t src = (size_t)m*NQKV + h*DHd;
            float q0=qkv[src+lane],       q1=qkv[src+lane+32];
            float k0=qkv[src+Dm+lane],    k1=qkv[src+Dm+lane+32];
            float v0=qkv[src+2*Dm+lane],  v1=qkv[src+2*Dm+lane+32];
            float fq = l2fac(sqrtf(warpsum(q0*q0 + q1*q1)));
            float fk = l2fac(sqrtf(warpsum(k0*k0 + k1*k1)));
            float kn0 = k0*fk, kn1 = k1*fk;
            float bd = warpsum(kn0*wbn0 + kn1*wbn1);
            size_t vdst = ((size_t)bh*SEQn + c0 + i)*DHd;
            float vv0, vv1;
            if(is_l0){ vv0=v0; vv1=v1; v0h[vdst+lane]=v0; v0h[vdst+lane+32]=v1; }
            else     { vv0=0.5f*(v0 + v0h[vdst+lane]); vv1=0.5f*(v1 + v0h[vdst+lane+32]); }
            qs[i*DHd+lane] = q0*fq*qsc0;  qs[i*DHd+lane+32] = q1*fq*qsc1;
            ks[i*DHd+lane] = kn0;         ks[i*DHd+lane+32] = kn1;
            vs[i*DHd+lane] = vv0;         vs[i*DHd+lane+32] = vv1;
            if(lane==0) bs[i] = 1.0f/(1.0f + __expf(-bd));
        }
        __syncthreads();
        for(int tt=0;tt<DCH;tt++){
            const float* kt = &ks[tt*DHd];
            const float* qt = &qs[tt*DHd];
            float p0=0,p1=0,p2=0,p3=0;
            #pragma unroll
            for(int j=0;j<32;j+=4){
                p0 += kt[2*j+par]*St[j];
                p1 += kt[2*(j+1)+par]*St[j+1];
                p2 += kt[2*(j+2)+par]*St[j+2];
                p3 += kt[2*(j+3)+par]*St[j+3];
            }
            float kS = (p0+p1)+(p2+p3);
            kS += __shfl_xor_sync(0xffffffffu, kS, 1);
            float dlt = bs[tt]*(vs[tt*DHd + col] - kS);
            float o0=0,o1=0,o2=0,o3=0;
            #pragma unroll
            for(int j=0;j<32;j+=4){
                St[j]   += kt[2*j+par]*dlt;     o0 += qt[2*j+par]*St[j];
                St[j+1] += kt[2*(j+1)+par]*dlt; o1 += qt[2*(j+1)+par]*St[j+1];
                St[j+2] += kt[2*(j+2)+par]*dlt; o2 += qt[2*(j+2)+par]*St[j+2];
                St[j+3] += kt[2*(j+3)+par]*dlt; o3 += qt[2*(j+3)+par]*St[j+3];
            }
            float o = (o0+o1)+(o2+o3);
            o += __shfl_xor_sync(0xffffffffu, o, 1);
            o *= fo;
            float oN = __shfl_down_sync(0xffffffffu, o, 2);
            if((t & 3) == 0){
                op2[(size_t)(b*SEQn + c0 + tt)*UD + h*32 + (col>>1)] = packh2(o, oN);
            }
        }
    }
}

// ---------------- residual ----------------
__global__ void resid_k(float* __restrict__ x, const float* __restrict__ o,
                        const float* __restrict__ alpha, uint32_t* __restrict__ xp2){
    __shared__ float red[256];
    int m = blockIdx.x, t = threadIdx.x;
    const float2* o2 = (const float2*)(o + (size_t)m*Dm);
    float2 oa = o2[t], ob = o2[t+256];
    float s = oa.x*oa.x + oa.y*oa.y + ob.x*ob.x + ob.y*ob.y;
    s = blocksum256(s, red);
    float fh = l2fac(sqrtf(s));
    float2* x2 = (float2*)(x + (size_t)m*Dm);
    float2 xa = x2[t], xb = x2[t+256];
    const float2* al2 = (const float2*)alpha;
    float2 aa = al2[t], ab = al2[t+256];
    float ya0 = xa.x + aa.x*8.0f*(oa.x*fh - xa.x);
    float ya1 = xa.y + aa.y*8.0f*(oa.y*fh - xa.y);
    float yb0 = xb.x + ab.x*8.0f*(ob.x*fh - xb.x);
    float yb1 = xb.y + ab.y*8.0f*(ob.y*fh - xb.y);
    float s2 = ya0*ya0 + ya1*ya1 + yb0*yb0 + yb1*yb1;
    s2 = blocksum256(s2, red);
    float f2 = l2fac(sqrtf(s2));
    ya0*=f2; ya1*=f2; yb0*=f2; yb1*=f2;
    x2[t]     = make_float2(ya0, ya1);
    x2[t+256] = make_float2(yb0, yb1);
    uint32_t* dp = xp2 + (size_t)m*UD;
    dp[t]     = packh2(ya0, ya1);
    dp[t+256] = packh2(yb0, yb1);
}

// ---------------- host ----------------
template<typename T> static void* symaddr(T& s){
    void* p = nullptr; cudaGetSymbolAddress(&p, s); return p;
}

extern "C" void kernel_launch(void* const* d_in, const int* in_sizes, int n_in,
                              void* d_out, int out_size){
    (void)in_sizes; (void)n_in; (void)out_size;
    const int*   ids        = (const int*)  d_in[0];
    const float* W_emb      = (const float*)d_in[2];
    const float* Wq         = (const float*)d_in[3];
    const float* Wk         = (const float*)d_in[4];
    const float* Wv         = (const float*)d_in[5];
    const float* Wbeta      = (const float*)d_in[6];
    const float* Wo         = (const float*)d_in[7];
    const float* Wffh       = (const float*)d_in[8];
    const float* Wffg       = (const float*)d_in[9];
    const float* Wffo       = (const float*)d_in[10];
    const float* qk_scale   = (const float*)d_in[11];
    const float* beta_scale = (const float*)d_in[12];
    const float* attn_alpha = (const float*)d_in[13];
    const float* ff_alpha   = (const float*)d_in[14];
    const float* ffh_scale  = (const float*)d_in[15];
    const float* ffg_scale  = (const float*)d_in[16];
    const float* W_logits   = (const float*)d_in[17];
    const float* logit_scale= (const float*)d_in[18];
    float* out = (float*)d_out;

    float* x     = (float*)symaddr(g_x);
    float* qkv   = (float*)symaddr(g_qkv);
    float* obuf  = (float*)symaddr(g_obuf);
    float* v0h   = (float*)symaddr(g_v0h);
    float* fo    = (float*)symaddr(g_fo);
    float* fffo  = (float*)symaddr(g_fffo);
    uint32_t* xp2   = (uint32_t*)symaddr(g_xp2);
    uint32_t* op2   = (uint32_t*)symaddr(g_op2);
    uint32_t* zp2   = (uint32_t*)symaddr(g_zp2);
    uint32_t* wqkv2 = (uint32_t*)symaddr(g_wqkv2);
    uint32_t* wo2   = (uint32_t*)symaddr(g_wo2);
    uint32_t* whg2  = (uint32_t*)symaddr(g_whg2);
    uint32_t* wfo2  = (uint32_t*)symaddr(g_wfo2);
    uint32_t* wl2   = (uint32_t*)symaddr(g_wl2);

    cudaFuncSetAttribute(gemm_mma_k<128,128,64,32,3,0>, cudaFuncAttributeMaxDynamicSharedMemorySize, 98304);
    cudaFuncSetAttribute(gemm_mma_k<128,64,32,32,3,1>,  cudaFuncAttributeMaxDynamicSharedMemorySize, 73728);
    cudaFuncSetAttribute(gemm_mma_k<64,64,32,16,4,0>,   cudaFuncAttributeMaxDynamicSharedMemorySize, 65536);

    colnorm_k<<<dim3((Dm+255)/256,   NL), 256>>>(Wo,   fo,   Dm, Dm);
    colnorm_k<<<dim3((DFFn+255)/256, NL), 256>>>(Wffo, fffo, Dm, DFFn);

    wpack_qkv_k<<<NL*NQKV, 256>>>(Wq, Wk, Wv, wqkv2);
    wpack_o_k<<<NL*Dm, 256>>>(Wo, wo2);
    wpack_hg_k<<<NL*NHG, 256>>>(Wffh, Wffg, ffh_scale, ffg_scale, whg2);
    wpack_fo_k<<<NL*Dm, 256>>>(Wffo, fffo, wfo2);
    wpack_log_k<<<NV, 256>>>(W_logits, logit_scale, wl2);

    embed_k<<<MT, 256>>>(ids, W_emb, x, xp2);

    for(int l=0;l<NL;l++){
        gemm_mma_k<128,128,64,32,3,0><<<dim3(8, NQKV/128), 256, 98304>>>(
            xp2, wqkv2 + (size_t)l*NQKV*UD, qkv, NQKV, Dm);
        delta_k<<<NB*NH, 128>>>(qkv, qk_scale + l*Dm, Wbeta, beta_scale, l,
                                (l==0)?1:0, v0h, op2, fo + l*Dm);
        gemm_mma_k<64,64,32,16,4,0><<<dim3(16, 16), 256, 65536>>>(
            op2, wo2 + (size_t)l*Dm*UD, obuf, Dm, Dm);
        resid_k<<<MT, 256>>>(x, obuf, attn_alpha + l*Dm, xp2);
        gemm_mma_k<128,64,32,32,3,1><<<dim3(8, NHG/64), 256, 73728>>>(
            xp2, whg2 + (size_t)l*NHG*UD, zp2, DFFP, Dm);
        gemm_mma_k<64,64,32,16,4,0><<<dim3(16, 16), 256, 65536>>>(
            zp2, wfo2 + (size_t)l*Dm*UF, obuf, Dm, DFFP);
        resid_k<<<MT, 256>>>(x, obuf, ff_alpha + l*Dm, xp2);
    }
    gemm_mma_k<128,128,64,32,3,0><<<dim3(8, NV/128), 256, 98304>>>(
        xp2, wl2, out, NV, Dm);
}